// round 11
// baseline (speedup 1.0000x reference)
#include <cuda_runtime.h>
#include <cuda_bf16.h>
#include <math.h>
#include <stdint.h>

#define T_ 128
#define B_ 64
#define E_ 1024
#define H_ 1024
#define V_ 10000
#define VP 10112              // V padded to 128 (79*128)
#define M_ (T_*B_)            // 8192
#define BH (B_*H_)
#define K3 3072               // embed B-side split [Bh|Bl|Bh]
#define K2 2048               // interleaved [hi32|lo32] per 32-k group

#define GRID 128
#define NT 256

// Scratch (no allocs allowed)
__device__ float g_U0[(size_t)M_*H_];
__device__ float g_H1f[BH];
__device__ unsigned int g_bar[256];
__device__ __nv_bfloat16 g_A2[(size_t)M_*K2];     // H1 interleaved [Ah32|Al32]*32
__device__ __nv_bfloat16 g_B2[(size_t)VP*K2];     // Wdec interleaved [Bh32|Bl32]*32
__device__ __nv_bfloat16 g_h0h[2][BH], g_h0l[2][BH];
__device__ __nv_bfloat16 g_hid0h[BH], g_hid0l[BH];
__device__ __nv_bfloat16 g_hp1i[(size_t)B_*K2];   // initial h1 interleaved
__device__ __nv_bfloat16 g_embH[(size_t)V_*E_];
__device__ __nv_bfloat16 g_embL[(size_t)V_*E_];
__device__ __nv_bfloat16 g_W03[(size_t)H_*K3];

// ===========================================================================
// Grid barrier + helpers
// ===========================================================================
__global__ void reset_bar_kernel() {
    if (threadIdx.x < 256) g_bar[threadIdx.x] = 0;
}

__device__ __forceinline__ void gsync(int slot) {
    __syncthreads();
    if (threadIdx.x == 0) {
        __threadfence();
        atomicAdd(&g_bar[slot], 1u);
        while (*((volatile unsigned int*)&g_bar[slot]) < GRID) { }
        __threadfence();
    }
    __syncthreads();
}

__device__ __forceinline__ void split_bf16(float x, __nv_bfloat16& h, __nv_bfloat16& l) {
    h = __float2bfloat16(x);
    l = __float2bfloat16(x - __bfloat162float(h));
}

__device__ __forceinline__ uint32_t smem_u32(const void* p) {
    uint32_t a;
    asm("{ .reg .u64 t; cvta.to.shared.u64 t, %1; cvt.u32.u64 %0, t; }"
        : "=r"(a) : "l"(p));
    return a;
}
__device__ __forceinline__ void cp16(uint32_t dst, const void* src) {
    asm volatile("cp.async.cg.shared.global [%0], [%1], 16;"
                 :: "r"(dst), "l"(src));
}
__device__ __forceinline__ void ldm_x4(uint32_t& r0, uint32_t& r1,
                                       uint32_t& r2, uint32_t& r3, uint32_t addr) {
    asm volatile("ldmatrix.sync.aligned.m8n8.x4.shared.b16 {%0,%1,%2,%3}, [%4];"
                 : "=r"(r0), "=r"(r1), "=r"(r2), "=r"(r3) : "r"(addr));
}
__device__ __forceinline__ void mma16816(float* d,
                                         const uint32_t* a,
                                         uint32_t b0, uint32_t b1) {
    asm volatile("mma.sync.aligned.m16n8k16.row.col.f32.bf16.bf16.f32 "
                 "{%0,%1,%2,%3}, {%4,%5,%6,%7}, {%8,%9}, {%0,%1,%2,%3};"
                 : "+f"(d[0]), "+f"(d[1]), "+f"(d[2]), "+f"(d[3])
                 : "r"(a[0]), "r"(a[1]), "r"(a[2]), "r"(a[3]), "r"(b0), "r"(b1));
}
__device__ __forceinline__ void mma16816d(float& d0, float& d1, float& d2, float& d3,
                                          uint32_t a0, uint32_t a1, uint32_t a2, uint32_t a3,
                                          uint32_t b0, uint32_t b1) {
    asm volatile("mma.sync.aligned.m16n8k16.row.col.f32.bf16.bf16.f32 "
                 "{%0,%1,%2,%3}, {%4,%5,%6,%7}, {%8,%9}, {%0,%1,%2,%3};"
                 : "+f"(d0), "+f"(d1), "+f"(d2), "+f"(d3)
                 : "r"(a0), "r"(a1), "r"(a2), "r"(a3), "r"(b0), "r"(b1));
}
__device__ __forceinline__ __nv_bfloat162 pack2(__nv_bfloat16 a, __nv_bfloat16 b) {
    __nv_bfloat162 p; p.x = a; p.y = b; return p;
}

// ===========================================================================
// Conversion kernels
// ===========================================================================
__global__ __launch_bounds__(256)
void convert_emb(const float* __restrict__ Wemb,
                 __nv_bfloat16* __restrict__ eh, __nv_bfloat16* __restrict__ el)
{
    size_t q = (size_t)blockIdx.x * 256 + threadIdx.x;
    if (q < (size_t)V_ * E_ / 4) {
        float4 v = *(const float4*)(Wemb + q * 4);
        __nv_bfloat16 h0,l0,h1,l1,h2,l2,h3,l3;
        split_bf16(v.x,h0,l0); split_bf16(v.y,h1,l1);
        split_bf16(v.z,h2,l2); split_bf16(v.w,h3,l3);
        *(__nv_bfloat162*)(eh + q*4)     = pack2(h0,h1);
        *(__nv_bfloat162*)(eh + q*4 + 2) = pack2(h2,h3);
        *(__nv_bfloat162*)(el + q*4)     = pack2(l0,l1);
        *(__nv_bfloat162*)(el + q*4 + 2) = pack2(l2,l3);
    }
}

__global__ __launch_bounds__(256)
void convert_win0(const float* __restrict__ W, __nv_bfloat16* __restrict__ W3)
{
    size_t q = (size_t)blockIdx.x * 256 + threadIdx.x;
    int n = (int)(q >> 8), kq = (int)(q & 255) * 4;
    float4 v = *(const float4*)(W + (size_t)n * E_ + kq);
    __nv_bfloat16 h0,l0,h1,l1,h2,l2,h3,l3;
    split_bf16(v.x,h0,l0); split_bf16(v.y,h1,l1);
    split_bf16(v.z,h2,l2); split_bf16(v.w,h3,l3);
    __nv_bfloat16* base = W3 + (size_t)n * K3 + kq;
    *(__nv_bfloat162*)(base)          = pack2(h0,h1);
    *(__nv_bfloat162*)(base + 2)      = pack2(h2,h3);
    *(__nv_bfloat162*)(base + 1024)   = pack2(l0,l1);
    *(__nv_bfloat162*)(base + 1026)   = pack2(l2,l3);
    *(__nv_bfloat162*)(base + 2048)   = pack2(h0,h1);
    *(__nv_bfloat162*)(base + 2050)   = pack2(h2,h3);
}

// Wdec -> interleaved K2 layout: row n, 32-k group kb: [hi32 | lo32]
__global__ __launch_bounds__(256)
void convert_wdec(const float* __restrict__ W, __nv_bfloat16* __restrict__ B2)
{
    size_t q = (size_t)blockIdx.x * 256 + threadIdx.x;
    int n = (int)(q >> 8), kq = (int)(q & 255) * 4;
    float4 v = (n < V_) ? *(const float4*)(W + (size_t)n * H_ + kq)
                        : make_float4(0.f,0.f,0.f,0.f);
    __nv_bfloat16 h0,l0,h1,l1,h2,l2,h3,l3;
    split_bf16(v.x,h0,l0); split_bf16(v.y,h1,l1);
    split_bf16(v.z,h2,l2); split_bf16(v.w,h3,l3);
    int kb = kq >> 5, jj = kq & 31;
    __nv_bfloat16* base = B2 + (size_t)n * K2 + kb * 64 + jj;
    *(__nv_bfloat162*)(base)      = pack2(h0,h1);
    *(__nv_bfloat162*)(base + 2)  = pack2(h2,h3);
    *(__nv_bfloat162*)(base + 32) = pack2(l0,l1);
    *(__nv_bfloat162*)(base + 34) = pack2(l2,l3);
}

// ===========================================================================
// Embedding projection via mma.sync (proven: 128x128, occ=2, 2-stage, K3)
// ===========================================================================
#define DEC_SMEM 65536

__global__ __launch_bounds__(256, 2)
void embed_mma(const __nv_bfloat16* __restrict__ EH,
               const __nv_bfloat16* __restrict__ EL,
               const __nv_bfloat16* __restrict__ W3,
               const int* __restrict__ tokens,
               const float* __restrict__ b0, float* __restrict__ C)
{
    extern __shared__ char dsm[];
    const uint32_t sb = smem_u32(dsm);

    const int tid  = threadIdx.x;
    const int lane = tid & 31, wid = tid >> 5;
    const int wm = wid >> 2, wn = wid & 3;
    const int m0 = blockIdx.y * 128, n0 = blockIdx.x * 128;

    float acc[4][4][4];
    #pragma unroll
    for (int i = 0; i < 4; i++)
        #pragma unroll
        for (int j = 0; j < 4; j++)
            #pragma unroll
            for (int q = 0; q < 4; q++) acc[i][j][q] = 0.f;

    int lrow[4], lcb[4], tokr[4];
    #pragma unroll
    for (int i = 0; i < 4; i++) {
        int idx = tid + i * 256;
        lrow[i] = idx >> 3;
        lcb[i]  = (idx & 7) * 16;
        tokr[i] = tokens[m0 + lrow[i]];
    }

    #define LOAD_TILE_E(ch, buf) do {                                          \
        const uint32_t Ab_ = sb + (buf) * 32768;                               \
        const uint32_t Bb_ = Ab_ + 16384;                                      \
        const __nv_bfloat16* Aarr_ = ((ch) < 32) ? EH : EL;                    \
        const int kc_ = (((ch) < 16) ? (ch) : (((ch) < 32) ? (ch) - 16 : (ch) - 32)) * 64; \
        _Pragma("unroll")                                                      \
        for (int i_ = 0; i_ < 4; i_++) {                                       \
            int r_ = lrow[i_], cb_ = lcb[i_];                                  \
            uint32_t sw_ = (uint32_t)(cb_ ^ ((r_ & 7) << 4));                  \
            cp16(Ab_ + r_ * 128 + sw_,                                         \
                 (const char*)Aarr_ + (((size_t)tokr[i_] * E_ + kc_) * 2 + cb_)); \
            cp16(Bb_ + r_ * 128 + sw_,                                         \
                 (const char*)W3 + (((size_t)(n0 + r_) * K3 + (ch) * 64) * 2 + cb_)); \
        }                                                                      \
        asm volatile("cp.async.commit_group;");                                \
    } while (0)

    LOAD_TILE_E(0, 0);

    const int KCH = K3 / 64;   // 48
    for (int ch = 0; ch < KCH; ++ch) {
        if (ch + 1 < KCH) {
            LOAD_TILE_E(ch + 1, (ch + 1) & 1);
            asm volatile("cp.async.wait_group 1;");
        } else {
            asm volatile("cp.async.wait_group 0;");
        }
        __syncthreads();

        const uint32_t Ab = sb + (ch & 1) * 32768;
        const uint32_t Bb = Ab + 16384;

        #pragma unroll
        for (int ks = 0; ks < 4; ++ks) {
            const int kb2 = ks * 32;
            uint32_t b[8];
            #pragma unroll
            for (int h = 0; h < 2; ++h) {
                int nrow = wn * 32 + h * 16 + ((lane >> 4) & 1) * 8 + (lane & 7);
                int kcol = kb2 + ((lane >> 3) & 1) * 16;
                uint32_t ad = Bb + nrow * 128 + (kcol ^ ((nrow & 7) << 4));
                ldm_x4(b[4*h+0], b[4*h+1], b[4*h+2], b[4*h+3], ad);
            }
            #pragma unroll
            for (int mf = 0; mf < 4; ++mf) {
                int arow = wm * 64 + mf * 16 + (lane & 15);
                int acol = kb2 + ((lane >> 4) & 1) * 16;
                uint32_t ad = Ab + arow * 128 + (acol ^ ((arow & 7) << 4));
                uint32_t a0, a1, a2r, a3r;
                ldm_x4(a0, a1, a2r, a3r, ad);
                #pragma unroll
                for (int nf = 0; nf < 4; ++nf)
                    mma16816d(acc[mf][nf][0], acc[mf][nf][1],
                              acc[mf][nf][2], acc[mf][nf][3],
                              a0, a1, a2r, a3r, b[nf*2], b[nf*2+1]);
            }
        }
        __syncthreads();
    }

    #pragma unroll
    for (int mf = 0; mf < 4; ++mf) {
        const int r0 = m0 + wm * 64 + mf * 16 + (lane >> 2);
        #pragma unroll
        for (int nf = 0; nf < 4; ++nf) {
            const int c = n0 + wn * 32 + nf * 8 + (lane & 3) * 2;
            float2 bia = *(const float2*)(b0 + c);
            float2 v0 = make_float2(acc[mf][nf][0] + bia.x, acc[mf][nf][1] + bia.y);
            float2 v1 = make_float2(acc[mf][nf][2] + bia.x, acc[mf][nf][3] + bia.y);
            *(float2*)(C + (size_t)r0 * H_ + c)     = v0;
            *(float2*)(C + (size_t)(r0+8) * H_ + c) = v1;
        }
    }
}

// ===========================================================================
// Persistent tensor-core recurrence (proven structure; h1 now interleaved K2)
// ===========================================================================
#define RSM_H   98304
#define RSM_RED (RSM_H + 65536)
#define RSM_TOTAL (RSM_RED + 4608)

#define LOADCH(ch, buf) do {                                                   \
    const int seg_ = tid & 7;                                                  \
    const int r0_  = tid >> 3;                                                 \
    const size_t hiOff_ = (size_t)(2*(ch) + (seg_ >> 2)) * 64 + (seg_ & 3) * 8;\
    _Pragma("unroll")                                                          \
    for (int i_ = 0; i_ < 8; i_++) {                                           \
        const int arr_ = i_ >> 1;                                              \
        const int row_ = r0_ + (i_ & 1) * 32;                                  \
        const char* src_ =                                                     \
          (arr_ == 0) ? (const char*)h0h + ((size_t)row_*H_  + (size_t)(ch)*64 + seg_*8)*2 : \
          (arr_ == 1) ? (const char*)h0l + ((size_t)row_*H_  + (size_t)(ch)*64 + seg_*8)*2 : \
          (arr_ == 2) ? (const char*)h1i + ((size_t)row_*K2 + hiOff_)*2 :      \
                        (const char*)h1i + ((size_t)row_*K2 + hiOff_ + 32)*2;  \
        cp16(sb + RSM_H + (buf)*32768 + arr_*8192 + row_*128                   \
                 + (uint32_t)((seg_*16) ^ ((row_ & 7) << 4)), src_);           \
    }                                                                          \
    asm volatile("cp.async.commit_group;");                                    \
} while (0)

__global__ __launch_bounds__(256, 1)
void rnn_persistent_mma(const float* __restrict__ Wh0,
                        const float* __restrict__ Win1,
                        const float* __restrict__ Wh1,
                        const float* __restrict__ b1v,
                        const float* __restrict__ hidden)
{
    extern __shared__ char rsm[];
    const uint32_t sb = smem_u32(rsm);
    const int tid = threadIdx.x, lane = tid & 31, wid = tid >> 5;
    const int wg = wid >> 2, mw = wid & 3;
    const int n0 = blockIdx.x * 8;

    {
        const float* Wm[3] = {Wh0, Win1, Wh1};
        #pragma unroll 1
        for (int m = 0; m < 3; ++m) {
            const float* src = Wm[m] + (size_t)n0 * H_;
            for (int idx = tid; idx < 8 * H_; idx += 256) {
                int r = idx >> 10, k = idx & 1023;
                float v = src[(size_t)r * H_ + k];
                __nv_bfloat16 hh, ll; split_bf16(v, hh, ll);
                uint32_t off = (uint32_t)(2 * k) ^ ((r & 7) << 4);
                *(__nv_bfloat16*)(rsm + m*32768 + r*2048 + off)     = hh;
                *(__nv_bfloat16*)(rsm + m*32768 + (r+8)*2048 + off) = ll;
            }
        }
    }
    for (size_t i = (size_t)blockIdx.x * 256 + tid; i < 2 * (size_t)BH;
         i += (size_t)GRID * 256) {
        __nv_bfloat16 hh, ll; split_bf16(hidden[i], hh, ll);
        if (i < (size_t)BH) { g_hid0h[i] = hh; g_hid0l[i] = ll; }
        else {
            size_t e = i - BH;
            size_t row = e >> 10;
            int k = (int)(e & 1023);
            size_t p = row * K2 + (size_t)(k >> 5) * 64 + (k & 31);
            g_hp1i[p] = hh; g_hp1i[p + 32] = ll;
        }
    }
    gsync(0);

    const float b1c0 = b1v[n0 + (lane & 3) * 2];
    const float b1c1 = b1v[n0 + (lane & 3) * 2 + 1];

    for (int tt = -1; tt < T_; ++tt) {
        const __nv_bfloat16 *h0h, *h0l, *h1i;
        if (tt < 0) { h0h = g_hid0h; h0l = g_hid0l; }
        else        { h0h = g_h0h[tt & 1]; h0l = g_h0l[tt & 1]; }
        h1i = (tt <= 0) ? g_hp1i : (g_A2 + (size_t)(tt - 1) * B_ * K2);

        float P0[4] = {0.f,0.f,0.f,0.f}, P1[4] = {0.f,0.f,0.f,0.f};

        LOADCH(0, 0);
        for (int ch = 0; ch < 16; ++ch) {
            if (ch < 15) { LOADCH(ch + 1, (ch + 1) & 1);
                           asm volatile("cp.async.wait_group 1;"); }
            else         { asm volatile("cp.async.wait_group 0;"); }
            __syncthreads();
            const uint32_t hb = sb + RSM_H + (ch & 1) * 32768;
            #pragma unroll
            for (int k16 = 0; k16 < 2; ++k16) {
                const int kb2 = wg * 64 + k16 * 32;
                const int kbw = ch * 128 + kb2;
                const int arow = mw * 16 + (lane & 15);
                const uint32_t aoff = (uint32_t)(kb2 + ((lane >> 4) & 1) * 16)
                                      ^ ((arow & 7) << 4);
                const int brow = ((lane >> 4) & 1) * 8 + (lane & 7);
                const uint32_t boff = (uint32_t)(kbw + ((lane >> 3) & 1) * 16)
                                      ^ ((brow & 7) << 4);

                uint32_t aH0[4], aL0[4];
                ldm_x4(aH0[0], aH0[1], aH0[2], aH0[3], hb + arow*128 + aoff);
                ldm_x4(aL0[0], aL0[1], aL0[2], aL0[3], hb + 8192 + arow*128 + aoff);
                uint32_t b0f[4];
                ldm_x4(b0f[0], b0f[1], b0f[2], b0f[3], sb + brow*2048 + boff);

                mma16816(P0, aH0, b0f[0], b0f[1]);
                mma16816(P0, aH0, b0f[2], b0f[3]);
                mma16816(P0, aL0, b0f[0], b0f[1]);

                if (tt >= 0) {
                    uint32_t aH1[4], aL1[4];
                    ldm_x4(aH1[0], aH1[1], aH1[2], aH1[3], hb + 16384 + arow*128 + aoff);
                    ldm_x4(aL1[0], aL1[1], aL1[2], aL1[3], hb + 24576 + arow*128 + aoff);
                    uint32_t bif[4], bhf[4];
                    ldm_x4(bif[0], bif[1], bif[2], bif[3], sb + 32768 + brow*2048 + boff);
                    ldm_x4(bhf[0], bhf[1], bhf[2], bhf[3], sb + 65536 + brow*2048 + boff);

                    mma16816(P1, aH0, bif[0], bif[1]);
                    mma16816(P1, aH0, bif[2], bif[3]);
                    mma16816(P1, aL0, bif[0], bif[1]);
                    mma16816(P1, aH1, bhf[0], bhf[1]);
                    mma16816(P1, aH1, bhf[2], bhf[3]);
                    mma16816(P1, aL1, bhf[0], bhf[1]);
                }
            }
            __syncthreads();
        }

        float* red = (float*)(rsm + RSM_RED);
        if (wg == 1) {
            float* r = red + (mw * 32 + lane) * 9;
            r[0]=P0[0]; r[1]=P0[1]; r[2]=P0[2]; r[3]=P0[3];
            r[4]=P1[0]; r[5]=P1[1]; r[6]=P1[2]; r[7]=P1[3];
        }
        __syncthreads();
        if (wg == 0) {
            const float* r = red + (mw * 32 + lane) * 9;
            #pragma unroll
            for (int j = 0; j < 4; j++) { P0[j] += r[j]; P1[j] += r[j + 4]; }

            const int r0 = mw * 16 + (lane >> 2);
            const int c0 = n0 + (lane & 3) * 2;
            const int rws[4] = {r0, r0, r0 + 8, r0 + 8};
            const int cls[4] = {c0, c0 + 1, c0, c0 + 1};
            const float bb[4] = {b1c0, b1c1, b1c0, b1c1};

            if (tt >= 0) {
                #pragma unroll
                for (int j = 0; j < 4; j++) {
                    float v = tanhf(P1[j] + bb[j]);
                    __nv_bfloat16 hh, ll; split_bf16(v, hh, ll);
                    size_t rowb = (size_t)(tt * 64 + rws[j]) * K2;
                    size_t p = rowb + (size_t)(cls[j] >> 5) * 64 + (cls[j] & 31);
                    g_A2[p] = hh; g_A2[p + 32] = ll;
                    if (tt == T_ - 1) g_H1f[rws[j] * H_ + cls[j]] = v;
                }
            }
            if (tt < T_ - 1) {
                __nv_bfloat16* dh = g_h0h[(tt + 1) & 1];
                __nv_bfloat16* dl = g_h0l[(tt + 1) & 1];
                #pragma unroll
                for (int j = 0; j < 4; j++) {
                    float u = g_U0[(size_t)(tt + 1) * BH + rws[j] * H_ + cls[j]];
                    float v = tanhf(P0[j] + u);
                    __nv_bfloat16 hh, ll; split_bf16(v, hh, ll);
                    dh[rws[j] * H_ + cls[j]] = hh;
                    dl[rws[j] * H_ + cls[j]] = ll;
                }
            }
        }
        gsync(tt + 2);
    }
}

// ===========================================================================
// Decoder GEMM: interleaved K2, 32 chunks, 3 terms per k16. 128x128, occ=2.
// smem row 128B = [hi32(64B) | lo32(64B)] for both A and B.
// ===========================================================================
__global__ __launch_bounds__(256, 2)
void decoder_mma(const __nv_bfloat16* __restrict__ A2,
                 const __nv_bfloat16* __restrict__ B2,
                 const float* __restrict__ bdec, float* __restrict__ C)
{
    extern __shared__ char dsm[];
    const uint32_t sb = smem_u32(dsm);

    const int tid  = threadIdx.x;
    const int lane = tid & 31, wid = tid >> 5;
    const int wm = wid >> 2, wn = wid & 3;
    const int m0 = blockIdx.y * 128, n0 = blockIdx.x * 128;

    float acc[4][4][4];
    #pragma unroll
    for (int i = 0; i < 4; i++)
        #pragma unroll
        for (int j = 0; j < 4; j++)
            #pragma unroll
            for (int q = 0; q < 4; q++) acc[i][j][q] = 0.f;

    int lrow[4], lcb[4];
    #pragma unroll
    for (int i = 0; i < 4; i++) {
        int idx = tid + i * 256;
        lrow[i] = idx >> 3;
        lcb[i]  = (idx & 7) * 16;
    }

    #define LOAD_TILE(ch, buf) do {                                            \
        const uint32_t Ab_ = sb + (buf) * 32768;                               \
        const uint32_t Bb_ = Ab_ + 16384;                                      \
        _Pragma("unroll")                                                      \
        for (int i_ = 0; i_ < 4; i_++) {                                       \
            int r_ = lrow[i_], cb_ = lcb[i_];                                  \
            uint32_t sw_ = (uint32_t)(cb_ ^ ((r_ & 7) << 4));                  \
            cp16(Ab_ + r_ * 128 + sw_,                                         \
                 (const char*)A2 + (((size_t)(m0 + r_) * K2 + (ch) * 64) * 2 + cb_)); \
            cp16(Bb_ + r_ * 128 + sw_,                                         \
                 (const char*)B2 + (((size_t)(n0 + r_) * K2 + (ch) * 64) * 2 + cb_)); \
        }                                                                      \
        asm volatile("cp.async.commit_group;");                                \
    } while (0)

    LOAD_TILE(0, 0);

    const int KCH = K2 / 64;   // 32
    for (int ch = 0; ch < KCH; ++ch) {
        if (ch + 1 < KCH) {
            LOAD_TILE(ch + 1, (ch + 1) & 1);
            asm volatile("cp.async.wait_group 1;");
        } else {
            asm volatile("cp.async.wait_group 0;");
        }
        __syncthreads();

        const uint32_t Ab = sb + (ch & 1) * 32768;
        const uint32_t Bb = Ab + 16384;

        #pragma unroll
        for (int s = 0; s < 2; ++s) {
            const int kb2 = s * 32;                   // hi base; lo = kb2 + 64
            uint32_t bh[8], bl[8];
            #pragma unroll
            for (int h = 0; h < 2; ++h) {
                int nrow = wn * 32 + h * 16 + ((lane >> 4) & 1) * 8 + (lane & 7);
                int ksel = ((lane >> 3) & 1) * 16;
                uint32_t swm = (uint32_t)((nrow & 7) << 4);
                uint32_t adH = Bb + nrow * 128 + ((uint32_t)(kb2 + ksel) ^ swm);
                uint32_t adL = Bb + nrow * 128 + ((uint32_t)(64 + kb2 + ksel) ^ swm);
                ldm_x4(bh[4*h+0], bh[4*h+1], bh[4*h+2], bh[4*h+3], adH);
                ldm_x4(bl[4*h+0], bl[4*h+1], bl[4*h+2], bl[4*h+3], adL);
            }
            #pragma unroll
            for (int mf = 0; mf < 4; ++mf) {
                int arow = wm * 64 + mf * 16 + (lane & 15);
                int ksel = ((lane >> 4) & 1) * 16;
                uint32_t swm = (uint32_t)((arow & 7) << 4);
                uint32_t adH = Ab + arow * 128 + ((uint32_t)(kb2 + ksel) ^ swm);
                uint32_t adL = Ab + arow * 128 + ((uint32_t)(64 + kb2 + ksel) ^ swm);
                uint32_t ah0, ah1, ah2, ah3, al0, al1, al2, al3;
                ldm_x4(ah0, ah1, ah2, ah3, adH);
                ldm_x4(al0, al1, al2, al3, adL);
                #pragma unroll
                for (int nf = 0; nf < 4; ++nf) {
                    mma16816d(acc[mf][nf][0], acc[mf][nf][1],
                              acc[mf][nf][2], acc[mf][nf][3],
                              ah0, ah1, ah2, ah3, bh[nf*2], bh[nf*2+1]);
                    mma16816d(acc[mf][nf][0], acc[mf][nf][1],
                              acc[mf][nf][2], acc[mf][nf][3],
                              ah0, ah1, ah2, ah3, bl[nf*2], bl[nf*2+1]);
                    mma16816d(acc[mf][nf][0], acc[mf][nf][1],
                              acc[mf][nf][2], acc[mf][nf][3],
                              al0, al1, al2, al3, bh[nf*2], bh[nf*2+1]);
                }
            }
        }
        __syncthreads();
    }

    #pragma unroll
    for (int mf = 0; mf < 4; ++mf) {
        const int r0 = m0 + wm * 64 + mf * 16 + (lane >> 2);
        #pragma unroll
        for (int nf = 0; nf < 4; ++nf) {
            const int c = n0 + wn * 32 + nf * 8 + (lane & 3) * 2;
            if (c < V_) {
                float2 bia = *(const float2*)(bdec + c);
                float2 v0 = make_float2(acc[mf][nf][0] + bia.x, acc[mf][nf][1] + bia.y);
                float2 v1 = make_float2(acc[mf][nf][2] + bia.x, acc[mf][nf][3] + bia.y);
                *(float2*)(C + (size_t)r0 * V_ + c)     = v0;
                *(float2*)(C + (size_t)(r0+8) * V_ + c) = v1;
            }
        }
    }
}

// ===========================================================================
// Final hidden state
// ===========================================================================
__global__ void copy_final(const __nv_bfloat16* __restrict__ h0hh,
                           const __nv_bfloat16* __restrict__ h0ll,
                           const float* __restrict__ h1f,
                           float* __restrict__ out)
{
    int i = blockIdx.x * blockDim.x + threadIdx.x;
    if (i < BH) {
        out[i]      = __bfloat162float(h0hh[i]) + __bfloat162float(h0ll[i]);
        out[BH + i] = h1f[i];
    }
}

extern "C" void kernel_launch(void* const* d_in, const int* in_sizes, int n_in,
                              void* d_out, int out_size)
{
    const float* emb    = (const float*)d_in[0];
    const float* W_in0  = (const float*)d_in[1];
    const float* Wh0    = (const float*)d_in[2];
    const float* b0     = (const float*)d_in[3];
    const float* W_in1  = (const float*)d_in[4];
    const float* Wh1    = (const float*)d_in[5];
    const float* b1     = (const float*)d_in[6];
    const float* Wdec   = (const float*)d_in[7];
    const float* bdec   = (const float*)d_in[8];
    const float* hidden = (const float*)d_in[9];
    const int*   tokens = (const int*)d_in[10];

    float* out    = (float*)d_out;
    float* logits = out;
    float* hfin   = out + (size_t)M_ * V_;

    float *U0 = nullptr, *H1f = nullptr;
    __nv_bfloat16 *A2 = nullptr, *B2 = nullptr, *h0h = nullptr, *h0l = nullptr;
    __nv_bfloat16 *EH = nullptr, *EL = nullptr, *W03 = nullptr;
    cudaGetSymbolAddress((void**)&U0,  g_U0);
    cudaGetSymbolAddress((void**)&H1f, g_H1f);
    cudaGetSymbolAddress((void**)&A2,  g_A2);
    cudaGetSymbolAddress((void**)&B2,  g_B2);
    cudaGetSymbolAddress((void**)&h0h, g_h0h);
    cudaGetSymbolAddress((void**)&h0l, g_h0l);
    cudaGetSymbolAddress((void**)&EH,  g_embH);
    cudaGetSymbolAddress((void**)&EL,  g_embL);
    cudaGetSymbolAddress((void**)&W03, g_W03);

    cudaFuncSetAttribute(rnn_persistent_mma,
                         cudaFuncAttributeMaxDynamicSharedMemorySize, RSM_TOTAL);
    cudaFuncSetAttribute(decoder_mma,
                         cudaFuncAttributeMaxDynamicSharedMemorySize, DEC_SMEM);
    cudaFuncSetAttribute(embed_mma,
                         cudaFuncAttributeMaxDynamicSharedMemorySize, DEC_SMEM);

    // 0) splits (vectorized)
    reset_bar_kernel<<<1, 256>>>();
    convert_emb<<<(int)(((size_t)V_ * E_ / 4 + 255) / 256), 256>>>(emb, EH, EL);
    convert_win0<<<(int)(((size_t)H_ * 256) / 256), 256>>>(W_in0, W03);
    convert_wdec<<<(int)(((size_t)VP * 256) / 256), 256>>>(Wdec, B2);

    // 1) U0 = emb[tokens] @ W_in0^T + b0
    embed_mma<<<dim3(H_ / 128, M_ / 128), 256, DEC_SMEM>>>(EH, EL, W03, tokens,
                                                           b0, U0);

    // 2) Persistent tensor-core recurrence
    rnn_persistent_mma<<<GRID, NT, RSM_TOTAL>>>(Wh0, W_in1, Wh1, b1, hidden);

    // 3) logits = A2 @ B2^T + bdec (interleaved K2, 3 terms/k16)
    decoder_mma<<<dim3(VP / 128, M_ / 128), 256, DEC_SMEM>>>(A2, B2, bdec, logits);

    // 4) final hidden states
    copy_final<<<(BH + 255) / 256, 256>>>(h0h + BH, h0l + BH, H1f, hfin);

    (void)in_sizes; (void)n_in; (void)out_size;
}

// round 12
// speedup vs baseline: 1.4755x; 1.4755x over previous
#include <cuda_runtime.h>
#include <cuda_bf16.h>
#include <math.h>
#include <stdint.h>

#define T_ 128
#define B_ 64
#define E_ 1024
#define H_ 1024
#define V_ 10000
#define VP 10112              // V padded to 128 (79*128)
#define M_ (T_*B_)            // 8192
#define BH (B_*H_)
#define K3 3072               // [Ah|Ah|Al] x [Bh|Bl|Bh] 3-term split

#define GRID 128
#define NT 256

// Scratch (no allocs allowed)
__device__ float g_U0[(size_t)M_*H_];
__device__ float g_H1f[BH];
__device__ unsigned int g_bar[256];
__device__ __nv_bfloat16 g_A3[(size_t)M_*K3];
__device__ __nv_bfloat16 g_B3[(size_t)VP*K3];
__device__ __nv_bfloat16 g_h0h[2][BH], g_h0l[2][BH];
__device__ __nv_bfloat16 g_hid0h[BH], g_hid0l[BH];
__device__ __nv_bfloat16 g_hp1h[BH],  g_hp1l[BH];
__device__ __nv_bfloat16 g_embH[(size_t)V_*E_];
__device__ __nv_bfloat16 g_embL[(size_t)V_*E_];
__device__ __nv_bfloat16 g_W03[(size_t)H_*K3];

// ===========================================================================
// Grid barrier + helpers
// ===========================================================================
__global__ void reset_bar_kernel() {
    if (threadIdx.x < 256) g_bar[threadIdx.x] = 0;
}

__device__ __forceinline__ void gsync(int slot) {
    __syncthreads();
    if (threadIdx.x == 0) {
        __threadfence();
        atomicAdd(&g_bar[slot], 1u);
        while (*((volatile unsigned int*)&g_bar[slot]) < GRID) { }
        __threadfence();
    }
    __syncthreads();
}

__device__ __forceinline__ void split_bf16(float x, __nv_bfloat16& h, __nv_bfloat16& l) {
    h = __float2bfloat16(x);
    l = __float2bfloat16(x - __bfloat162float(h));
}

__device__ __forceinline__ uint32_t smem_u32(const void* p) {
    uint32_t a;
    asm("{ .reg .u64 t; cvta.to.shared.u64 t, %1; cvt.u32.u64 %0, t; }"
        : "=r"(a) : "l"(p));
    return a;
}
__device__ __forceinline__ void cp16(uint32_t dst, const void* src) {
    asm volatile("cp.async.cg.shared.global [%0], [%1], 16;"
                 :: "r"(dst), "l"(src));
}
__device__ __forceinline__ void ldm_x4(uint32_t& r0, uint32_t& r1,
                                       uint32_t& r2, uint32_t& r3, uint32_t addr) {
    asm volatile("ldmatrix.sync.aligned.m8n8.x4.shared.b16 {%0,%1,%2,%3}, [%4];"
                 : "=r"(r0), "=r"(r1), "=r"(r2), "=r"(r3) : "r"(addr));
}
__device__ __forceinline__ void mma16816(float* d,
                                         const uint32_t* a,
                                         uint32_t b0, uint32_t b1) {
    asm volatile("mma.sync.aligned.m16n8k16.row.col.f32.bf16.bf16.f32 "
                 "{%0,%1,%2,%3}, {%4,%5,%6,%7}, {%8,%9}, {%0,%1,%2,%3};"
                 : "+f"(d[0]), "+f"(d[1]), "+f"(d[2]), "+f"(d[3])
                 : "r"(a[0]), "r"(a[1]), "r"(a[2]), "r"(a[3]), "r"(b0), "r"(b1));
}
__device__ __forceinline__ void mma16816d(float& d0, float& d1, float& d2, float& d3,
                                          uint32_t a0, uint32_t a1, uint32_t a2, uint32_t a3,
                                          uint32_t b0, uint32_t b1) {
    asm volatile("mma.sync.aligned.m16n8k16.row.col.f32.bf16.bf16.f32 "
                 "{%0,%1,%2,%3}, {%4,%5,%6,%7}, {%8,%9}, {%0,%1,%2,%3};"
                 : "+f"(d0), "+f"(d1), "+f"(d2), "+f"(d3)
                 : "r"(a0), "r"(a1), "r"(a2), "r"(a3), "r"(b0), "r"(b1));
}
__device__ __forceinline__ __nv_bfloat162 pack2(__nv_bfloat16 a, __nv_bfloat16 b) {
    __nv_bfloat162 p; p.x = a; p.y = b; return p;
}
__device__ __forceinline__ void stcs2(float* p, float2 v) {
    asm volatile("st.global.cs.v2.f32 [%0], {%1, %2};"
                 :: "l"(p), "f"(v.x), "f"(v.y) : "memory");
}

// ===========================================================================
// Conversion kernels (vectorized — validated in round 8)
// ===========================================================================
__global__ __launch_bounds__(256)
void convert_emb(const float* __restrict__ Wemb,
                 __nv_bfloat16* __restrict__ eh, __nv_bfloat16* __restrict__ el)
{
    size_t q = (size_t)blockIdx.x * 256 + threadIdx.x;
    if (q < (size_t)V_ * E_ / 4) {
        float4 v = *(const float4*)(Wemb + q * 4);
        __nv_bfloat16 h0,l0,h1,l1,h2,l2,h3,l3;
        split_bf16(v.x,h0,l0); split_bf16(v.y,h1,l1);
        split_bf16(v.z,h2,l2); split_bf16(v.w,h3,l3);
        *(__nv_bfloat162*)(eh + q*4)     = pack2(h0,h1);
        *(__nv_bfloat162*)(eh + q*4 + 2) = pack2(h2,h3);
        *(__nv_bfloat162*)(el + q*4)     = pack2(l0,l1);
        *(__nv_bfloat162*)(el + q*4 + 2) = pack2(l2,l3);
    }
}

__global__ __launch_bounds__(256)
void convert_win0(const float* __restrict__ W, __nv_bfloat16* __restrict__ W3)
{
    size_t q = (size_t)blockIdx.x * 256 + threadIdx.x;
    int n = (int)(q >> 8), kq = (int)(q & 255) * 4;
    float4 v = *(const float4*)(W + (size_t)n * E_ + kq);
    __nv_bfloat16 h0,l0,h1,l1,h2,l2,h3,l3;
    split_bf16(v.x,h0,l0); split_bf16(v.y,h1,l1);
    split_bf16(v.z,h2,l2); split_bf16(v.w,h3,l3);
    __nv_bfloat16* base = W3 + (size_t)n * K3 + kq;
    *(__nv_bfloat162*)(base)          = pack2(h0,h1);
    *(__nv_bfloat162*)(base + 2)      = pack2(h2,h3);
    *(__nv_bfloat162*)(base + 1024)   = pack2(l0,l1);
    *(__nv_bfloat162*)(base + 1026)   = pack2(l2,l3);
    *(__nv_bfloat162*)(base + 2048)   = pack2(h0,h1);
    *(__nv_bfloat162*)(base + 2050)   = pack2(h2,h3);
}

__global__ __launch_bounds__(256)
void convert_wdec(const float* __restrict__ W, __nv_bfloat16* __restrict__ B3)
{
    size_t q = (size_t)blockIdx.x * 256 + threadIdx.x;
    int n = (int)(q >> 8), kq = (int)(q & 255) * 4;
    float4 v = (n < V_) ? *(const float4*)(W + (size_t)n * H_ + kq)
                        : make_float4(0.f,0.f,0.f,0.f);
    __nv_bfloat16 h0,l0,h1,l1,h2,l2,h3,l3;
    split_bf16(v.x,h0,l0); split_bf16(v.y,h1,l1);
    split_bf16(v.z,h2,l2); split_bf16(v.w,h3,l3);
    __nv_bfloat16* base = B3 + (size_t)n * K3 + kq;
    *(__nv_bfloat162*)(base)          = pack2(h0,h1);
    *(__nv_bfloat162*)(base + 2)      = pack2(h2,h3);
    *(__nv_bfloat162*)(base + 1024)   = pack2(l0,l1);
    *(__nv_bfloat162*)(base + 1026)   = pack2(l2,l3);
    *(__nv_bfloat162*)(base + 2048)   = pack2(h0,h1);
    *(__nv_bfloat162*)(base + 2050)   = pack2(h2,h3);
}

// ===========================================================================
// Embedding projection via mma.sync (round-7 proven: 128x128, occ=2, 2-stage)
// ===========================================================================
#define DEC_SMEM 65536

__global__ __launch_bounds__(256, 2)
void embed_mma(const __nv_bfloat16* __restrict__ EH,
               const __nv_bfloat16* __restrict__ EL,
               const __nv_bfloat16* __restrict__ W3,
               const int* __restrict__ tokens,
               const float* __restrict__ b0, float* __restrict__ C)
{
    extern __shared__ char dsm[];
    const uint32_t sb = smem_u32(dsm);

    const int tid  = threadIdx.x;
    const int lane = tid & 31, wid = tid >> 5;
    const int wm = wid >> 2, wn = wid & 3;
    const int m0 = blockIdx.y * 128, n0 = blockIdx.x * 128;

    float acc[4][4][4];
    #pragma unroll
    for (int i = 0; i < 4; i++)
        #pragma unroll
        for (int j = 0; j < 4; j++)
            #pragma unroll
            for (int q = 0; q < 4; q++) acc[i][j][q] = 0.f;

    int lrow[4], lcb[4], tokr[4];
    #pragma unroll
    for (int i = 0; i < 4; i++) {
        int idx = tid + i * 256;
        lrow[i] = idx >> 3;
        lcb[i]  = (idx & 7) * 16;
        tokr[i] = tokens[m0 + lrow[i]];
    }

    #define LOAD_TILE_E(ch, buf) do {                                          \
        const uint32_t Ab_ = sb + (buf) * 32768;                               \
        const uint32_t Bb_ = Ab_ + 16384;                                      \
        const __nv_bfloat16* Aarr_ = ((ch) < 32) ? EH : EL;                    \
        const int kc_ = (((ch) < 16) ? (ch) : (((ch) < 32) ? (ch) - 16 : (ch) - 32)) * 64; \
        _Pragma("unroll")                                                      \
        for (int i_ = 0; i_ < 4; i_++) {                                       \
            int r_ = lrow[i_], cb_ = lcb[i_];                                  \
            uint32_t sw_ = (uint32_t)(cb_ ^ ((r_ & 7) << 4));                  \
            cp16(Ab_ + r_ * 128 + sw_,                                         \
                 (const char*)Aarr_ + (((size_t)tokr[i_] * E_ + kc_) * 2 + cb_)); \
            cp16(Bb_ + r_ * 128 + sw_,                                         \
                 (const char*)W3 + (((size_t)(n0 + r_) * K3 + (ch) * 64) * 2 + cb_)); \
        }                                                                      \
        asm volatile("cp.async.commit_group;");                                \
    } while (0)

    LOAD_TILE_E(0, 0);

    const int KCH = K3 / 64;   // 48
    for (int ch = 0; ch < KCH; ++ch) {
        if (ch + 1 < KCH) {
            LOAD_TILE_E(ch + 1, (ch + 1) & 1);
            asm volatile("cp.async.wait_group 1;");
        } else {
            asm volatile("cp.async.wait_group 0;");
        }
        __syncthreads();

        const uint32_t Ab = sb + (ch & 1) * 32768;
        const uint32_t Bb = Ab + 16384;

        #pragma unroll
        for (int ks = 0; ks < 4; ++ks) {
            const int kb2 = ks * 32;
            uint32_t b[8];
            #pragma unroll
            for (int h = 0; h < 2; ++h) {
                int nrow = wn * 32 + h * 16 + ((lane >> 4) & 1) * 8 + (lane & 7);
                int kcol = kb2 + ((lane >> 3) & 1) * 16;
                uint32_t ad = Bb + nrow * 128 + (kcol ^ ((nrow & 7) << 4));
                ldm_x4(b[4*h+0], b[4*h+1], b[4*h+2], b[4*h+3], ad);
            }
            #pragma unroll
            for (int mf = 0; mf < 4; ++mf) {
                int arow = wm * 64 + mf * 16 + (lane & 15);
                int acol = kb2 + ((lane >> 4) & 1) * 16;
                uint32_t ad = Ab + arow * 128 + (acol ^ ((arow & 7) << 4));
                uint32_t a0, a1, a2r, a3r;
                ldm_x4(a0, a1, a2r, a3r, ad);
                #pragma unroll
                for (int nf = 0; nf < 4; ++nf)
                    mma16816d(acc[mf][nf][0], acc[mf][nf][1],
                              acc[mf][nf][2], acc[mf][nf][3],
                              a0, a1, a2r, a3r, b[nf*2], b[nf*2+1]);
            }
        }
        __syncthreads();
    }

    #pragma unroll
    for (int mf = 0; mf < 4; ++mf) {
        const int r0 = m0 + wm * 64 + mf * 16 + (lane >> 2);
        #pragma unroll
        for (int nf = 0; nf < 4; ++nf) {
            const int c = n0 + wn * 32 + nf * 8 + (lane & 3) * 2;
            float2 bia = *(const float2*)(b0 + c);
            float2 v0 = make_float2(acc[mf][nf][0] + bia.x, acc[mf][nf][1] + bia.y);
            float2 v1 = make_float2(acc[mf][nf][2] + bia.x, acc[mf][nf][3] + bia.y);
            stcs2(C + (size_t)r0 * H_ + c,     v0);
            stcs2(C + (size_t)(r0+8) * H_ + c, v1);
        }
    }
}

// ===========================================================================
// Persistent tensor-core recurrence (round-7 proven structure, untouched)
// ===========================================================================
#define RSM_H   98304
#define RSM_RED (RSM_H + 65536)
#define RSM_TOTAL (RSM_RED + 4608)

#define LOADCH(ch, buf) do {                                                   \
    const int seg_ = tid & 7;                                                  \
    const int r0_  = tid >> 3;                                                 \
    _Pragma("unroll")                                                          \
    for (int i_ = 0; i_ < 8; i_++) {                                           \
        const int arr_ = i_ >> 1;                                              \
        const int row_ = r0_ + (i_ & 1) * 32;                                  \
        const char* src_ =                                                     \
          (arr_ == 0) ? (const char*)h0h + ((size_t)row_*H_  + (size_t)(ch)*64 + seg_*8)*2 : \
          (arr_ == 1) ? (const char*)h0l + ((size_t)row_*H_  + (size_t)(ch)*64 + seg_*8)*2 : \
          (arr_ == 2) ? (const char*)h1h + ((size_t)row_*h1s + (size_t)(ch)*64 + seg_*8)*2 : \
                        (const char*)h1l + ((size_t)row_*h1s + (size_t)(ch)*64 + seg_*8)*2;  \
        cp16(sb + RSM_H + (buf)*32768 + arr_*8192 + row_*128                   \
                 + (uint32_t)((seg_*16) ^ ((row_ & 7) << 4)), src_);           \
    }                                                                          \
    asm volatile("cp.async.commit_group;");                                    \
} while (0)

__global__ __launch_bounds__(256, 1)
void rnn_persistent_mma(const float* __restrict__ Wh0,
                        const float* __restrict__ Win1,
                        const float* __restrict__ Wh1,
                        const float* __restrict__ b1v,
                        const float* __restrict__ hidden)
{
    extern __shared__ char rsm[];
    const uint32_t sb = smem_u32(rsm);
    const int tid = threadIdx.x, lane = tid & 31, wid = tid >> 5;
    const int wg = wid >> 2, mw = wid & 3;
    const int n0 = blockIdx.x * 8;

    {
        const float* Wm[3] = {Wh0, Win1, Wh1};
        #pragma unroll 1
        for (int m = 0; m < 3; ++m) {
            const float* src = Wm[m] + (size_t)n0 * H_;
            for (int idx = tid; idx < 8 * H_; idx += 256) {
                int r = idx >> 10, k = idx & 1023;
                float v = src[(size_t)r * H_ + k];
                __nv_bfloat16 hh, ll; split_bf16(v, hh, ll);
                uint32_t off = (uint32_t)(2 * k) ^ ((r & 7) << 4);
                *(__nv_bfloat16*)(rsm + m*32768 + r*2048 + off)     = hh;
                *(__nv_bfloat16*)(rsm + m*32768 + (r+8)*2048 + off) = ll;
            }
        }
    }
    for (size_t i = (size_t)blockIdx.x * 256 + tid; i < 2 * (size_t)BH;
         i += (size_t)GRID * 256) {
        __nv_bfloat16 hh, ll; split_bf16(hidden[i], hh, ll);
        if (i < (size_t)BH) { g_hid0h[i] = hh; g_hid0l[i] = ll; }
        else                { g_hp1h[i - BH] = hh; g_hp1l[i - BH] = ll; }
    }
    gsync(0);

    const float b1c0 = b1v[n0 + (lane & 3) * 2];
    const float b1c1 = b1v[n0 + (lane & 3) * 2 + 1];

    for (int tt = -1; tt < T_; ++tt) {
        const __nv_bfloat16 *h0h, *h0l, *h1h, *h1l;
        size_t h1s;
        if (tt < 0) { h0h = g_hid0h; h0l = g_hid0l; }
        else        { h0h = g_h0h[tt & 1]; h0l = g_h0l[tt & 1]; }
        if (tt <= 0) { h1h = g_hp1h; h1l = g_hp1l; h1s = H_; }
        else { h1h = g_A3 + (size_t)(tt - 1) * B_ * K3; h1l = h1h + 2048; h1s = K3; }

        float P0[4] = {0.f,0.f,0.f,0.f}, P1[4] = {0.f,0.f,0.f,0.f};

        LOADCH(0, 0);
        for (int ch = 0; ch < 16; ++ch) {
            if (ch < 15) { LOADCH(ch + 1, (ch + 1) & 1);
                           asm volatile("cp.async.wait_group 1;"); }
            else         { asm volatile("cp.async.wait_group 0;"); }
            __syncthreads();
            const uint32_t hb = sb + RSM_H + (ch & 1) * 32768;
            #pragma unroll
            for (int k16 = 0; k16 < 2; ++k16) {
                const int kb2 = wg * 64 + k16 * 32;
                const int kbw = ch * 128 + kb2;
                const int arow = mw * 16 + (lane & 15);
                const uint32_t aoff = (uint32_t)(kb2 + ((lane >> 4) & 1) * 16)
                                      ^ ((arow & 7) << 4);
                const int brow = ((lane >> 4) & 1) * 8 + (lane & 7);
                const uint32_t boff = (uint32_t)(kbw + ((lane >> 3) & 1) * 16)
                                      ^ ((brow & 7) << 4);

                uint32_t aH0[4], aL0[4];
                ldm_x4(aH0[0], aH0[1], aH0[2], aH0[3], hb + arow*128 + aoff);
                ldm_x4(aL0[0], aL0[1], aL0[2], aL0[3], hb + 8192 + arow*128 + aoff);
                uint32_t b0f[4];
                ldm_x4(b0f[0], b0f[1], b0f[2], b0f[3], sb + brow*2048 + boff);

                mma16816(P0, aH0, b0f[0], b0f[1]);
                mma16816(P0, aH0, b0f[2], b0f[3]);
                mma16816(P0, aL0, b0f[0], b0f[1]);

                if (tt >= 0) {
                    uint32_t aH1[4], aL1[4];
                    ldm_x4(aH1[0], aH1[1], aH1[2], aH1[3], hb + 16384 + arow*128 + aoff);
                    ldm_x4(aL1[0], aL1[1], aL1[2], aL1[3], hb + 24576 + arow*128 + aoff);
                    uint32_t bif[4], bhf[4];
                    ldm_x4(bif[0], bif[1], bif[2], bif[3], sb + 32768 + brow*2048 + boff);
                    ldm_x4(bhf[0], bhf[1], bhf[2], bhf[3], sb + 65536 + brow*2048 + boff);

                    mma16816(P1, aH0, bif[0], bif[1]);
                    mma16816(P1, aH0, bif[2], bif[3]);
                    mma16816(P1, aL0, bif[0], bif[1]);
                    mma16816(P1, aH1, bhf[0], bhf[1]);
                    mma16816(P1, aH1, bhf[2], bhf[3]);
                    mma16816(P1, aL1, bhf[0], bhf[1]);
                }
            }
            __syncthreads();
        }

        float* red = (float*)(rsm + RSM_RED);
        if (wg == 1) {
            float* r = red + (mw * 32 + lane) * 9;
            r[0]=P0[0]; r[1]=P0[1]; r[2]=P0[2]; r[3]=P0[3];
            r[4]=P1[0]; r[5]=P1[1]; r[6]=P1[2]; r[7]=P1[3];
        }
        __syncthreads();
        if (wg == 0) {
            const float* r = red + (mw * 32 + lane) * 9;
            #pragma unroll
            for (int j = 0; j < 4; j++) { P0[j] += r[j]; P1[j] += r[j + 4]; }

            const int r0 = mw * 16 + (lane >> 2);
            const int c0 = n0 + (lane & 3) * 2;
            const int rws[4] = {r0, r0, r0 + 8, r0 + 8};
            const int cls[4] = {c0, c0 + 1, c0, c0 + 1};
            const float bb[4] = {b1c0, b1c1, b1c0, b1c1};

            if (tt >= 0) {
                #pragma unroll
                for (int j = 0; j < 4; j++) {
                    float v = tanhf(P1[j] + bb[j]);
                    __nv_bfloat16 hh, ll; split_bf16(v, hh, ll);
                    size_t ab = ((size_t)(tt * 64 + rws[j])) * K3 + cls[j];
                    g_A3[ab] = hh; g_A3[ab + 1024] = hh; g_A3[ab + 2048] = ll;
                    if (tt == T_ - 1) g_H1f[rws[j] * H_ + cls[j]] = v;
                }
            }
            if (tt < T_ - 1) {
                __nv_bfloat16* dh = g_h0h[(tt + 1) & 1];
                __nv_bfloat16* dl = g_h0l[(tt + 1) & 1];
                #pragma unroll
                for (int j = 0; j < 4; j++) {
                    float u = g_U0[(size_t)(tt + 1) * BH + rws[j] * H_ + cls[j]];
                    float v = tanhf(P0[j] + u);
                    __nv_bfloat16 hh, ll; split_bf16(v, hh, ll);
                    dh[rws[j] * H_ + cls[j]] = hh;
                    dl[rws[j] * H_ + cls[j]] = ll;
                }
            }
        }
        gsync(tt + 2);
    }
}

// ===========================================================================
// mma.sync bf16 decoder GEMM (round-7 proven: 128x128, occ=2, 2-stage)
// Epilogue uses streaming stores: logits written once, evict-first.
// ===========================================================================
__global__ __launch_bounds__(256, 2)
void decoder_mma(const __nv_bfloat16* __restrict__ A3,
                 const __nv_bfloat16* __restrict__ B3,
                 const float* __restrict__ bdec, float* __restrict__ C)
{
    extern __shared__ char dsm[];
    const uint32_t sb = smem_u32(dsm);

    const int tid  = threadIdx.x;
    const int lane = tid & 31, wid = tid >> 5;
    const int wm = wid >> 2, wn = wid & 3;
    const int m0 = blockIdx.y * 128, n0 = blockIdx.x * 128;

    float acc[4][4][4];
    #pragma unroll
    for (int i = 0; i < 4; i++)
        #pragma unroll
        for (int j = 0; j < 4; j++)
            #pragma unroll
            for (int q = 0; q < 4; q++) acc[i][j][q] = 0.f;

    int lrow[4], lcb[4];
    #pragma unroll
    for (int i = 0; i < 4; i++) {
        int idx = tid + i * 256;
        lrow[i] = idx >> 3;
        lcb[i]  = (idx & 7) * 16;
    }

    #define LOAD_TILE(ch, buf) do {                                            \
        const uint32_t Ab_ = sb + (buf) * 32768;                               \
        const uint32_t Bb_ = Ab_ + 16384;                                      \
        _Pragma("unroll")                                                      \
        for (int i_ = 0; i_ < 4; i_++) {                                       \
            int r_ = lrow[i_], cb_ = lcb[i_];                                  \
            uint32_t sw_ = (uint32_t)(cb_ ^ ((r_ & 7) << 4));                  \
            cp16(Ab_ + r_ * 128 + sw_,                                         \
                 (const char*)A3 + (((size_t)(m0 + r_) * K3 + (ch) * 64) * 2 + cb_)); \
            cp16(Bb_ + r_ * 128 + sw_,                                         \
                 (const char*)B3 + (((size_t)(n0 + r_) * K3 + (ch) * 64) * 2 + cb_)); \
        }                                                                      \
        asm volatile("cp.async.commit_group;");                                \
    } while (0)

    LOAD_TILE(0, 0);

    const int KCH = K3 / 64;   // 48
    for (int ch = 0; ch < KCH; ++ch) {
        if (ch + 1 < KCH) {
            LOAD_TILE(ch + 1, (ch + 1) & 1);
            asm volatile("cp.async.wait_group 1;");
        } else {
            asm volatile("cp.async.wait_group 0;");
        }
        __syncthreads();

        const uint32_t Ab = sb + (ch & 1) * 32768;
        const uint32_t Bb = Ab + 16384;

        #pragma unroll
        for (int ks = 0; ks < 4; ++ks) {
            const int kb2 = ks * 32;
            uint32_t b[8];
            #pragma unroll
            for (int h = 0; h < 2; ++h) {
                int nrow = wn * 32 + h * 16 + ((lane >> 4) & 1) * 8 + (lane & 7);
                int kcol = kb2 + ((lane >> 3) & 1) * 16;
                uint32_t ad = Bb + nrow * 128 + (kcol ^ ((nrow & 7) << 4));
                ldm_x4(b[4*h+0], b[4*h+1], b[4*h+2], b[4*h+3], ad);
            }
            #pragma unroll
            for (int mf = 0; mf < 4; ++mf) {
                int arow = wm * 64 + mf * 16 + (lane & 15);
                int acol = kb2 + ((lane >> 4) & 1) * 16;
                uint32_t ad = Ab + arow * 128 + (acol ^ ((arow & 7) << 4));
                uint32_t a0, a1, a2r, a3r;
                ldm_x4(a0, a1, a2r, a3r, ad);
                #pragma unroll
                for (int nf = 0; nf < 4; ++nf)
                    mma16816d(acc[mf][nf][0], acc[mf][nf][1],
                              acc[mf][nf][2], acc[mf][nf][3],
                              a0, a1, a2r, a3r, b[nf*2], b[nf*2+1]);
            }
        }
        __syncthreads();
    }

    #pragma unroll
    for (int mf = 0; mf < 4; ++mf) {
        const int r0 = m0 + wm * 64 + mf * 16 + (lane >> 2);
        #pragma unroll
        for (int nf = 0; nf < 4; ++nf) {
            const int c = n0 + wn * 32 + nf * 8 + (lane & 3) * 2;
            if (c < V_) {
                float2 bia = *(const float2*)(bdec + c);
                float2 v0 = make_float2(acc[mf][nf][0] + bia.x, acc[mf][nf][1] + bia.y);
                float2 v1 = make_float2(acc[mf][nf][2] + bia.x, acc[mf][nf][3] + bia.y);
                stcs2(C + (size_t)r0 * V_ + c,     v0);
                stcs2(C + (size_t)(r0+8) * V_ + c, v1);
            }
        }
    }
}

// ===========================================================================
// Final hidden state
// ===========================================================================
__global__ void copy_final(const __nv_bfloat16* __restrict__ h0hh,
                           const __nv_bfloat16* __restrict__ h0ll,
                           const float* __restrict__ h1f,
                           float* __restrict__ out)
{
    int i = blockIdx.x * blockDim.x + threadIdx.x;
    if (i < BH) {
        out[i]      = __bfloat162float(h0hh[i]) + __bfloat162float(h0ll[i]);
        out[BH + i] = h1f[i];
    }
}

extern "C" void kernel_launch(void* const* d_in, const int* in_sizes, int n_in,
                              void* d_out, int out_size)
{
    const float* emb    = (const float*)d_in[0];
    const float* W_in0  = (const float*)d_in[1];
    const float* Wh0    = (const float*)d_in[2];
    const float* b0     = (const float*)d_in[3];
    const float* W_in1  = (const float*)d_in[4];
    const float* Wh1    = (const float*)d_in[5];
    const float* b1     = (const float*)d_in[6];
    const float* Wdec   = (const float*)d_in[7];
    const float* bdec   = (const float*)d_in[8];
    const float* hidden = (const float*)d_in[9];
    const int*   tokens = (const int*)d_in[10];

    float* out    = (float*)d_out;
    float* logits = out;
    float* hfin   = out + (size_t)M_ * V_;

    float *U0 = nullptr, *H1f = nullptr;
    __nv_bfloat16 *A3 = nullptr, *B3 = nullptr, *h0h = nullptr, *h0l = nullptr;
    __nv_bfloat16 *EH = nullptr, *EL = nullptr, *W03 = nullptr;
    cudaGetSymbolAddress((void**)&U0,  g_U0);
    cudaGetSymbolAddress((void**)&H1f, g_H1f);
    cudaGetSymbolAddress((void**)&A3,  g_A3);
    cudaGetSymbolAddress((void**)&B3,  g_B3);
    cudaGetSymbolAddress((void**)&h0h, g_h0h);
    cudaGetSymbolAddress((void**)&h0l, g_h0l);
    cudaGetSymbolAddress((void**)&EH,  g_embH);
    cudaGetSymbolAddress((void**)&EL,  g_embL);
    cudaGetSymbolAddress((void**)&W03, g_W03);

    cudaFuncSetAttribute(rnn_persistent_mma,
                         cudaFuncAttributeMaxDynamicSharedMemorySize, RSM_TOTAL);
    cudaFuncSetAttribute(decoder_mma,
                         cudaFuncAttributeMaxDynamicSharedMemorySize, DEC_SMEM);
    cudaFuncSetAttribute(embed_mma,
                         cudaFuncAttributeMaxDynamicSharedMemorySize, DEC_SMEM);

    // 0) splits (vectorized)
    reset_bar_kernel<<<1, 256>>>();
    convert_emb<<<(int)(((size_t)V_ * E_ / 4 + 255) / 256), 256>>>(emb, EH, EL);
    convert_win0<<<(int)(((size_t)H_ * 256) / 256), 256>>>(W_in0, W03);
    convert_wdec<<<(int)(((size_t)VP * 256) / 256), 256>>>(Wdec, B3);

    // 1) U0 = emb[tokens] @ W_in0^T + b0
    embed_mma<<<dim3(H_ / 128, M_ / 128), 256, DEC_SMEM>>>(EH, EL, W03, tokens,
                                                           b0, U0);

    // 2) Persistent tensor-core recurrence
    rnn_persistent_mma<<<GRID, NT, RSM_TOTAL>>>(Wh0, W_in1, Wh1, b1, hidden);

    // 3) logits = A3 @ B3^T + bdec (streaming stores)
    decoder_mma<<<dim3(VP / 128, M_ / 128), 256, DEC_SMEM>>>(A3, B3, bdec, logits);

    // 4) final hidden states
    copy_final<<<(BH + 255) / 256, 256>>>(h0h + BH, h0l + BH, H1f, hfin);

    (void)in_sizes; (void)n_in; (void)out_size;
}

// round 13
// speedup vs baseline: 1.5136x; 1.0258x over previous
#include <cuda_runtime.h>
#include <cuda_bf16.h>
#include <math.h>
#include <stdint.h>

#define T_ 128
#define B_ 64
#define E_ 1024
#define H_ 1024
#define V_ 10000
#define VP 10112              // V padded to 128 (79*128)
#define M_ (T_*B_)            // 8192
#define BH (B_*H_)
#define K3 3072               // [Ah|Ah|Al] x [Bh|Bl|Bh] 3-term split

#define GRID 128
#define NT 256

// Scratch (no allocs allowed)
__device__ float g_U0[(size_t)M_*H_];
__device__ float g_H1f[BH];
__device__ unsigned int g_bar[256];
__device__ __nv_bfloat16 g_A3[(size_t)M_*K3];
__device__ __nv_bfloat16 g_B3[(size_t)VP*K3];
__device__ __nv_bfloat16 g_h0h[2][BH], g_h0l[2][BH];
__device__ __nv_bfloat16 g_hid0h[BH], g_hid0l[BH];
__device__ __nv_bfloat16 g_hp1h[BH],  g_hp1l[BH];
__device__ __nv_bfloat16 g_embH[(size_t)V_*E_];
__device__ __nv_bfloat16 g_embL[(size_t)V_*E_];
__device__ __nv_bfloat16 g_W03[(size_t)H_*K3];

// ===========================================================================
// Grid barrier + helpers
// ===========================================================================
__global__ void reset_bar_kernel() {
    if (threadIdx.x < 256) g_bar[threadIdx.x] = 0;
}

__device__ __forceinline__ void gsync(int slot) {
    __syncthreads();
    if (threadIdx.x == 0) {
        __threadfence();
        atomicAdd(&g_bar[slot], 1u);
        while (*((volatile unsigned int*)&g_bar[slot]) < GRID) { }
        __threadfence();
    }
    __syncthreads();
}

__device__ __forceinline__ void split_bf16(float x, __nv_bfloat16& h, __nv_bfloat16& l) {
    h = __float2bfloat16(x);
    l = __float2bfloat16(x - __bfloat162float(h));
}

__device__ __forceinline__ uint32_t smem_u32(const void* p) {
    uint32_t a;
    asm("{ .reg .u64 t; cvta.to.shared.u64 t, %1; cvt.u32.u64 %0, t; }"
        : "=r"(a) : "l"(p));
    return a;
}
__device__ __forceinline__ void cp16(uint32_t dst, const void* src) {
    asm volatile("cp.async.cg.shared.global [%0], [%1], 16;"
                 :: "r"(dst), "l"(src));
}
__device__ __forceinline__ void ldm_x4(uint32_t& r0, uint32_t& r1,
                                       uint32_t& r2, uint32_t& r3, uint32_t addr) {
    asm volatile("ldmatrix.sync.aligned.m8n8.x4.shared.b16 {%0,%1,%2,%3}, [%4];"
                 : "=r"(r0), "=r"(r1), "=r"(r2), "=r"(r3) : "r"(addr));
}
__device__ __forceinline__ void mma16816(float* d,
                                         const uint32_t* a,
                                         uint32_t b0, uint32_t b1) {
    asm volatile("mma.sync.aligned.m16n8k16.row.col.f32.bf16.bf16.f32 "
                 "{%0,%1,%2,%3}, {%4,%5,%6,%7}, {%8,%9}, {%0,%1,%2,%3};"
                 : "+f"(d[0]), "+f"(d[1]), "+f"(d[2]), "+f"(d[3])
                 : "r"(a[0]), "r"(a[1]), "r"(a[2]), "r"(a[3]), "r"(b0), "r"(b1));
}
__device__ __forceinline__ void mma16816d(float& d0, float& d1, float& d2, float& d3,
                                          uint32_t a0, uint32_t a1, uint32_t a2, uint32_t a3,
                                          uint32_t b0, uint32_t b1) {
    asm volatile("mma.sync.aligned.m16n8k16.row.col.f32.bf16.bf16.f32 "
                 "{%0,%1,%2,%3}, {%4,%5,%6,%7}, {%8,%9}, {%0,%1,%2,%3};"
                 : "+f"(d0), "+f"(d1), "+f"(d2), "+f"(d3)
                 : "r"(a0), "r"(a1), "r"(a2), "r"(a3), "r"(b0), "r"(b1));
}
__device__ __forceinline__ __nv_bfloat162 pack2(__nv_bfloat16 a, __nv_bfloat16 b) {
    __nv_bfloat162 p; p.x = a; p.y = b; return p;
}

// ===========================================================================
// Conversion kernels (vectorized — validated in round 8)
// ===========================================================================
__global__ __launch_bounds__(256)
void convert_emb(const float* __restrict__ Wemb,
                 __nv_bfloat16* __restrict__ eh, __nv_bfloat16* __restrict__ el)
{
    size_t q = (size_t)blockIdx.x * 256 + threadIdx.x;
    if (q < (size_t)V_ * E_ / 4) {
        float4 v = *(const float4*)(Wemb + q * 4);
        __nv_bfloat16 h0,l0,h1,l1,h2,l2,h3,l3;
        split_bf16(v.x,h0,l0); split_bf16(v.y,h1,l1);
        split_bf16(v.z,h2,l2); split_bf16(v.w,h3,l3);
        *(__nv_bfloat162*)(eh + q*4)     = pack2(h0,h1);
        *(__nv_bfloat162*)(eh + q*4 + 2) = pack2(h2,h3);
        *(__nv_bfloat162*)(el + q*4)     = pack2(l0,l1);
        *(__nv_bfloat162*)(el + q*4 + 2) = pack2(l2,l3);
    }
}

__global__ __launch_bounds__(256)
void convert_win0(const float* __restrict__ W, __nv_bfloat16* __restrict__ W3)
{
    size_t q = (size_t)blockIdx.x * 256 + threadIdx.x;
    int n = (int)(q >> 8), kq = (int)(q & 255) * 4;
    float4 v = *(const float4*)(W + (size_t)n * E_ + kq);
    __nv_bfloat16 h0,l0,h1,l1,h2,l2,h3,l3;
    split_bf16(v.x,h0,l0); split_bf16(v.y,h1,l1);
    split_bf16(v.z,h2,l2); split_bf16(v.w,h3,l3);
    __nv_bfloat16* base = W3 + (size_t)n * K3 + kq;
    *(__nv_bfloat162*)(base)          = pack2(h0,h1);
    *(__nv_bfloat162*)(base + 2)      = pack2(h2,h3);
    *(__nv_bfloat162*)(base + 1024)   = pack2(l0,l1);
    *(__nv_bfloat162*)(base + 1026)   = pack2(l2,l3);
    *(__nv_bfloat162*)(base + 2048)   = pack2(h0,h1);
    *(__nv_bfloat162*)(base + 2050)   = pack2(h2,h3);
}

__global__ __launch_bounds__(256)
void convert_wdec(const float* __restrict__ W, __nv_bfloat16* __restrict__ B3)
{
    size_t q = (size_t)blockIdx.x * 256 + threadIdx.x;
    int n = (int)(q >> 8), kq = (int)(q & 255) * 4;
    float4 v = (n < V_) ? *(const float4*)(W + (size_t)n * H_ + kq)
                        : make_float4(0.f,0.f,0.f,0.f);
    __nv_bfloat16 h0,l0,h1,l1,h2,l2,h3,l3;
    split_bf16(v.x,h0,l0); split_bf16(v.y,h1,l1);
    split_bf16(v.z,h2,l2); split_bf16(v.w,h3,l3);
    __nv_bfloat16* base = B3 + (size_t)n * K3 + kq;
    *(__nv_bfloat162*)(base)          = pack2(h0,h1);
    *(__nv_bfloat162*)(base + 2)      = pack2(h2,h3);
    *(__nv_bfloat162*)(base + 1024)   = pack2(l0,l1);
    *(__nv_bfloat162*)(base + 1026)   = pack2(l2,l3);
    *(__nv_bfloat162*)(base + 2048)   = pack2(h0,h1);
    *(__nv_bfloat162*)(base + 2050)   = pack2(h2,h3);
}

// ===========================================================================
// Embedding projection via mma.sync (proven: 128x128, occ=2, 2-stage)
// ===========================================================================
#define DEC_SMEM 65536

__global__ __launch_bounds__(256, 2)
void embed_mma(const __nv_bfloat16* __restrict__ EH,
               const __nv_bfloat16* __restrict__ EL,
               const __nv_bfloat16* __restrict__ W3,
               const int* __restrict__ tokens,
               const float* __restrict__ b0, float* __restrict__ C)
{
    extern __shared__ char dsm[];
    const uint32_t sb = smem_u32(dsm);

    const int tid  = threadIdx.x;
    const int lane = tid & 31, wid = tid >> 5;
    const int wm = wid >> 2, wn = wid & 3;
    const int m0 = blockIdx.y * 128, n0 = blockIdx.x * 128;

    float acc[4][4][4];
    #pragma unroll
    for (int i = 0; i < 4; i++)
        #pragma unroll
        for (int j = 0; j < 4; j++)
            #pragma unroll
            for (int q = 0; q < 4; q++) acc[i][j][q] = 0.f;

    int lrow[4], lcb[4], tokr[4];
    #pragma unroll
    for (int i = 0; i < 4; i++) {
        int idx = tid + i * 256;
        lrow[i] = idx >> 3;
        lcb[i]  = (idx & 7) * 16;
        tokr[i] = tokens[m0 + lrow[i]];
    }

    #define LOAD_TILE_E(ch, buf) do {                                          \
        const uint32_t Ab_ = sb + (buf) * 32768;                               \
        const uint32_t Bb_ = Ab_ + 16384;                                      \
        const __nv_bfloat16* Aarr_ = ((ch) < 32) ? EH : EL;                    \
        const int kc_ = (((ch) < 16) ? (ch) : (((ch) < 32) ? (ch) - 16 : (ch) - 32)) * 64; \
        _Pragma("unroll")                                                      \
        for (int i_ = 0; i_ < 4; i_++) {                                       \
            int r_ = lrow[i_], cb_ = lcb[i_];                                  \
            uint32_t sw_ = (uint32_t)(cb_ ^ ((r_ & 7) << 4));                  \
            cp16(Ab_ + r_ * 128 + sw_,                                         \
                 (const char*)Aarr_ + (((size_t)tokr[i_] * E_ + kc_) * 2 + cb_)); \
            cp16(Bb_ + r_ * 128 + sw_,                                         \
                 (const char*)W3 + (((size_t)(n0 + r_) * K3 + (ch) * 64) * 2 + cb_)); \
        }                                                                      \
        asm volatile("cp.async.commit_group;");                                \
    } while (0)

    LOAD_TILE_E(0, 0);

    const int KCH = K3 / 64;   // 48
    for (int ch = 0; ch < KCH; ++ch) {
        if (ch + 1 < KCH) {
            LOAD_TILE_E(ch + 1, (ch + 1) & 1);
            asm volatile("cp.async.wait_group 1;");
        } else {
            asm volatile("cp.async.wait_group 0;");
        }
        __syncthreads();

        const uint32_t Ab = sb + (ch & 1) * 32768;
        const uint32_t Bb = Ab + 16384;

        #pragma unroll
        for (int ks = 0; ks < 4; ++ks) {
            const int kb2 = ks * 32;
            uint32_t b[8];
            #pragma unroll
            for (int h = 0; h < 2; ++h) {
                int nrow = wn * 32 + h * 16 + ((lane >> 4) & 1) * 8 + (lane & 7);
                int kcol = kb2 + ((lane >> 3) & 1) * 16;
                uint32_t ad = Bb + nrow * 128 + (kcol ^ ((nrow & 7) << 4));
                ldm_x4(b[4*h+0], b[4*h+1], b[4*h+2], b[4*h+3], ad);
            }
            #pragma unroll
            for (int mf = 0; mf < 4; ++mf) {
                int arow = wm * 64 + mf * 16 + (lane & 15);
                int acol = kb2 + ((lane >> 4) & 1) * 16;
                uint32_t ad = Ab + arow * 128 + (acol ^ ((arow & 7) << 4));
                uint32_t a0, a1, a2r, a3r;
                ldm_x4(a0, a1, a2r, a3r, ad);
                #pragma unroll
                for (int nf = 0; nf < 4; ++nf)
                    mma16816d(acc[mf][nf][0], acc[mf][nf][1],
                              acc[mf][nf][2], acc[mf][nf][3],
                              a0, a1, a2r, a3r, b[nf*2], b[nf*2+1]);
            }
        }
        __syncthreads();
    }

    #pragma unroll
    for (int mf = 0; mf < 4; ++mf) {
        const int r0 = m0 + wm * 64 + mf * 16 + (lane >> 2);
        #pragma unroll
        for (int nf = 0; nf < 4; ++nf) {
            const int c = n0 + wn * 32 + nf * 8 + (lane & 3) * 2;
            float2 bia = *(const float2*)(b0 + c);
            float2 v0 = make_float2(acc[mf][nf][0] + bia.x, acc[mf][nf][1] + bia.y);
            float2 v1 = make_float2(acc[mf][nf][2] + bia.x, acc[mf][nf][3] + bia.y);
            *(float2*)(C + (size_t)r0 * H_ + c)     = v0;
            *(float2*)(C + (size_t)(r0+8) * H_ + c) = v1;
        }
    }
}

// ===========================================================================
// Persistent tensor-core recurrence. Round-7 mainloop; parallel split epilogue:
//   wg0 sums P1 and writes h1 (A3, H1f); wg1 sums P0 and writes h0 splits.
// ===========================================================================
#define RSM_H   98304
#define RSM_RED (RSM_H + 65536)
#define RSM_TOTAL (RSM_RED + 128*12*4)

#define LOADCH(ch, buf) do {                                                   \
    const int seg_ = tid & 7;                                                  \
    const int r0_  = tid >> 3;                                                 \
    _Pragma("unroll")                                                          \
    for (int i_ = 0; i_ < 8; i_++) {                                           \
        const int arr_ = i_ >> 1;                                              \
        const int row_ = r0_ + (i_ & 1) * 32;                                  \
        const char* src_ =                                                     \
          (arr_ == 0) ? (const char*)h0h + ((size_t)row_*H_  + (size_t)(ch)*64 + seg_*8)*2 : \
          (arr_ == 1) ? (const char*)h0l + ((size_t)row_*H_  + (size_t)(ch)*64 + seg_*8)*2 : \
          (arr_ == 2) ? (const char*)h1h + ((size_t)row_*h1s + (size_t)(ch)*64 + seg_*8)*2 : \
                        (const char*)h1l + ((size_t)row_*h1s + (size_t)(ch)*64 + seg_*8)*2;  \
        cp16(sb + RSM_H + (buf)*32768 + arr_*8192 + row_*128                   \
                 + (uint32_t)((seg_*16) ^ ((row_ & 7) << 4)), src_);           \
    }                                                                          \
    asm volatile("cp.async.commit_group;");                                    \
} while (0)

__global__ __launch_bounds__(256, 1)
void rnn_persistent_mma(const float* __restrict__ Wh0,
                        const float* __restrict__ Win1,
                        const float* __restrict__ Wh1,
                        const float* __restrict__ b1v,
                        const float* __restrict__ hidden)
{
    extern __shared__ char rsm[];
    const uint32_t sb = smem_u32(rsm);
    const int tid = threadIdx.x, lane = tid & 31, wid = tid >> 5;
    const int wg = wid >> 2, mw = wid & 3;
    const int n0 = blockIdx.x * 8;

    {
        const float* Wm[3] = {Wh0, Win1, Wh1};
        #pragma unroll 1
        for (int m = 0; m < 3; ++m) {
            const float* src = Wm[m] + (size_t)n0 * H_;
            for (int idx = tid; idx < 8 * H_; idx += 256) {
                int r = idx >> 10, k = idx & 1023;
                float v = src[(size_t)r * H_ + k];
                __nv_bfloat16 hh, ll; split_bf16(v, hh, ll);
                uint32_t off = (uint32_t)(2 * k) ^ ((r & 7) << 4);
                *(__nv_bfloat16*)(rsm + m*32768 + r*2048 + off)     = hh;
                *(__nv_bfloat16*)(rsm + m*32768 + (r+8)*2048 + off) = ll;
            }
        }
    }
    for (size_t i = (size_t)blockIdx.x * 256 + tid; i < 2 * (size_t)BH;
         i += (size_t)GRID * 256) {
        __nv_bfloat16 hh, ll; split_bf16(hidden[i], hh, ll);
        if (i < (size_t)BH) { g_hid0h[i] = hh; g_hid0l[i] = ll; }
        else                { g_hp1h[i - BH] = hh; g_hp1l[i - BH] = ll; }
    }
    gsync(0);

    const float b1c0 = b1v[n0 + (lane & 3) * 2];
    const float b1c1 = b1v[n0 + (lane & 3) * 2 + 1];

    for (int tt = -1; tt < T_; ++tt) {
        const __nv_bfloat16 *h0h, *h0l, *h1h, *h1l;
        size_t h1s;
        if (tt < 0) { h0h = g_hid0h; h0l = g_hid0l; }
        else        { h0h = g_h0h[tt & 1]; h0l = g_h0l[tt & 1]; }
        if (tt <= 0) { h1h = g_hp1h; h1l = g_hp1l; h1s = H_; }
        else { h1h = g_A3 + (size_t)(tt - 1) * B_ * K3; h1l = h1h + 2048; h1s = K3; }

        float P0[4] = {0.f,0.f,0.f,0.f}, P1[4] = {0.f,0.f,0.f,0.f};

        LOADCH(0, 0);
        for (int ch = 0; ch < 16; ++ch) {
            if (ch < 15) { LOADCH(ch + 1, (ch + 1) & 1);
                           asm volatile("cp.async.wait_group 1;"); }
            else         { asm volatile("cp.async.wait_group 0;"); }
            __syncthreads();
            const uint32_t hb = sb + RSM_H + (ch & 1) * 32768;
            #pragma unroll
            for (int k16 = 0; k16 < 2; ++k16) {
                const int kb2 = wg * 64 + k16 * 32;
                const int kbw = ch * 128 + kb2;
                const int arow = mw * 16 + (lane & 15);
                const uint32_t aoff = (uint32_t)(kb2 + ((lane >> 4) & 1) * 16)
                                      ^ ((arow & 7) << 4);
                const int brow = ((lane >> 4) & 1) * 8 + (lane & 7);
                const uint32_t boff = (uint32_t)(kbw + ((lane >> 3) & 1) * 16)
                                      ^ ((brow & 7) << 4);

                uint32_t aH0[4], aL0[4];
                ldm_x4(aH0[0], aH0[1], aH0[2], aH0[3], hb + arow*128 + aoff);
                ldm_x4(aL0[0], aL0[1], aL0[2], aL0[3], hb + 8192 + arow*128 + aoff);
                uint32_t b0f[4];
                ldm_x4(b0f[0], b0f[1], b0f[2], b0f[3], sb + brow*2048 + boff);

                mma16816(P0, aH0, b0f[0], b0f[1]);
                mma16816(P0, aH0, b0f[2], b0f[3]);
                mma16816(P0, aL0, b0f[0], b0f[1]);

                if (tt >= 0) {
                    uint32_t aH1[4], aL1[4];
                    ldm_x4(aH1[0], aH1[1], aH1[2], aH1[3], hb + 16384 + arow*128 + aoff);
                    ldm_x4(aL1[0], aL1[1], aL1[2], aL1[3], hb + 24576 + arow*128 + aoff);
                    uint32_t bif[4], bhf[4];
                    ldm_x4(bif[0], bif[1], bif[2], bif[3], sb + 32768 + brow*2048 + boff);
                    ldm_x4(bhf[0], bhf[1], bhf[2], bhf[3], sb + 65536 + brow*2048 + boff);

                    mma16816(P1, aH0, bif[0], bif[1]);
                    mma16816(P1, aH0, bif[2], bif[3]);
                    mma16816(P1, aL0, bif[0], bif[1]);
                    mma16816(P1, aH1, bhf[0], bhf[1]);
                    mma16816(P1, aH1, bhf[2], bhf[3]);
                    mma16816(P1, aL1, bhf[0], bhf[1]);
                }
            }
            __syncthreads();
        }

        // Cross-wg partial exchange: wg1 -> redA (P1 partials), wg0 -> redB (P0)
        float* redA = (float*)(rsm + RSM_RED);           // 128 x 8
        float* redB = redA + 128 * 8;                    // 128 x 4
        const int tl = mw * 32 + lane;
        if (wg == 1) {
            float* r = redA + tl * 8;
            r[0]=P0[0]; r[1]=P0[1]; r[2]=P0[2]; r[3]=P0[3];
            r[4]=P1[0]; r[5]=P1[1]; r[6]=P1[2]; r[7]=P1[3];
        } else {
            float* r = redB + tl * 4;
            r[0]=P0[0]; r[1]=P0[1]; r[2]=P0[2]; r[3]=P0[3];
        }
        __syncthreads();

        const int r0 = mw * 16 + (lane >> 2);
        const int c0 = n0 + (lane & 3) * 2;
        const int rws[4] = {r0, r0, r0 + 8, r0 + 8};
        const int cls[4] = {c0, c0 + 1, c0, c0 + 1};

        if (wg == 0) {
            // L1 epilogue: h1(tt) -> A3 (+ H1f at last step)
            if (tt >= 0) {
                const float* r = redA + tl * 8;
                const float bb[4] = {b1c0, b1c1, b1c0, b1c1};
                #pragma unroll
                for (int j = 0; j < 4; j++) {
                    float v = tanhf((P1[j] + r[j + 4]) + bb[j]);
                    __nv_bfloat16 hh, ll; split_bf16(v, hh, ll);
                    size_t ab = ((size_t)(tt * 64 + rws[j])) * K3 + cls[j];
                    g_A3[ab] = hh; g_A3[ab + 1024] = hh; g_A3[ab + 2048] = ll;
                    if (tt == T_ - 1) g_H1f[rws[j] * H_ + cls[j]] = v;
                }
            }
        } else {
            // L0 epilogue: h0(tt+1) split writes
            if (tt < T_ - 1) {
                const float* r = redA + tl * 8;     // own partials were stored here
                const float* s = redB + tl * 4;     // wg0's P0 partials
                __nv_bfloat16* dh = g_h0h[(tt + 1) & 1];
                __nv_bfloat16* dl = g_h0l[(tt + 1) & 1];
                #pragma unroll
                for (int j = 0; j < 4; j++) {
                    float u = g_U0[(size_t)(tt + 1) * BH + rws[j] * H_ + cls[j]];
                    float v = tanhf((s[j] + r[j]) + u);
                    __nv_bfloat16 hh, ll; split_bf16(v, hh, ll);
                    dh[rws[j] * H_ + cls[j]] = hh;
                    dl[rws[j] * H_ + cls[j]] = ll;
                }
            }
        }
        gsync(tt + 2);
    }
}

// ===========================================================================
// mma.sync bf16 decoder GEMM (round-7 proven: 128x128, occ=2, 2-stage)
// ===========================================================================
__global__ __launch_bounds__(256, 2)
void decoder_mma(const __nv_bfloat16* __restrict__ A3,
                 const __nv_bfloat16* __restrict__ B3,
                 const float* __restrict__ bdec, float* __restrict__ C)
{
    extern __shared__ char dsm[];
    const uint32_t sb = smem_u32(dsm);

    const int tid  = threadIdx.x;
    const int lane = tid & 31, wid = tid >> 5;
    const int wm = wid >> 2, wn = wid & 3;
    const int m0 = blockIdx.y * 128, n0 = blockIdx.x * 128;

    float acc[4][4][4];
    #pragma unroll
    for (int i = 0; i < 4; i++)
        #pragma unroll
        for (int j = 0; j < 4; j++)
            #pragma unroll
            for (int q = 0; q < 4; q++) acc[i][j][q] = 0.f;

    int lrow[4], lcb[4];
    #pragma unroll
    for (int i = 0; i < 4; i++) {
        int idx = tid + i * 256;
        lrow[i] = idx >> 3;
        lcb[i]  = (idx & 7) * 16;
    }

    #define LOAD_TILE(ch, buf) do {                                            \
        const uint32_t Ab_ = sb + (buf) * 32768;                               \
        const uint32_t Bb_ = Ab_ + 16384;                                      \
        _Pragma("unroll")                                                      \
        for (int i_ = 0; i_ < 4; i_++) {                                       \
            int r_ = lrow[i_], cb_ = lcb[i_];                                  \
            uint32_t sw_ = (uint32_t)(cb_ ^ ((r_ & 7) << 4));                  \
            cp16(Ab_ + r_ * 128 + sw_,                                         \
                 (const char*)A3 + (((size_t)(m0 + r_) * K3 + (ch) * 64) * 2 + cb_)); \
            cp16(Bb_ + r_ * 128 + sw_,                                         \
                 (const char*)B3 + (((size_t)(n0 + r_) * K3 + (ch) * 64) * 2 + cb_)); \
        }                                                                      \
        asm volatile("cp.async.commit_group;");                                \
    } while (0)

    LOAD_TILE(0, 0);

    const int KCH = K3 / 64;   // 48
    for (int ch = 0; ch < KCH; ++ch) {
        if (ch + 1 < KCH) {
            LOAD_TILE(ch + 1, (ch + 1) & 1);
            asm volatile("cp.async.wait_group 1;");
        } else {
            asm volatile("cp.async.wait_group 0;");
        }
        __syncthreads();

        const uint32_t Ab = sb + (ch & 1) * 32768;
        const uint32_t Bb = Ab + 16384;

        #pragma unroll
        for (int ks = 0; ks < 4; ++ks) {
            const int kb2 = ks * 32;
            uint32_t b[8];
            #pragma unroll
            for (int h = 0; h < 2; ++h) {
                int nrow = wn * 32 + h * 16 + ((lane >> 4) & 1) * 8 + (lane & 7);
                int kcol = kb2 + ((lane >> 3) & 1) * 16;
                uint32_t ad = Bb + nrow * 128 + (kcol ^ ((nrow & 7) << 4));
                ldm_x4(b[4*h+0], b[4*h+1], b[4*h+2], b[4*h+3], ad);
            }
            #pragma unroll
            for (int mf = 0; mf < 4; ++mf) {
                int arow = wm * 64 + mf * 16 + (lane & 15);
                int acol = kb2 + ((lane >> 4) & 1) * 16;
                uint32_t ad = Ab + arow * 128 + (acol ^ ((arow & 7) << 4));
                uint32_t a0, a1, a2r, a3r;
                ldm_x4(a0, a1, a2r, a3r, ad);
                #pragma unroll
                for (int nf = 0; nf < 4; ++nf)
                    mma16816d(acc[mf][nf][0], acc[mf][nf][1],
                              acc[mf][nf][2], acc[mf][nf][3],
                              a0, a1, a2r, a3r, b[nf*2], b[nf*2+1]);
            }
        }
        __syncthreads();
    }

    #pragma unroll
    for (int mf = 0; mf < 4; ++mf) {
        const int r0 = m0 + wm * 64 + mf * 16 + (lane >> 2);
        #pragma unroll
        for (int nf = 0; nf < 4; ++nf) {
            const int c = n0 + wn * 32 + nf * 8 + (lane & 3) * 2;
            if (c < V_) {
                float2 bia = *(const float2*)(bdec + c);
                float2 v0 = make_float2(acc[mf][nf][0] + bia.x, acc[mf][nf][1] + bia.y);
                float2 v1 = make_float2(acc[mf][nf][2] + bia.x, acc[mf][nf][3] + bia.y);
                *(float2*)(C + (size_t)r0 * V_ + c)     = v0;
                *(float2*)(C + (size_t)(r0+8) * V_ + c) = v1;
            }
        }
    }
}

// ===========================================================================
// Final hidden state
// ===========================================================================
__global__ void copy_final(const __nv_bfloat16* __restrict__ h0hh,
                           const __nv_bfloat16* __restrict__ h0ll,
                           const float* __restrict__ h1f,
                           float* __restrict__ out)
{
    int i = blockIdx.x * blockDim.x + threadIdx.x;
    if (i < BH) {
        out[i]      = __bfloat162float(h0hh[i]) + __bfloat162float(h0ll[i]);
        out[BH + i] = h1f[i];
    }
}

extern "C" void kernel_launch(void* const* d_in, const int* in_sizes, int n_in,
                              void* d_out, int out_size)
{
    const float* emb    = (const float*)d_in[0];
    const float* W_in0  = (const float*)d_in[1];
    const float* Wh0    = (const float*)d_in[2];
    const float* b0     = (const float*)d_in[3];
    const float* W_in1  = (const float*)d_in[4];
    const float* Wh1    = (const float*)d_in[5];
    const float* b1     = (const float*)d_in[6];
    const float* Wdec   = (const float*)d_in[7];
    const float* bdec   = (const float*)d_in[8];
    const float* hidden = (const float*)d_in[9];
    const int*   tokens = (const int*)d_in[10];

    float* out    = (float*)d_out;
    float* logits = out;
    float* hfin   = out + (size_t)M_ * V_;

    float *U0 = nullptr, *H1f = nullptr;
    __nv_bfloat16 *A3 = nullptr, *B3 = nullptr, *h0h = nullptr, *h0l = nullptr;
    __nv_bfloat16 *EH = nullptr, *EL = nullptr, *W03 = nullptr;
    cudaGetSymbolAddress((void**)&U0,  g_U0);
    cudaGetSymbolAddress((void**)&H1f, g_H1f);
    cudaGetSymbolAddress((void**)&A3,  g_A3);
    cudaGetSymbolAddress((void**)&B3,  g_B3);
    cudaGetSymbolAddress((void**)&h0h, g_h0h);
    cudaGetSymbolAddress((void**)&h0l, g_h0l);
    cudaGetSymbolAddress((void**)&EH,  g_embH);
    cudaGetSymbolAddress((void**)&EL,  g_embL);
    cudaGetSymbolAddress((void**)&W03, g_W03);

    cudaFuncSetAttribute(rnn_persistent_mma,
                         cudaFuncAttributeMaxDynamicSharedMemorySize, RSM_TOTAL);
    cudaFuncSetAttribute(decoder_mma,
                         cudaFuncAttributeMaxDynamicSharedMemorySize, DEC_SMEM);
    cudaFuncSetAttribute(embed_mma,
                         cudaFuncAttributeMaxDynamicSharedMemorySize, DEC_SMEM);

    // 0) splits (vectorized)
    reset_bar_kernel<<<1, 256>>>();
    convert_emb<<<(int)(((size_t)V_ * E_ / 4 + 255) / 256), 256>>>(emb, EH, EL);
    convert_win0<<<(int)(((size_t)H_ * 256) / 256), 256>>>(W_in0, W03);
    convert_wdec<<<(int)(((size_t)VP * 256) / 256), 256>>>(Wdec, B3);

    // 1) U0 = emb[tokens] @ W_in0^T + b0
    embed_mma<<<dim3(H_ / 128, M_ / 128), 256, DEC_SMEM>>>(EH, EL, W03, tokens,
                                                           b0, U0);

    // 2) Persistent tensor-core recurrence (parallel split epilogue)
    rnn_persistent_mma<<<GRID, NT, RSM_TOTAL>>>(Wh0, W_in1, Wh1, b1, hidden);

    // 3) logits = A3 @ B3^T + bdec
    decoder_mma<<<dim3(VP / 128, M_ / 128), 256, DEC_SMEM>>>(A3, B3, bdec, logits);

    // 4) final hidden states
    copy_final<<<(BH + 255) / 256, 256>>>(h0h + BH, h0l + BH, H1f, hfin);

    (void)in_sizes; (void)n_in; (void)out_size;
}

// round 14
// speedup vs baseline: 1.7336x; 1.1453x over previous
#include <cuda_runtime.h>
#include <cuda_bf16.h>
#include <cuda_fp16.h>
#include <math.h>
#include <stdint.h>

#define T_ 128
#define B_ 64
#define E_ 1024
#define H_ 1024
#define V_ 10000
#define VP 10112              // V padded to 128 (79*128)
#define M_ (T_*B_)            // 8192
#define BH (B_*H_)
#define K3 3072               // bf16 3-term split (embed + recurrence)
#define KD 2048               // fp16 2-term decoder A: [Ah|Al]

#define GRID 128
#define NT 256

// Scratch (no allocs allowed)
__device__ float g_U0[(size_t)M_*H_];
__device__ float g_H1f[BH];
__device__ unsigned int g_bar[256];
__device__ __nv_bfloat16 g_A3[(size_t)M_*K3];     // recurrence h1 (hi @0, lo @2048)
__device__ __half        g_A2f[(size_t)M_*KD];    // decoder A: [Ah|Al] fp16
__device__ __half        g_B1f[(size_t)VP*H_];    // decoder B: Bh fp16 (single copy)
__device__ __nv_bfloat16 g_h0h[2][BH], g_h0l[2][BH];
__device__ __nv_bfloat16 g_hid0h[BH], g_hid0l[BH];
__device__ __nv_bfloat16 g_hp1h[BH],  g_hp1l[BH];
__device__ __nv_bfloat16 g_embH[(size_t)V_*E_];
__device__ __nv_bfloat16 g_embL[(size_t)V_*E_];
__device__ __nv_bfloat16 g_W03[(size_t)H_*K3];

// ===========================================================================
// Grid barrier + helpers
// ===========================================================================
__global__ void reset_bar_kernel() {
    if (threadIdx.x < 256) g_bar[threadIdx.x] = 0;
}

__device__ __forceinline__ void gsync(int slot) {
    __syncthreads();
    if (threadIdx.x == 0) {
        __threadfence();
        atomicAdd(&g_bar[slot], 1u);
        while (*((volatile unsigned int*)&g_bar[slot]) < GRID) { }
        __threadfence();
    }
    __syncthreads();
}

__device__ __forceinline__ void split_bf16(float x, __nv_bfloat16& h, __nv_bfloat16& l) {
    h = __float2bfloat16(x);
    l = __float2bfloat16(x - __bfloat162float(h));
}

__device__ __forceinline__ uint32_t smem_u32(const void* p) {
    uint32_t a;
    asm("{ .reg .u64 t; cvta.to.shared.u64 t, %1; cvt.u32.u64 %0, t; }"
        : "=r"(a) : "l"(p));
    return a;
}
__device__ __forceinline__ void cp16(uint32_t dst, const void* src) {
    asm volatile("cp.async.cg.shared.global [%0], [%1], 16;"
                 :: "r"(dst), "l"(src));
}
__device__ __forceinline__ void ldm_x4(uint32_t& r0, uint32_t& r1,
                                       uint32_t& r2, uint32_t& r3, uint32_t addr) {
    asm volatile("ldmatrix.sync.aligned.m8n8.x4.shared.b16 {%0,%1,%2,%3}, [%4];"
                 : "=r"(r0), "=r"(r1), "=r"(r2), "=r"(r3) : "r"(addr));
}
__device__ __forceinline__ void mma16816(float* d,
                                         const uint32_t* a,
                                         uint32_t b0, uint32_t b1) {
    asm volatile("mma.sync.aligned.m16n8k16.row.col.f32.bf16.bf16.f32 "
                 "{%0,%1,%2,%3}, {%4,%5,%6,%7}, {%8,%9}, {%0,%1,%2,%3};"
                 : "+f"(d[0]), "+f"(d[1]), "+f"(d[2]), "+f"(d[3])
                 : "r"(a[0]), "r"(a[1]), "r"(a[2]), "r"(a[3]), "r"(b0), "r"(b1));
}
__device__ __forceinline__ void mma16816d(float& d0, float& d1, float& d2, float& d3,
                                          uint32_t a0, uint32_t a1, uint32_t a2, uint32_t a3,
                                          uint32_t b0, uint32_t b1) {
    asm volatile("mma.sync.aligned.m16n8k16.row.col.f32.bf16.bf16.f32 "
                 "{%0,%1,%2,%3}, {%4,%5,%6,%7}, {%8,%9}, {%0,%1,%2,%3};"
                 : "+f"(d0), "+f"(d1), "+f"(d2), "+f"(d3)
                 : "r"(a0), "r"(a1), "r"(a2), "r"(a3), "r"(b0), "r"(b1));
}
__device__ __forceinline__ void mma16816h(float& d0, float& d1, float& d2, float& d3,
                                          uint32_t a0, uint32_t a1, uint32_t a2, uint32_t a3,
                                          uint32_t b0, uint32_t b1) {
    asm volatile("mma.sync.aligned.m16n8k16.row.col.f32.f16.f16.f32 "
                 "{%0,%1,%2,%3}, {%4,%5,%6,%7}, {%8,%9}, {%0,%1,%2,%3};"
                 : "+f"(d0), "+f"(d1), "+f"(d2), "+f"(d3)
                 : "r"(a0), "r"(a1), "r"(a2), "r"(a3), "r"(b0), "r"(b1));
}
__device__ __forceinline__ __nv_bfloat162 pack2(__nv_bfloat16 a, __nv_bfloat16 b) {
    __nv_bfloat162 p; p.x = a; p.y = b; return p;
}

// ===========================================================================
// Conversion kernels
// ===========================================================================
__global__ __launch_bounds__(256)
void convert_emb(const float* __restrict__ Wemb,
                 __nv_bfloat16* __restrict__ eh, __nv_bfloat16* __restrict__ el)
{
    size_t q = (size_t)blockIdx.x * 256 + threadIdx.x;
    if (q < (size_t)V_ * E_ / 4) {
        float4 v = *(const float4*)(Wemb + q * 4);
        __nv_bfloat16 h0,l0,h1,l1,h2,l2,h3,l3;
        split_bf16(v.x,h0,l0); split_bf16(v.y,h1,l1);
        split_bf16(v.z,h2,l2); split_bf16(v.w,h3,l3);
        *(__nv_bfloat162*)(eh + q*4)     = pack2(h0,h1);
        *(__nv_bfloat162*)(eh + q*4 + 2) = pack2(h2,h3);
        *(__nv_bfloat162*)(el + q*4)     = pack2(l0,l1);
        *(__nv_bfloat162*)(el + q*4 + 2) = pack2(l2,l3);
    }
}

__global__ __launch_bounds__(256)
void convert_win0(const float* __restrict__ W, __nv_bfloat16* __restrict__ W3)
{
    size_t q = (size_t)blockIdx.x * 256 + threadIdx.x;
    int n = (int)(q >> 8), kq = (int)(q & 255) * 4;
    float4 v = *(const float4*)(W + (size_t)n * E_ + kq);
    __nv_bfloat16 h0,l0,h1,l1,h2,l2,h3,l3;
    split_bf16(v.x,h0,l0); split_bf16(v.y,h1,l1);
    split_bf16(v.z,h2,l2); split_bf16(v.w,h3,l3);
    __nv_bfloat16* base = W3 + (size_t)n * K3 + kq;
    *(__nv_bfloat162*)(base)          = pack2(h0,h1);
    *(__nv_bfloat162*)(base + 2)      = pack2(h2,h3);
    *(__nv_bfloat162*)(base + 1024)   = pack2(l0,l1);
    *(__nv_bfloat162*)(base + 1026)   = pack2(l2,l3);
    *(__nv_bfloat162*)(base + 2048)   = pack2(h0,h1);
    *(__nv_bfloat162*)(base + 2050)   = pack2(h2,h3);
}

// Wdec -> single fp16 copy (decoder B)
__global__ __launch_bounds__(256)
void convert_wdec(const float* __restrict__ W, __half* __restrict__ Bf)
{
    size_t q = (size_t)blockIdx.x * 256 + threadIdx.x;
    int n = (int)(q >> 8), kq = (int)(q & 255) * 4;
    float4 v = (n < V_) ? *(const float4*)(W + (size_t)n * H_ + kq)
                        : make_float4(0.f,0.f,0.f,0.f);
    __half2 p0 = __floats2half2_rn(v.x, v.y);
    __half2 p1 = __floats2half2_rn(v.z, v.w);
    *(__half2*)(Bf + (size_t)n * H_ + kq)     = p0;
    *(__half2*)(Bf + (size_t)n * H_ + kq + 2) = p1;
}

// ===========================================================================
// Embedding projection via mma.sync (proven: 128x128, occ=2, 2-stage, bf16 K3)
// ===========================================================================
#define DEC_SMEM 65536

__global__ __launch_bounds__(256, 2)
void embed_mma(const __nv_bfloat16* __restrict__ EH,
               const __nv_bfloat16* __restrict__ EL,
               const __nv_bfloat16* __restrict__ W3,
               const int* __restrict__ tokens,
               const float* __restrict__ b0, float* __restrict__ C)
{
    extern __shared__ char dsm[];
    const uint32_t sb = smem_u32(dsm);

    const int tid  = threadIdx.x;
    const int lane = tid & 31, wid = tid >> 5;
    const int wm = wid >> 2, wn = wid & 3;
    const int m0 = blockIdx.y * 128, n0 = blockIdx.x * 128;

    float acc[4][4][4];
    #pragma unroll
    for (int i = 0; i < 4; i++)
        #pragma unroll
        for (int j = 0; j < 4; j++)
            #pragma unroll
            for (int q = 0; q < 4; q++) acc[i][j][q] = 0.f;

    int lrow[4], lcb[4], tokr[4];
    #pragma unroll
    for (int i = 0; i < 4; i++) {
        int idx = tid + i * 256;
        lrow[i] = idx >> 3;
        lcb[i]  = (idx & 7) * 16;
        tokr[i] = tokens[m0 + lrow[i]];
    }

    #define LOAD_TILE_E(ch, buf) do {                                          \
        const uint32_t Ab_ = sb + (buf) * 32768;                               \
        const uint32_t Bb_ = Ab_ + 16384;                                      \
        const __nv_bfloat16* Aarr_ = ((ch) < 32) ? EH : EL;                    \
        const int kc_ = (((ch) < 16) ? (ch) : (((ch) < 32) ? (ch) - 16 : (ch) - 32)) * 64; \
        _Pragma("unroll")                                                      \
        for (int i_ = 0; i_ < 4; i_++) {                                       \
            int r_ = lrow[i_], cb_ = lcb[i_];                                  \
            uint32_t sw_ = (uint32_t)(cb_ ^ ((r_ & 7) << 4));                  \
            cp16(Ab_ + r_ * 128 + sw_,                                         \
                 (const char*)Aarr_ + (((size_t)tokr[i_] * E_ + kc_) * 2 + cb_)); \
            cp16(Bb_ + r_ * 128 + sw_,                                         \
                 (const char*)W3 + (((size_t)(n0 + r_) * K3 + (ch) * 64) * 2 + cb_)); \
        }                                                                      \
        asm volatile("cp.async.commit_group;");                                \
    } while (0)

    LOAD_TILE_E(0, 0);

    const int KCH = K3 / 64;   // 48
    for (int ch = 0; ch < KCH; ++ch) {
        if (ch + 1 < KCH) {
            LOAD_TILE_E(ch + 1, (ch + 1) & 1);
            asm volatile("cp.async.wait_group 1;");
        } else {
            asm volatile("cp.async.wait_group 0;");
        }
        __syncthreads();

        const uint32_t Ab = sb + (ch & 1) * 32768;
        const uint32_t Bb = Ab + 16384;

        #pragma unroll
        for (int ks = 0; ks < 4; ++ks) {
            const int kb2 = ks * 32;
            uint32_t b[8];
            #pragma unroll
            for (int h = 0; h < 2; ++h) {
                int nrow = wn * 32 + h * 16 + ((lane >> 4) & 1) * 8 + (lane & 7);
                int kcol = kb2 + ((lane >> 3) & 1) * 16;
                uint32_t ad = Bb + nrow * 128 + (kcol ^ ((nrow & 7) << 4));
                ldm_x4(b[4*h+0], b[4*h+1], b[4*h+2], b[4*h+3], ad);
            }
            #pragma unroll
            for (int mf = 0; mf < 4; ++mf) {
                int arow = wm * 64 + mf * 16 + (lane & 15);
                int acol = kb2 + ((lane >> 4) & 1) * 16;
                uint32_t ad = Ab + arow * 128 + (acol ^ ((arow & 7) << 4));
                uint32_t a0, a1, a2r, a3r;
                ldm_x4(a0, a1, a2r, a3r, ad);
                #pragma unroll
                for (int nf = 0; nf < 4; ++nf)
                    mma16816d(acc[mf][nf][0], acc[mf][nf][1],
                              acc[mf][nf][2], acc[mf][nf][3],
                              a0, a1, a2r, a3r, b[nf*2], b[nf*2+1]);
            }
        }
        __syncthreads();
    }

    #pragma unroll
    for (int mf = 0; mf < 4; ++mf) {
        const int r0 = m0 + wm * 64 + mf * 16 + (lane >> 2);
        #pragma unroll
        for (int nf = 0; nf < 4; ++nf) {
            const int c = n0 + wn * 32 + nf * 8 + (lane & 3) * 2;
            float2 bia = *(const float2*)(b0 + c);
            float2 v0 = make_float2(acc[mf][nf][0] + bia.x, acc[mf][nf][1] + bia.y);
            float2 v1 = make_float2(acc[mf][nf][2] + bia.x, acc[mf][nf][3] + bia.y);
            *(float2*)(C + (size_t)r0 * H_ + c)     = v0;
            *(float2*)(C + (size_t)(r0+8) * H_ + c) = v1;
        }
    }
}

// ===========================================================================
// Persistent tensor-core recurrence. Round-13 proven structure + parallel
// split epilogue; wg0 now also writes the fp16 decoder A ([Ah|Al]).
// ===========================================================================
#define RSM_H   98304
#define RSM_RED (RSM_H + 65536)
#define RSM_TOTAL (RSM_RED + 128*12*4)

#define LOADCH(ch, buf) do {                                                   \
    const int seg_ = tid & 7;                                                  \
    const int r0_  = tid >> 3;                                                 \
    _Pragma("unroll")                                                          \
    for (int i_ = 0; i_ < 8; i_++) {                                           \
        const int arr_ = i_ >> 1;                                              \
        const int row_ = r0_ + (i_ & 1) * 32;                                  \
        const char* src_ =                                                     \
          (arr_ == 0) ? (const char*)h0h + ((size_t)row_*H_  + (size_t)(ch)*64 + seg_*8)*2 : \
          (arr_ == 1) ? (const char*)h0l + ((size_t)row_*H_  + (size_t)(ch)*64 + seg_*8)*2 : \
          (arr_ == 2) ? (const char*)h1h + ((size_t)row_*h1s + (size_t)(ch)*64 + seg_*8)*2 : \
                        (const char*)h1l + ((size_t)row_*h1s + (size_t)(ch)*64 + seg_*8)*2;  \
        cp16(sb + RSM_H + (buf)*32768 + arr_*8192 + row_*128                   \
                 + (uint32_t)((seg_*16) ^ ((row_ & 7) << 4)), src_);           \
    }                                                                          \
    asm volatile("cp.async.commit_group;");                                    \
} while (0)

__global__ __launch_bounds__(256, 1)
void rnn_persistent_mma(const float* __restrict__ Wh0,
                        const float* __restrict__ Win1,
                        const float* __restrict__ Wh1,
                        const float* __restrict__ b1v,
                        const float* __restrict__ hidden)
{
    extern __shared__ char rsm[];
    const uint32_t sb = smem_u32(rsm);
    const int tid = threadIdx.x, lane = tid & 31, wid = tid >> 5;
    const int wg = wid >> 2, mw = wid & 3;
    const int n0 = blockIdx.x * 8;

    {
        const float* Wm[3] = {Wh0, Win1, Wh1};
        #pragma unroll 1
        for (int m = 0; m < 3; ++m) {
            const float* src = Wm[m] + (size_t)n0 * H_;
            for (int idx = tid; idx < 8 * H_; idx += 256) {
                int r = idx >> 10, k = idx & 1023;
                float v = src[(size_t)r * H_ + k];
                __nv_bfloat16 hh, ll; split_bf16(v, hh, ll);
                uint32_t off = (uint32_t)(2 * k) ^ ((r & 7) << 4);
                *(__nv_bfloat16*)(rsm + m*32768 + r*2048 + off)     = hh;
                *(__nv_bfloat16*)(rsm + m*32768 + (r+8)*2048 + off) = ll;
            }
        }
    }
    for (size_t i = (size_t)blockIdx.x * 256 + tid; i < 2 * (size_t)BH;
         i += (size_t)GRID * 256) {
        __nv_bfloat16 hh, ll; split_bf16(hidden[i], hh, ll);
        if (i < (size_t)BH) { g_hid0h[i] = hh; g_hid0l[i] = ll; }
        else                { g_hp1h[i - BH] = hh; g_hp1l[i - BH] = ll; }
    }
    gsync(0);

    const float b1c0 = b1v[n0 + (lane & 3) * 2];
    const float b1c1 = b1v[n0 + (lane & 3) * 2 + 1];

    for (int tt = -1; tt < T_; ++tt) {
        const __nv_bfloat16 *h0h, *h0l, *h1h, *h1l;
        size_t h1s;
        if (tt < 0) { h0h = g_hid0h; h0l = g_hid0l; }
        else        { h0h = g_h0h[tt & 1]; h0l = g_h0l[tt & 1]; }
        if (tt <= 0) { h1h = g_hp1h; h1l = g_hp1l; h1s = H_; }
        else { h1h = g_A3 + (size_t)(tt - 1) * B_ * K3; h1l = h1h + 2048; h1s = K3; }

        float P0[4] = {0.f,0.f,0.f,0.f}, P1[4] = {0.f,0.f,0.f,0.f};

        LOADCH(0, 0);
        for (int ch = 0; ch < 16; ++ch) {
            if (ch < 15) { LOADCH(ch + 1, (ch + 1) & 1);
                           asm volatile("cp.async.wait_group 1;"); }
            else         { asm volatile("cp.async.wait_group 0;"); }
            __syncthreads();
            const uint32_t hb = sb + RSM_H + (ch & 1) * 32768;
            #pragma unroll
            for (int k16 = 0; k16 < 2; ++k16) {
                const int kb2 = wg * 64 + k16 * 32;
                const int kbw = ch * 128 + kb2;
                const int arow = mw * 16 + (lane & 15);
                const uint32_t aoff = (uint32_t)(kb2 + ((lane >> 4) & 1) * 16)
                                      ^ ((arow & 7) << 4);
                const int brow = ((lane >> 4) & 1) * 8 + (lane & 7);
                const uint32_t boff = (uint32_t)(kbw + ((lane >> 3) & 1) * 16)
                                      ^ ((brow & 7) << 4);

                uint32_t aH0[4], aL0[4];
                ldm_x4(aH0[0], aH0[1], aH0[2], aH0[3], hb + arow*128 + aoff);
                ldm_x4(aL0[0], aL0[1], aL0[2], aL0[3], hb + 8192 + arow*128 + aoff);
                uint32_t b0f[4];
                ldm_x4(b0f[0], b0f[1], b0f[2], b0f[3], sb + brow*2048 + boff);

                mma16816(P0, aH0, b0f[0], b0f[1]);
                mma16816(P0, aH0, b0f[2], b0f[3]);
                mma16816(P0, aL0, b0f[0], b0f[1]);

                if (tt >= 0) {
                    uint32_t aH1[4], aL1[4];
                    ldm_x4(aH1[0], aH1[1], aH1[2], aH1[3], hb + 16384 + arow*128 + aoff);
                    ldm_x4(aL1[0], aL1[1], aL1[2], aL1[3], hb + 24576 + arow*128 + aoff);
                    uint32_t bif[4], bhf[4];
                    ldm_x4(bif[0], bif[1], bif[2], bif[3], sb + 32768 + brow*2048 + boff);
                    ldm_x4(bhf[0], bhf[1], bhf[2], bhf[3], sb + 65536 + brow*2048 + boff);

                    mma16816(P1, aH0, bif[0], bif[1]);
                    mma16816(P1, aH0, bif[2], bif[3]);
                    mma16816(P1, aL0, bif[0], bif[1]);
                    mma16816(P1, aH1, bhf[0], bhf[1]);
                    mma16816(P1, aH1, bhf[2], bhf[3]);
                    mma16816(P1, aL1, bhf[0], bhf[1]);
                }
            }
            __syncthreads();
        }

        // Cross-wg partial exchange: wg1 -> redA (P0+P1), wg0 -> redB (P0)
        float* redA = (float*)(rsm + RSM_RED);           // 128 x 8
        float* redB = redA + 128 * 8;                    // 128 x 4
        const int tl = mw * 32 + lane;
        if (wg == 1) {
            float* r = redA + tl * 8;
            r[0]=P0[0]; r[1]=P0[1]; r[2]=P0[2]; r[3]=P0[3];
            r[4]=P1[0]; r[5]=P1[1]; r[6]=P1[2]; r[7]=P1[3];
        } else {
            float* r = redB + tl * 4;
            r[0]=P0[0]; r[1]=P0[1]; r[2]=P0[2]; r[3]=P0[3];
        }
        __syncthreads();

        const int r0 = mw * 16 + (lane >> 2);
        const int c0 = n0 + (lane & 3) * 2;
        const int rws[4] = {r0, r0, r0 + 8, r0 + 8};
        const int cls[4] = {c0, c0 + 1, c0, c0 + 1};

        if (wg == 0) {
            // L1 epilogue: h1(tt) -> A3 (bf16 hi/lo) + A2f (fp16 [Ah|Al])
            if (tt >= 0) {
                const float* r = redA + tl * 8;
                const float bb[4] = {b1c0, b1c1, b1c0, b1c1};
                #pragma unroll
                for (int j = 0; j < 4; j++) {
                    float v = tanhf((P1[j] + r[j + 4]) + bb[j]);
                    __nv_bfloat16 hh, ll; split_bf16(v, hh, ll);
                    size_t row = (size_t)(tt * 64 + rws[j]);
                    size_t ab = row * K3 + cls[j];
                    g_A3[ab] = hh; g_A3[ab + 2048] = ll;
                    __half fh = __float2half_rn(v);
                    __half fl = __float2half_rn(v - __half2float(fh));
                    size_t af = row * KD + cls[j];
                    g_A2f[af] = fh; g_A2f[af + 1024] = fl;
                    if (tt == T_ - 1) g_H1f[rws[j] * H_ + cls[j]] = v;
                }
            }
        } else {
            // L0 epilogue: h0(tt+1) split writes
            if (tt < T_ - 1) {
                const float* r = redA + tl * 8;
                const float* s = redB + tl * 4;
                __nv_bfloat16* dh = g_h0h[(tt + 1) & 1];
                __nv_bfloat16* dl = g_h0l[(tt + 1) & 1];
                #pragma unroll
                for (int j = 0; j < 4; j++) {
                    float u = g_U0[(size_t)(tt + 1) * BH + rws[j] * H_ + cls[j]];
                    float v = tanhf((s[j] + r[j]) + u);
                    __nv_bfloat16 hh, ll; split_bf16(v, hh, ll);
                    dh[rws[j] * H_ + cls[j]] = hh;
                    dl[rws[j] * H_ + cls[j]] = ll;
                }
            }
        }
        gsync(tt + 2);
    }
}

// ===========================================================================
// Decoder GEMM: fp16 2-term. A=[Ah|Al] (KD=2048), B=Bh single copy (H_=1024,
// chunk index ch&15). Structure identical to proven 128x128/occ2/2-stage.
// ===========================================================================
__global__ __launch_bounds__(256, 2)
void decoder_mma(const __half* __restrict__ A2,
                 const __half* __restrict__ B1,
                 const float* __restrict__ bdec, float* __restrict__ C)
{
    extern __shared__ char dsm[];
    const uint32_t sb = smem_u32(dsm);

    const int tid  = threadIdx.x;
    const int lane = tid & 31, wid = tid >> 5;
    const int wm = wid >> 2, wn = wid & 3;
    const int m0 = blockIdx.y * 128, n0 = blockIdx.x * 128;

    float acc[4][4][4];
    #pragma unroll
    for (int i = 0; i < 4; i++)
        #pragma unroll
        for (int j = 0; j < 4; j++)
            #pragma unroll
            for (int q = 0; q < 4; q++) acc[i][j][q] = 0.f;

    int lrow[4], lcb[4];
    #pragma unroll
    for (int i = 0; i < 4; i++) {
        int idx = tid + i * 256;
        lrow[i] = idx >> 3;
        lcb[i]  = (idx & 7) * 16;
    }

    #define LOAD_TILE(ch, buf) do {                                            \
        const uint32_t Ab_ = sb + (buf) * 32768;                               \
        const uint32_t Bb_ = Ab_ + 16384;                                      \
        const int kcB_ = ((ch) & 15) * 64;                                     \
        _Pragma("unroll")                                                      \
        for (int i_ = 0; i_ < 4; i_++) {                                       \
            int r_ = lrow[i_], cb_ = lcb[i_];                                  \
            uint32_t sw_ = (uint32_t)(cb_ ^ ((r_ & 7) << 4));                  \
            cp16(Ab_ + r_ * 128 + sw_,                                         \
                 (const char*)A2 + (((size_t)(m0 + r_) * KD + (ch) * 64) * 2 + cb_)); \
            cp16(Bb_ + r_ * 128 + sw_,                                         \
                 (const char*)B1 + (((size_t)(n0 + r_) * H_ + kcB_) * 2 + cb_)); \
        }                                                                      \
        asm volatile("cp.async.commit_group;");                                \
    } while (0)

    LOAD_TILE(0, 0);

    const int KCH = KD / 64;   // 32
    for (int ch = 0; ch < KCH; ++ch) {
        if (ch + 1 < KCH) {
            LOAD_TILE(ch + 1, (ch + 1) & 1);
            asm volatile("cp.async.wait_group 1;");
        } else {
            asm volatile("cp.async.wait_group 0;");
        }
        __syncthreads();

        const uint32_t Ab = sb + (ch & 1) * 32768;
        const uint32_t Bb = Ab + 16384;

        #pragma unroll
        for (int ks = 0; ks < 4; ++ks) {
            const int kb2 = ks * 32;
            uint32_t b[8];
            #pragma unroll
            for (int h = 0; h < 2; ++h) {
                int nrow = wn * 32 + h * 16 + ((lane >> 4) & 1) * 8 + (lane & 7);
                int kcol = kb2 + ((lane >> 3) & 1) * 16;
                uint32_t ad = Bb + nrow * 128 + (kcol ^ ((nrow & 7) << 4));
                ldm_x4(b[4*h+0], b[4*h+1], b[4*h+2], b[4*h+3], ad);
            }
            #pragma unroll
            for (int mf = 0; mf < 4; ++mf) {
                int arow = wm * 64 + mf * 16 + (lane & 15);
                int acol = kb2 + ((lane >> 4) & 1) * 16;
                uint32_t ad = Ab + arow * 128 + (acol ^ ((arow & 7) << 4));
                uint32_t a0, a1, a2r, a3r;
                ldm_x4(a0, a1, a2r, a3r, ad);
                #pragma unroll
                for (int nf = 0; nf < 4; ++nf)
                    mma16816h(acc[mf][nf][0], acc[mf][nf][1],
                              acc[mf][nf][2], acc[mf][nf][3],
                              a0, a1, a2r, a3r, b[nf*2], b[nf*2+1]);
            }
        }
        __syncthreads();
    }

    #pragma unroll
    for (int mf = 0; mf < 4; ++mf) {
        const int r0 = m0 + wm * 64 + mf * 16 + (lane >> 2);
        #pragma unroll
        for (int nf = 0; nf < 4; ++nf) {
            const int c = n0 + wn * 32 + nf * 8 + (lane & 3) * 2;
            if (c < V_) {
                float2 bia = *(const float2*)(bdec + c);
                float2 v0 = make_float2(acc[mf][nf][0] + bia.x, acc[mf][nf][1] + bia.y);
                float2 v1 = make_float2(acc[mf][nf][2] + bia.x, acc[mf][nf][3] + bia.y);
                *(float2*)(C + (size_t)r0 * V_ + c)     = v0;
                *(float2*)(C + (size_t)(r0+8) * V_ + c) = v1;
            }
        }
    }
}

// ===========================================================================
// Final hidden state
// ===========================================================================
__global__ void copy_final(const __nv_bfloat16* __restrict__ h0hh,
                           const __nv_bfloat16* __restrict__ h0ll,
                           const float* __restrict__ h1f,
                           float* __restrict__ out)
{
    int i = blockIdx.x * blockDim.x + threadIdx.x;
    if (i < BH) {
        out[i]      = __bfloat162float(h0hh[i]) + __bfloat162float(h0ll[i]);
        out[BH + i] = h1f[i];
    }
}

extern "C" void kernel_launch(void* const* d_in, const int* in_sizes, int n_in,
                              void* d_out, int out_size)
{
    const float* emb    = (const float*)d_in[0];
    const float* W_in0  = (const float*)d_in[1];
    const float* Wh0    = (const float*)d_in[2];
    const float* b0     = (const float*)d_in[3];
    const float* W_in1  = (const float*)d_in[4];
    const float* Wh1    = (const float*)d_in[5];
    const float* b1     = (const float*)d_in[6];
    const float* Wdec   = (const float*)d_in[7];
    const float* bdec   = (const float*)d_in[8];
    const float* hidden = (const float*)d_in[9];
    const int*   tokens = (const int*)d_in[10];

    float* out    = (float*)d_out;
    float* logits = out;
    float* hfin   = out + (size_t)M_ * V_;

    float *U0 = nullptr, *H1f = nullptr;
    __nv_bfloat16 *h0h = nullptr, *h0l = nullptr;
    __nv_bfloat16 *EH = nullptr, *EL = nullptr, *W03 = nullptr;
    __half *A2f = nullptr, *B1f = nullptr;
    cudaGetSymbolAddress((void**)&U0,  g_U0);
    cudaGetSymbolAddress((void**)&H1f, g_H1f);
    cudaGetSymbolAddress((void**)&A2f, g_A2f);
    cudaGetSymbolAddress((void**)&B1f, g_B1f);
    cudaGetSymbolAddress((void**)&h0h, g_h0h);
    cudaGetSymbolAddress((void**)&h0l, g_h0l);
    cudaGetSymbolAddress((void**)&EH,  g_embH);
    cudaGetSymbolAddress((void**)&EL,  g_embL);
    cudaGetSymbolAddress((void**)&W03, g_W03);

    cudaFuncSetAttribute(rnn_persistent_mma,
                         cudaFuncAttributeMaxDynamicSharedMemorySize, RSM_TOTAL);
    cudaFuncSetAttribute(decoder_mma,
                         cudaFuncAttributeMaxDynamicSharedMemorySize, DEC_SMEM);
    cudaFuncSetAttribute(embed_mma,
                         cudaFuncAttributeMaxDynamicSharedMemorySize, DEC_SMEM);

    // 0) splits (vectorized)
    reset_bar_kernel<<<1, 256>>>();
    convert_emb<<<(int)(((size_t)V_ * E_ / 4 + 255) / 256), 256>>>(emb, EH, EL);
    convert_win0<<<(int)(((size_t)H_ * 256) / 256), 256>>>(W_in0, W03);
    convert_wdec<<<(int)(((size_t)VP * 256) / 256), 256>>>(Wdec, B1f);

    // 1) U0 = emb[tokens] @ W_in0^T + b0  (bf16 3-term, proven)
    embed_mma<<<dim3(H_ / 128, M_ / 128), 256, DEC_SMEM>>>(EH, EL, W03, tokens,
                                                           b0, U0);

    // 2) Persistent tensor-core recurrence (bf16 3-term, parallel epilogue)
    rnn_persistent_mma<<<GRID, NT, RSM_TOTAL>>>(Wh0, W_in1, Wh1, b1, hidden);

    // 3) logits = A2f @ B1f^T + bdec  (fp16 2-term)
    decoder_mma<<<dim3(VP / 128, M_ / 128), 256, DEC_SMEM>>>(A2f, B1f, bdec, logits);

    // 4) final hidden states
    copy_final<<<(BH + 255) / 256, 256>>>(h0h + BH, h0l + BH, H1f, hfin);

    (void)in_sizes; (void)n_in; (void)out_size;
}

// round 15
// speedup vs baseline: 2.0293x; 1.1706x over previous
#include <cuda_runtime.h>
#include <cuda_bf16.h>
#include <cuda_fp16.h>
#include <math.h>
#include <stdint.h>

#define T_ 128
#define B_ 64
#define E_ 1024
#define H_ 1024
#define V_ 10000
#define VP 10112              // V padded to 128 (79*128)
#define M_ (T_*B_)            // 8192
#define BH (B_*H_)
#define K3 3072               // bf16 3-term split (embed + recurrence)
#define KD 1024               // fp16 single-term decoder A

#define GRID 128
#define NT 256

// Scratch (no allocs allowed)
__device__ float g_U0[(size_t)M_*H_];
__device__ float g_H1f[BH];
__device__ unsigned int g_bar[256];
__device__ __nv_bfloat16 g_A3[(size_t)M_*K3];     // recurrence h1 (hi @0, lo @2048)
__device__ __half        g_A2f[(size_t)M_*KD];    // decoder A: Ah fp16
__device__ __half        g_B1f[(size_t)VP*H_];    // decoder B: Bh fp16
__device__ __nv_bfloat16 g_h0h[2][BH], g_h0l[2][BH];
__device__ __nv_bfloat16 g_hid0h[BH], g_hid0l[BH];
__device__ __nv_bfloat16 g_hp1h[BH],  g_hp1l[BH];
__device__ __nv_bfloat16 g_embH[(size_t)V_*E_];
__device__ __nv_bfloat16 g_embL[(size_t)V_*E_];
__device__ __nv_bfloat16 g_W03[(size_t)H_*K3];

// ===========================================================================
// Grid barrier + helpers
// ===========================================================================
__global__ void reset_bar_kernel() {
    if (threadIdx.x < 256) g_bar[threadIdx.x] = 0;
}

__device__ __forceinline__ void gsync(int slot) {
    __syncthreads();
    if (threadIdx.x == 0) {
        __threadfence();
        atomicAdd(&g_bar[slot], 1u);
        while (*((volatile unsigned int*)&g_bar[slot]) < GRID) { }
        __threadfence();
    }
    __syncthreads();
}

__device__ __forceinline__ void split_bf16(float x, __nv_bfloat16& h, __nv_bfloat16& l) {
    h = __float2bfloat16(x);
    l = __float2bfloat16(x - __bfloat162float(h));
}

__device__ __forceinline__ uint32_t smem_u32(const void* p) {
    uint32_t a;
    asm("{ .reg .u64 t; cvta.to.shared.u64 t, %1; cvt.u32.u64 %0, t; }"
        : "=r"(a) : "l"(p));
    return a;
}
__device__ __forceinline__ void cp16(uint32_t dst, const void* src) {
    asm volatile("cp.async.cg.shared.global [%0], [%1], 16;"
                 :: "r"(dst), "l"(src));
}
__device__ __forceinline__ void ldm_x4(uint32_t& r0, uint32_t& r1,
                                       uint32_t& r2, uint32_t& r3, uint32_t addr) {
    asm volatile("ldmatrix.sync.aligned.m8n8.x4.shared.b16 {%0,%1,%2,%3}, [%4];"
                 : "=r"(r0), "=r"(r1), "=r"(r2), "=r"(r3) : "r"(addr));
}
__device__ __forceinline__ void mma16816(float* d,
                                         const uint32_t* a,
                                         uint32_t b0, uint32_t b1) {
    asm volatile("mma.sync.aligned.m16n8k16.row.col.f32.bf16.bf16.f32 "
                 "{%0,%1,%2,%3}, {%4,%5,%6,%7}, {%8,%9}, {%0,%1,%2,%3};"
                 : "+f"(d[0]), "+f"(d[1]), "+f"(d[2]), "+f"(d[3])
                 : "r"(a[0]), "r"(a[1]), "r"(a[2]), "r"(a[3]), "r"(b0), "r"(b1));
}
__device__ __forceinline__ void mma16816d(float& d0, float& d1, float& d2, float& d3,
                                          uint32_t a0, uint32_t a1, uint32_t a2, uint32_t a3,
                                          uint32_t b0, uint32_t b1) {
    asm volatile("mma.sync.aligned.m16n8k16.row.col.f32.bf16.bf16.f32 "
                 "{%0,%1,%2,%3}, {%4,%5,%6,%7}, {%8,%9}, {%0,%1,%2,%3};"
                 : "+f"(d0), "+f"(d1), "+f"(d2), "+f"(d3)
                 : "r"(a0), "r"(a1), "r"(a2), "r"(a3), "r"(b0), "r"(b1));
}
__device__ __forceinline__ void mma16816h(float& d0, float& d1, float& d2, float& d3,
                                          uint32_t a0, uint32_t a1, uint32_t a2, uint32_t a3,
                                          uint32_t b0, uint32_t b1) {
    asm volatile("mma.sync.aligned.m16n8k16.row.col.f32.f16.f16.f32 "
                 "{%0,%1,%2,%3}, {%4,%5,%6,%7}, {%8,%9}, {%0,%1,%2,%3};"
                 : "+f"(d0), "+f"(d1), "+f"(d2), "+f"(d3)
                 : "r"(a0), "r"(a1), "r"(a2), "r"(a3), "r"(b0), "r"(b1));
}
__device__ __forceinline__ __nv_bfloat162 pack2(__nv_bfloat16 a, __nv_bfloat16 b) {
    __nv_bfloat162 p; p.x = a; p.y = b; return p;
}

// ===========================================================================
// Conversion kernels
// ===========================================================================
__global__ __launch_bounds__(256)
void convert_emb(const float* __restrict__ Wemb,
                 __nv_bfloat16* __restrict__ eh, __nv_bfloat16* __restrict__ el)
{
    size_t q = (size_t)blockIdx.x * 256 + threadIdx.x;
    if (q < (size_t)V_ * E_ / 4) {
        float4 v = *(const float4*)(Wemb + q * 4);
        __nv_bfloat16 h0,l0,h1,l1,h2,l2,h3,l3;
        split_bf16(v.x,h0,l0); split_bf16(v.y,h1,l1);
        split_bf16(v.z,h2,l2); split_bf16(v.w,h3,l3);
        *(__nv_bfloat162*)(eh + q*4)     = pack2(h0,h1);
        *(__nv_bfloat162*)(eh + q*4 + 2) = pack2(h2,h3);
        *(__nv_bfloat162*)(el + q*4)     = pack2(l0,l1);
        *(__nv_bfloat162*)(el + q*4 + 2) = pack2(l2,l3);
    }
}

__global__ __launch_bounds__(256)
void convert_win0(const float* __restrict__ W, __nv_bfloat16* __restrict__ W3)
{
    size_t q = (size_t)blockIdx.x * 256 + threadIdx.x;
    int n = (int)(q >> 8), kq = (int)(q & 255) * 4;
    float4 v = *(const float4*)(W + (size_t)n * E_ + kq);
    __nv_bfloat16 h0,l0,h1,l1,h2,l2,h3,l3;
    split_bf16(v.x,h0,l0); split_bf16(v.y,h1,l1);
    split_bf16(v.z,h2,l2); split_bf16(v.w,h3,l3);
    __nv_bfloat16* base = W3 + (size_t)n * K3 + kq;
    *(__nv_bfloat162*)(base)          = pack2(h0,h1);
    *(__nv_bfloat162*)(base + 2)      = pack2(h2,h3);
    *(__nv_bfloat162*)(base + 1024)   = pack2(l0,l1);
    *(__nv_bfloat162*)(base + 1026)   = pack2(l2,l3);
    *(__nv_bfloat162*)(base + 2048)   = pack2(h0,h1);
    *(__nv_bfloat162*)(base + 2050)   = pack2(h2,h3);
}

// Wdec -> single fp16 copy (decoder B)
__global__ __launch_bounds__(256)
void convert_wdec(const float* __restrict__ W, __half* __restrict__ Bf)
{
    size_t q = (size_t)blockIdx.x * 256 + threadIdx.x;
    int n = (int)(q >> 8), kq = (int)(q & 255) * 4;
    float4 v = (n < V_) ? *(const float4*)(W + (size_t)n * H_ + kq)
                        : make_float4(0.f,0.f,0.f,0.f);
    __half2 p0 = __floats2half2_rn(v.x, v.y);
    __half2 p1 = __floats2half2_rn(v.z, v.w);
    *(__half2*)(Bf + (size_t)n * H_ + kq)     = p0;
    *(__half2*)(Bf + (size_t)n * H_ + kq + 2) = p1;
}

// ===========================================================================
// Embedding projection via mma.sync (proven: 128x128, occ=2, 2-stage, bf16 K3)
// ===========================================================================
#define DEC_SMEM 65536

__global__ __launch_bounds__(256, 2)
void embed_mma(const __nv_bfloat16* __restrict__ EH,
               const __nv_bfloat16* __restrict__ EL,
               const __nv_bfloat16* __restrict__ W3,
               const int* __restrict__ tokens,
               const float* __restrict__ b0, float* __restrict__ C)
{
    extern __shared__ char dsm[];
    const uint32_t sb = smem_u32(dsm);

    const int tid  = threadIdx.x;
    const int lane = tid & 31, wid = tid >> 5;
    const int wm = wid >> 2, wn = wid & 3;
    const int m0 = blockIdx.y * 128, n0 = blockIdx.x * 128;

    float acc[4][4][4];
    #pragma unroll
    for (int i = 0; i < 4; i++)
        #pragma unroll
        for (int j = 0; j < 4; j++)
            #pragma unroll
            for (int q = 0; q < 4; q++) acc[i][j][q] = 0.f;

    int lrow[4], lcb[4], tokr[4];
    #pragma unroll
    for (int i = 0; i < 4; i++) {
        int idx = tid + i * 256;
        lrow[i] = idx >> 3;
        lcb[i]  = (idx & 7) * 16;
        tokr[i] = tokens[m0 + lrow[i]];
    }

    #define LOAD_TILE_E(ch, buf) do {                                          \
        const uint32_t Ab_ = sb + (buf) * 32768;                               \
        const uint32_t Bb_ = Ab_ + 16384;                                      \
        const __nv_bfloat16* Aarr_ = ((ch) < 32) ? EH : EL;                    \
        const int kc_ = (((ch) < 16) ? (ch) : (((ch) < 32) ? (ch) - 16 : (ch) - 32)) * 64; \
        _Pragma("unroll")                                                      \
        for (int i_ = 0; i_ < 4; i_++) {                                       \
            int r_ = lrow[i_], cb_ = lcb[i_];                                  \
            uint32_t sw_ = (uint32_t)(cb_ ^ ((r_ & 7) << 4));                  \
            cp16(Ab_ + r_ * 128 + sw_,                                         \
                 (const char*)Aarr_ + (((size_t)tokr[i_] * E_ + kc_) * 2 + cb_)); \
            cp16(Bb_ + r_ * 128 + sw_,                                         \
                 (const char*)W3 + (((size_t)(n0 + r_) * K3 + (ch) * 64) * 2 + cb_)); \
        }                                                                      \
        asm volatile("cp.async.commit_group;");                                \
    } while (0)

    LOAD_TILE_E(0, 0);

    const int KCH = K3 / 64;   // 48
    for (int ch = 0; ch < KCH; ++ch) {
        if (ch + 1 < KCH) {
            LOAD_TILE_E(ch + 1, (ch + 1) & 1);
            asm volatile("cp.async.wait_group 1;");
        } else {
            asm volatile("cp.async.wait_group 0;");
        }
        __syncthreads();

        const uint32_t Ab = sb + (ch & 1) * 32768;
        const uint32_t Bb = Ab + 16384;

        #pragma unroll
        for (int ks = 0; ks < 4; ++ks) {
            const int kb2 = ks * 32;
            uint32_t b[8];
            #pragma unroll
            for (int h = 0; h < 2; ++h) {
                int nrow = wn * 32 + h * 16 + ((lane >> 4) & 1) * 8 + (lane & 7);
                int kcol = kb2 + ((lane >> 3) & 1) * 16;
                uint32_t ad = Bb + nrow * 128 + (kcol ^ ((nrow & 7) << 4));
                ldm_x4(b[4*h+0], b[4*h+1], b[4*h+2], b[4*h+3], ad);
            }
            #pragma unroll
            for (int mf = 0; mf < 4; ++mf) {
                int arow = wm * 64 + mf * 16 + (lane & 15);
                int acol = kb2 + ((lane >> 4) & 1) * 16;
                uint32_t ad = Ab + arow * 128 + (acol ^ ((arow & 7) << 4));
                uint32_t a0, a1, a2r, a3r;
                ldm_x4(a0, a1, a2r, a3r, ad);
                #pragma unroll
                for (int nf = 0; nf < 4; ++nf)
                    mma16816d(acc[mf][nf][0], acc[mf][nf][1],
                              acc[mf][nf][2], acc[mf][nf][3],
                              a0, a1, a2r, a3r, b[nf*2], b[nf*2+1]);
            }
        }
        __syncthreads();
    }

    #pragma unroll
    for (int mf = 0; mf < 4; ++mf) {
        const int r0 = m0 + wm * 64 + mf * 16 + (lane >> 2);
        #pragma unroll
        for (int nf = 0; nf < 4; ++nf) {
            const int c = n0 + wn * 32 + nf * 8 + (lane & 3) * 2;
            float2 bia = *(const float2*)(b0 + c);
            float2 v0 = make_float2(acc[mf][nf][0] + bia.x, acc[mf][nf][1] + bia.y);
            float2 v1 = make_float2(acc[mf][nf][2] + bia.x, acc[mf][nf][3] + bia.y);
            *(float2*)(C + (size_t)r0 * H_ + c)     = v0;
            *(float2*)(C + (size_t)(r0+8) * H_ + c) = v1;
        }
    }
}

// ===========================================================================
// Persistent tensor-core recurrence (round-13 proven + fp16 Ah store for decoder)
// ===========================================================================
#define RSM_H   98304
#define RSM_RED (RSM_H + 65536)
#define RSM_TOTAL (RSM_RED + 128*12*4)

#define LOADCH(ch, buf) do {                                                   \
    const int seg_ = tid & 7;                                                  \
    const int r0_  = tid >> 3;                                                 \
    _Pragma("unroll")                                                          \
    for (int i_ = 0; i_ < 8; i_++) {                                           \
        const int arr_ = i_ >> 1;                                              \
        const int row_ = r0_ + (i_ & 1) * 32;                                  \
        const char* src_ =                                                     \
          (arr_ == 0) ? (const char*)h0h + ((size_t)row_*H_  + (size_t)(ch)*64 + seg_*8)*2 : \
          (arr_ == 1) ? (const char*)h0l + ((size_t)row_*H_  + (size_t)(ch)*64 + seg_*8)*2 : \
          (arr_ == 2) ? (const char*)h1h + ((size_t)row_*h1s + (size_t)(ch)*64 + seg_*8)*2 : \
                        (const char*)h1l + ((size_t)row_*h1s + (size_t)(ch)*64 + seg_*8)*2;  \
        cp16(sb + RSM_H + (buf)*32768 + arr_*8192 + row_*128                   \
                 + (uint32_t)((seg_*16) ^ ((row_ & 7) << 4)), src_);           \
    }                                                                          \
    asm volatile("cp.async.commit_group;");                                    \
} while (0)

__global__ __launch_bounds__(256, 1)
void rnn_persistent_mma(const float* __restrict__ Wh0,
                        const float* __restrict__ Win1,
                        const float* __restrict__ Wh1,
                        const float* __restrict__ b1v,
                        const float* __restrict__ hidden)
{
    extern __shared__ char rsm[];
    const uint32_t sb = smem_u32(rsm);
    const int tid = threadIdx.x, lane = tid & 31, wid = tid >> 5;
    const int wg = wid >> 2, mw = wid & 3;
    const int n0 = blockIdx.x * 8;

    {
        const float* Wm[3] = {Wh0, Win1, Wh1};
        #pragma unroll 1
        for (int m = 0; m < 3; ++m) {
            const float* src = Wm[m] + (size_t)n0 * H_;
            for (int idx = tid; idx < 8 * H_; idx += 256) {
                int r = idx >> 10, k = idx & 1023;
                float v = src[(size_t)r * H_ + k];
                __nv_bfloat16 hh, ll; split_bf16(v, hh, ll);
                uint32_t off = (uint32_t)(2 * k) ^ ((r & 7) << 4);
                *(__nv_bfloat16*)(rsm + m*32768 + r*2048 + off)     = hh;
                *(__nv_bfloat16*)(rsm + m*32768 + (r+8)*2048 + off) = ll;
            }
        }
    }
    for (size_t i = (size_t)blockIdx.x * 256 + tid; i < 2 * (size_t)BH;
         i += (size_t)GRID * 256) {
        __nv_bfloat16 hh, ll; split_bf16(hidden[i], hh, ll);
        if (i < (size_t)BH) { g_hid0h[i] = hh; g_hid0l[i] = ll; }
        else                { g_hp1h[i - BH] = hh; g_hp1l[i - BH] = ll; }
    }
    gsync(0);

    const float b1c0 = b1v[n0 + (lane & 3) * 2];
    const float b1c1 = b1v[n0 + (lane & 3) * 2 + 1];

    for (int tt = -1; tt < T_; ++tt) {
        const __nv_bfloat16 *h0h, *h0l, *h1h, *h1l;
        size_t h1s;
        if (tt < 0) { h0h = g_hid0h; h0l = g_hid0l; }
        else        { h0h = g_h0h[tt & 1]; h0l = g_h0l[tt & 1]; }
        if (tt <= 0) { h1h = g_hp1h; h1l = g_hp1l; h1s = H_; }
        else { h1h = g_A3 + (size_t)(tt - 1) * B_ * K3; h1l = h1h + 2048; h1s = K3; }

        float P0[4] = {0.f,0.f,0.f,0.f}, P1[4] = {0.f,0.f,0.f,0.f};

        LOADCH(0, 0);
        for (int ch = 0; ch < 16; ++ch) {
            if (ch < 15) { LOADCH(ch + 1, (ch + 1) & 1);
                           asm volatile("cp.async.wait_group 1;"); }
            else         { asm volatile("cp.async.wait_group 0;"); }
            __syncthreads();
            const uint32_t hb = sb + RSM_H + (ch & 1) * 32768;
            #pragma unroll
            for (int k16 = 0; k16 < 2; ++k16) {
                const int kb2 = wg * 64 + k16 * 32;
                const int kbw = ch * 128 + kb2;
                const int arow = mw * 16 + (lane & 15);
                const uint32_t aoff = (uint32_t)(kb2 + ((lane >> 4) & 1) * 16)
                                      ^ ((arow & 7) << 4);
                const int brow = ((lane >> 4) & 1) * 8 + (lane & 7);
                const uint32_t boff = (uint32_t)(kbw + ((lane >> 3) & 1) * 16)
                                      ^ ((brow & 7) << 4);

                uint32_t aH0[4], aL0[4];
                ldm_x4(aH0[0], aH0[1], aH0[2], aH0[3], hb + arow*128 + aoff);
                ldm_x4(aL0[0], aL0[1], aL0[2], aL0[3], hb + 8192 + arow*128 + aoff);
                uint32_t b0f[4];
                ldm_x4(b0f[0], b0f[1], b0f[2], b0f[3], sb + brow*2048 + boff);

                mma16816(P0, aH0, b0f[0], b0f[1]);
                mma16816(P0, aH0, b0f[2], b0f[3]);
                mma16816(P0, aL0, b0f[0], b0f[1]);

                if (tt >= 0) {
                    uint32_t aH1[4], aL1[4];
                    ldm_x4(aH1[0], aH1[1], aH1[2], aH1[3], hb + 16384 + arow*128 + aoff);
                    ldm_x4(aL1[0], aL1[1], aL1[2], aL1[3], hb + 24576 + arow*128 + aoff);
                    uint32_t bif[4], bhf[4];
                    ldm_x4(bif[0], bif[1], bif[2], bif[3], sb + 32768 + brow*2048 + boff);
                    ldm_x4(bhf[0], bhf[1], bhf[2], bhf[3], sb + 65536 + brow*2048 + boff);

                    mma16816(P1, aH0, bif[0], bif[1]);
                    mma16816(P1, aH0, bif[2], bif[3]);
                    mma16816(P1, aL0, bif[0], bif[1]);
                    mma16816(P1, aH1, bhf[0], bhf[1]);
                    mma16816(P1, aH1, bhf[2], bhf[3]);
                    mma16816(P1, aL1, bhf[0], bhf[1]);
                }
            }
            __syncthreads();
        }

        // Cross-wg partial exchange: wg1 -> redA (P0+P1), wg0 -> redB (P0)
        float* redA = (float*)(rsm + RSM_RED);           // 128 x 8
        float* redB = redA + 128 * 8;                    // 128 x 4
        const int tl = mw * 32 + lane;
        if (wg == 1) {
            float* r = redA + tl * 8;
            r[0]=P0[0]; r[1]=P0[1]; r[2]=P0[2]; r[3]=P0[3];
            r[4]=P1[0]; r[5]=P1[1]; r[6]=P1[2]; r[7]=P1[3];
        } else {
            float* r = redB + tl * 4;
            r[0]=P0[0]; r[1]=P0[1]; r[2]=P0[2]; r[3]=P0[3];
        }
        __syncthreads();

        const int r0 = mw * 16 + (lane >> 2);
        const int c0 = n0 + (lane & 3) * 2;
        const int rws[4] = {r0, r0, r0 + 8, r0 + 8};
        const int cls[4] = {c0, c0 + 1, c0, c0 + 1};

        if (wg == 0) {
            // L1 epilogue: h1(tt) -> A3 (bf16 hi/lo) + A2f (fp16 Ah)
            if (tt >= 0) {
                const float* r = redA + tl * 8;
                const float bb[4] = {b1c0, b1c1, b1c0, b1c1};
                #pragma unroll
                for (int j = 0; j < 4; j++) {
                    float v = tanhf((P1[j] + r[j + 4]) + bb[j]);
                    __nv_bfloat16 hh, ll; split_bf16(v, hh, ll);
                    size_t row = (size_t)(tt * 64 + rws[j]);
                    size_t ab = row * K3 + cls[j];
                    g_A3[ab] = hh; g_A3[ab + 2048] = ll;
                    g_A2f[row * KD + cls[j]] = __float2half_rn(v);
                    if (tt == T_ - 1) g_H1f[rws[j] * H_ + cls[j]] = v;
                }
            }
        } else {
            // L0 epilogue: h0(tt+1) split writes
            if (tt < T_ - 1) {
                const float* r = redA + tl * 8;
                const float* s = redB + tl * 4;
                __nv_bfloat16* dh = g_h0h[(tt + 1) & 1];
                __nv_bfloat16* dl = g_h0l[(tt + 1) & 1];
                #pragma unroll
                for (int j = 0; j < 4; j++) {
                    float u = g_U0[(size_t)(tt + 1) * BH + rws[j] * H_ + cls[j]];
                    float v = tanhf((s[j] + r[j]) + u);
                    __nv_bfloat16 hh, ll; split_bf16(v, hh, ll);
                    dh[rws[j] * H_ + cls[j]] = hh;
                    dl[rws[j] * H_ + cls[j]] = ll;
                }
            }
        }
        gsync(tt + 2);
    }
}

// ===========================================================================
// Decoder GEMM: single-term fp16 (K=1024). Structure identical to proven
// 128x128/occ2/2-stage; KCH=16.
// ===========================================================================
__global__ __launch_bounds__(256, 2)
void decoder_mma(const __half* __restrict__ A2,
                 const __half* __restrict__ B1,
                 const float* __restrict__ bdec, float* __restrict__ C)
{
    extern __shared__ char dsm[];
    const uint32_t sb = smem_u32(dsm);

    const int tid  = threadIdx.x;
    const int lane = tid & 31, wid = tid >> 5;
    const int wm = wid >> 2, wn = wid & 3;
    const int m0 = blockIdx.y * 128, n0 = blockIdx.x * 128;

    float acc[4][4][4];
    #pragma unroll
    for (int i = 0; i < 4; i++)
        #pragma unroll
        for (int j = 0; j < 4; j++)
            #pragma unroll
            for (int q = 0; q < 4; q++) acc[i][j][q] = 0.f;

    int lrow[4], lcb[4];
    #pragma unroll
    for (int i = 0; i < 4; i++) {
        int idx = tid + i * 256;
        lrow[i] = idx >> 3;
        lcb[i]  = (idx & 7) * 16;
    }

    #define LOAD_TILE(ch, buf) do {                                            \
        const uint32_t Ab_ = sb + (buf) * 32768;                               \
        const uint32_t Bb_ = Ab_ + 16384;                                      \
        _Pragma("unroll")                                                      \
        for (int i_ = 0; i_ < 4; i_++) {                                       \
            int r_ = lrow[i_], cb_ = lcb[i_];                                  \
            uint32_t sw_ = (uint32_t)(cb_ ^ ((r_ & 7) << 4));                  \
            cp16(Ab_ + r_ * 128 + sw_,                                         \
                 (const char*)A2 + (((size_t)(m0 + r_) * KD + (ch) * 64) * 2 + cb_)); \
            cp16(Bb_ + r_ * 128 + sw_,                                         \
                 (const char*)B1 + (((size_t)(n0 + r_) * H_ + (ch) * 64) * 2 + cb_)); \
        }                                                                      \
        asm volatile("cp.async.commit_group;");                                \
    } while (0)

    LOAD_TILE(0, 0);

    const int KCH = KD / 64;   // 16
    for (int ch = 0; ch < KCH; ++ch) {
        if (ch + 1 < KCH) {
            LOAD_TILE(ch + 1, (ch + 1) & 1);
            asm volatile("cp.async.wait_group 1;");
        } else {
            asm volatile("cp.async.wait_group 0;");
        }
        __syncthreads();

        const uint32_t Ab = sb + (ch & 1) * 32768;
        const uint32_t Bb = Ab + 16384;

        #pragma unroll
        for (int ks = 0; ks < 4; ++ks) {
            const int kb2 = ks * 32;
            uint32_t b[8];
            #pragma unroll
            for (int h = 0; h < 2; ++h) {
                int nrow = wn * 32 + h * 16 + ((lane >> 4) & 1) * 8 + (lane & 7);
                int kcol = kb2 + ((lane >> 3) & 1) * 16;
                uint32_t ad = Bb + nrow * 128 + (kcol ^ ((nrow & 7) << 4));
                ldm_x4(b[4*h+0], b[4*h+1], b[4*h+2], b[4*h+3], ad);
            }
            #pragma unroll
            for (int mf = 0; mf < 4; ++mf) {
                int arow = wm * 64 + mf * 16 + (lane & 15);
                int acol = kb2 + ((lane >> 4) & 1) * 16;
                uint32_t ad = Ab + arow * 128 + (acol ^ ((arow & 7) << 4));
                uint32_t a0, a1, a2r, a3r;
                ldm_x4(a0, a1, a2r, a3r, ad);
                #pragma unroll
                for (int nf = 0; nf < 4; ++nf)
                    mma16816h(acc[mf][nf][0], acc[mf][nf][1],
                              acc[mf][nf][2], acc[mf][nf][3],
                              a0, a1, a2r, a3r, b[nf*2], b[nf*2+1]);
            }
        }
        __syncthreads();
    }

    #pragma unroll
    for (int mf = 0; mf < 4; ++mf) {
        const int r0 = m0 + wm * 64 + mf * 16 + (lane >> 2);
        #pragma unroll
        for (int nf = 0; nf < 4; ++nf) {
            const int c = n0 + wn * 32 + nf * 8 + (lane & 3) * 2;
            if (c < V_) {
                float2 bia = *(const float2*)(bdec + c);
                float2 v0 = make_float2(acc[mf][nf][0] + bia.x, acc[mf][nf][1] + bia.y);
                float2 v1 = make_float2(acc[mf][nf][2] + bia.x, acc[mf][nf][3] + bia.y);
                *(float2*)(C + (size_t)r0 * V_ + c)     = v0;
                *(float2*)(C + (size_t)(r0+8) * V_ + c) = v1;
            }
        }
    }
}

// ===========================================================================
// Final hidden state
// ===========================================================================
__global__ void copy_final(const __nv_bfloat16* __restrict__ h0hh,
                           const __nv_bfloat16* __restrict__ h0ll,
                           const float* __restrict__ h1f,
                           float* __restrict__ out)
{
    int i = blockIdx.x * blockDim.x + threadIdx.x;
    if (i < BH) {
        out[i]      = __bfloat162float(h0hh[i]) + __bfloat162float(h0ll[i]);
        out[BH + i] = h1f[i];
    }
}

extern "C" void kernel_launch(void* const* d_in, const int* in_sizes, int n_in,
                              void* d_out, int out_size)
{
    const float* emb    = (const float*)d_in[0];
    const float* W_in0  = (const float*)d_in[1];
    const float* Wh0    = (const float*)d_in[2];
    const float* b0     = (const float*)d_in[3];
    const float* W_in1  = (const float*)d_in[4];
    const float* Wh1    = (const float*)d_in[5];
    const float* b1     = (const float*)d_in[6];
    const float* Wdec   = (const float*)d_in[7];
    const float* bdec   = (const float*)d_in[8];
    const float* hidden = (const float*)d_in[9];
    const int*   tokens = (const int*)d_in[10];

    float* out    = (float*)d_out;
    float* logits = out;
    float* hfin   = out + (size_t)M_ * V_;

    float *U0 = nullptr, *H1f = nullptr;
    __nv_bfloat16 *h0h = nullptr, *h0l = nullptr;
    __nv_bfloat16 *EH = nullptr, *EL = nullptr, *W03 = nullptr;
    __half *A2f = nullptr, *B1f = nullptr;
    cudaGetSymbolAddress((void**)&U0,  g_U0);
    cudaGetSymbolAddress((void**)&H1f, g_H1f);
    cudaGetSymbolAddress((void**)&A2f, g_A2f);
    cudaGetSymbolAddress((void**)&B1f, g_B1f);
    cudaGetSymbolAddress((void**)&h0h, g_h0h);
    cudaGetSymbolAddress((void**)&h0l, g_h0l);
    cudaGetSymbolAddress((void**)&EH,  g_embH);
    cudaGetSymbolAddress((void**)&EL,  g_embL);
    cudaGetSymbolAddress((void**)&W03, g_W03);

    cudaFuncSetAttribute(rnn_persistent_mma,
                         cudaFuncAttributeMaxDynamicSharedMemorySize, RSM_TOTAL);
    cudaFuncSetAttribute(decoder_mma,
                         cudaFuncAttributeMaxDynamicSharedMemorySize, DEC_SMEM);
    cudaFuncSetAttribute(embed_mma,
                         cudaFuncAttributeMaxDynamicSharedMemorySize, DEC_SMEM);

    // 0) splits (vectorized)
    reset_bar_kernel<<<1, 256>>>();
    convert_emb<<<(int)(((size_t)V_ * E_ / 4 + 255) / 256), 256>>>(emb, EH, EL);
    convert_win0<<<(int)(((size_t)H_ * 256) / 256), 256>>>(W_in0, W03);
    convert_wdec<<<(int)(((size_t)VP * 256) / 256), 256>>>(Wdec, B1f);

    // 1) U0 = emb[tokens] @ W_in0^T + b0  (bf16 3-term, proven)
    embed_mma<<<dim3(H_ / 128, M_ / 128), 256, DEC_SMEM>>>(EH, EL, W03, tokens,
                                                           b0, U0);

    // 2) Persistent tensor-core recurrence (bf16 3-term, parallel epilogue)
    rnn_persistent_mma<<<GRID, NT, RSM_TOTAL>>>(Wh0, W_in1, Wh1, b1, hidden);

    // 3) logits = A2f @ B1f^T + bdec  (single-term fp16, K=1024)
    decoder_mma<<<dim3(VP / 128, M_ / 128), 256, DEC_SMEM>>>(A2f, B1f, bdec, logits);

    // 4) final hidden states
    copy_final<<<(BH + 255) / 256, 256>>>(h0h + BH, h0l + BH, H1f, hfin);

    (void)in_sizes; (void)n_in; (void)out_size;
}

// round 16
// speedup vs baseline: 2.0818x; 1.0259x over previous
#include <cuda_runtime.h>
#include <cuda_bf16.h>
#include <cuda_fp16.h>
#include <math.h>
#include <stdint.h>

#define T_ 128
#define B_ 64
#define E_ 1024
#define H_ 1024
#define V_ 10000
#define VP 10112              // V padded to 128 (79*128)
#define M_ (T_*B_)            // 8192
#define BH (B_*H_)
#define K3 3072               // bf16 3-term split (recurrence)
#define KE 2048               // fp16 2-term embed A: [Eh|El]
#define KD 1024               // fp16 single-term decoder A

#define GRID 128
#define NT 256

// Scratch (no allocs allowed)
__device__ float g_U0[(size_t)M_*H_];
__device__ float g_H1f[BH];
__device__ unsigned int g_bar[256];
__device__ __nv_bfloat16 g_A3[(size_t)M_*K3];     // recurrence h1 (hi @0, lo @2048)
__device__ __half        g_A2f[(size_t)M_*KD];    // decoder A: Ah fp16
__device__ __half        g_B1f[(size_t)VP*H_];    // decoder B: Bh fp16
__device__ __nv_bfloat16 g_h0h[2][BH], g_h0l[2][BH];
__device__ __nv_bfloat16 g_hid0h[BH], g_hid0l[BH];
__device__ __nv_bfloat16 g_hp1h[BH],  g_hp1l[BH];
__device__ __half        g_embH[(size_t)V_*E_];   // emb hi fp16
__device__ __half        g_embL[(size_t)V_*E_];   // emb lo fp16
__device__ __half        g_W01f[(size_t)H_*E_];   // W_in0 single fp16

// ===========================================================================
// Grid barrier + helpers
// ===========================================================================
__global__ void reset_bar_kernel() {
    if (threadIdx.x < 256) g_bar[threadIdx.x] = 0;
}

__device__ __forceinline__ void gsync(int slot) {
    __syncthreads();
    if (threadIdx.x == 0) {
        __threadfence();
        atomicAdd(&g_bar[slot], 1u);
        while (*((volatile unsigned int*)&g_bar[slot]) < GRID) { }
        __threadfence();
    }
    __syncthreads();
}

__device__ __forceinline__ void split_bf16(float x, __nv_bfloat16& h, __nv_bfloat16& l) {
    h = __float2bfloat16(x);
    l = __float2bfloat16(x - __bfloat162float(h));
}

__device__ __forceinline__ uint32_t smem_u32(const void* p) {
    uint32_t a;
    asm("{ .reg .u64 t; cvta.to.shared.u64 t, %1; cvt.u32.u64 %0, t; }"
        : "=r"(a) : "l"(p));
    return a;
}
__device__ __forceinline__ void cp16(uint32_t dst, const void* src) {
    asm volatile("cp.async.cg.shared.global [%0], [%1], 16;"
                 :: "r"(dst), "l"(src));
}
__device__ __forceinline__ void ldm_x4(uint32_t& r0, uint32_t& r1,
                                       uint32_t& r2, uint32_t& r3, uint32_t addr) {
    asm volatile("ldmatrix.sync.aligned.m8n8.x4.shared.b16 {%0,%1,%2,%3}, [%4];"
                 : "=r"(r0), "=r"(r1), "=r"(r2), "=r"(r3) : "r"(addr));
}
__device__ __forceinline__ void mma16816(float* d,
                                         const uint32_t* a,
                                         uint32_t b0, uint32_t b1) {
    asm volatile("mma.sync.aligned.m16n8k16.row.col.f32.bf16.bf16.f32 "
                 "{%0,%1,%2,%3}, {%4,%5,%6,%7}, {%8,%9}, {%0,%1,%2,%3};"
                 : "+f"(d[0]), "+f"(d[1]), "+f"(d[2]), "+f"(d[3])
                 : "r"(a[0]), "r"(a[1]), "r"(a[2]), "r"(a[3]), "r"(b0), "r"(b1));
}
__device__ __forceinline__ void mma16816h(float& d0, float& d1, float& d2, float& d3,
                                          uint32_t a0, uint32_t a1, uint32_t a2, uint32_t a3,
                                          uint32_t b0, uint32_t b1) {
    asm volatile("mma.sync.aligned.m16n8k16.row.col.f32.f16.f16.f32 "
                 "{%0,%1,%2,%3}, {%4,%5,%6,%7}, {%8,%9}, {%0,%1,%2,%3};"
                 : "+f"(d0), "+f"(d1), "+f"(d2), "+f"(d3)
                 : "r"(a0), "r"(a1), "r"(a2), "r"(a3), "r"(b0), "r"(b1));
}
__device__ __forceinline__ __nv_bfloat162 pack2(__nv_bfloat16 a, __nv_bfloat16 b) {
    __nv_bfloat162 p; p.x = a; p.y = b; return p;
}
__device__ __forceinline__ __half2 packh2(__half a, __half b) {
    __half2 p; p.x = a; p.y = b; return p;
}

// ===========================================================================
// Conversion kernels
// ===========================================================================
// emb -> fp16 hi/lo split
__global__ __launch_bounds__(256)
void convert_emb(const float* __restrict__ Wemb,
                 __half* __restrict__ eh, __half* __restrict__ el)
{
    size_t q = (size_t)blockIdx.x * 256 + threadIdx.x;
    if (q < (size_t)V_ * E_ / 4) {
        float4 v = *(const float4*)(Wemb + q * 4);
        __half h0 = __float2half_rn(v.x), l0 = __float2half_rn(v.x - __half2float(h0));
        __half h1 = __float2half_rn(v.y), l1 = __float2half_rn(v.y - __half2float(h1));
        __half h2 = __float2half_rn(v.z), l2 = __float2half_rn(v.z - __half2float(h2));
        __half h3 = __float2half_rn(v.w), l3 = __float2half_rn(v.w - __half2float(h3));
        *(__half2*)(eh + q*4)     = packh2(h0,h1);
        *(__half2*)(eh + q*4 + 2) = packh2(h2,h3);
        *(__half2*)(el + q*4)     = packh2(l0,l1);
        *(__half2*)(el + q*4 + 2) = packh2(l2,l3);
    }
}

// W_in0 -> single fp16 copy
__global__ __launch_bounds__(256)
void convert_win0(const float* __restrict__ W, __half* __restrict__ Wf)
{
    size_t q = (size_t)blockIdx.x * 256 + threadIdx.x;   // over H_*256 quads
    int n = (int)(q >> 8), kq = (int)(q & 255) * 4;
    float4 v = *(const float4*)(W + (size_t)n * E_ + kq);
    *(__half2*)(Wf + (size_t)n * E_ + kq)     = __floats2half2_rn(v.x, v.y);
    *(__half2*)(Wf + (size_t)n * E_ + kq + 2) = __floats2half2_rn(v.z, v.w);
}

// Wdec -> single fp16 copy (decoder B)
__global__ __launch_bounds__(256)
void convert_wdec(const float* __restrict__ W, __half* __restrict__ Bf)
{
    size_t q = (size_t)blockIdx.x * 256 + threadIdx.x;
    int n = (int)(q >> 8), kq = (int)(q & 255) * 4;
    float4 v = (n < V_) ? *(const float4*)(W + (size_t)n * H_ + kq)
                        : make_float4(0.f,0.f,0.f,0.f);
    *(__half2*)(Bf + (size_t)n * H_ + kq)     = __floats2half2_rn(v.x, v.y);
    *(__half2*)(Bf + (size_t)n * H_ + kq + 2) = __floats2half2_rn(v.z, v.w);
}

// ===========================================================================
// Embedding projection: fp16 2-term. A=[Eh|El] gathered (KE=2048), B=W single
// fp16 (K=1024, chunk ch&15). Proven 128x128/occ2/2-stage structure.
// ===========================================================================
#define DEC_SMEM 65536

__global__ __launch_bounds__(256, 2)
void embed_mma(const __half* __restrict__ EH,
               const __half* __restrict__ EL,
               const __half* __restrict__ W1,
               const int* __restrict__ tokens,
               const float* __restrict__ b0, float* __restrict__ C)
{
    extern __shared__ char dsm[];
    const uint32_t sb = smem_u32(dsm);

    const int tid  = threadIdx.x;
    const int lane = tid & 31, wid = tid >> 5;
    const int wm = wid >> 2, wn = wid & 3;
    const int m0 = blockIdx.y * 128, n0 = blockIdx.x * 128;

    float acc[4][4][4];
    #pragma unroll
    for (int i = 0; i < 4; i++)
        #pragma unroll
        for (int j = 0; j < 4; j++)
            #pragma unroll
            for (int q = 0; q < 4; q++) acc[i][j][q] = 0.f;

    int lrow[4], lcb[4], tokr[4];
    #pragma unroll
    for (int i = 0; i < 4; i++) {
        int idx = tid + i * 256;
        lrow[i] = idx >> 3;
        lcb[i]  = (idx & 7) * 16;
        tokr[i] = tokens[m0 + lrow[i]];
    }

    #define LOAD_TILE_E(ch, buf) do {                                          \
        const uint32_t Ab_ = sb + (buf) * 32768;                               \
        const uint32_t Bb_ = Ab_ + 16384;                                      \
        const __half* Aarr_ = ((ch) < 16) ? EH : EL;                           \
        const int kc_ = ((ch) & 15) * 64;                                      \
        _Pragma("unroll")                                                      \
        for (int i_ = 0; i_ < 4; i_++) {                                       \
            int r_ = lrow[i_], cb_ = lcb[i_];                                  \
            uint32_t sw_ = (uint32_t)(cb_ ^ ((r_ & 7) << 4));                  \
            cp16(Ab_ + r_ * 128 + sw_,                                         \
                 (const char*)Aarr_ + (((size_t)tokr[i_] * E_ + kc_) * 2 + cb_)); \
            cp16(Bb_ + r_ * 128 + sw_,                                         \
                 (const char*)W1 + (((size_t)(n0 + r_) * E_ + kc_) * 2 + cb_)); \
        }                                                                      \
        asm volatile("cp.async.commit_group;");                                \
    } while (0)

    LOAD_TILE_E(0, 0);

    const int KCH = KE / 64;   // 32
    for (int ch = 0; ch < KCH; ++ch) {
        if (ch + 1 < KCH) {
            LOAD_TILE_E(ch + 1, (ch + 1) & 1);
            asm volatile("cp.async.wait_group 1;");
        } else {
            asm volatile("cp.async.wait_group 0;");
        }
        __syncthreads();

        const uint32_t Ab = sb + (ch & 1) * 32768;
        const uint32_t Bb = Ab + 16384;

        #pragma unroll
        for (int ks = 0; ks < 4; ++ks) {
            const int kb2 = ks * 32;
            uint32_t b[8];
            #pragma unroll
            for (int h = 0; h < 2; ++h) {
                int nrow = wn * 32 + h * 16 + ((lane >> 4) & 1) * 8 + (lane & 7);
                int kcol = kb2 + ((lane >> 3) & 1) * 16;
                uint32_t ad = Bb + nrow * 128 + (kcol ^ ((nrow & 7) << 4));
                ldm_x4(b[4*h+0], b[4*h+1], b[4*h+2], b[4*h+3], ad);
            }
            #pragma unroll
            for (int mf = 0; mf < 4; ++mf) {
                int arow = wm * 64 + mf * 16 + (lane & 15);
                int acol = kb2 + ((lane >> 4) & 1) * 16;
                uint32_t ad = Ab + arow * 128 + (acol ^ ((arow & 7) << 4));
                uint32_t a0, a1, a2r, a3r;
                ldm_x4(a0, a1, a2r, a3r, ad);
                #pragma unroll
                for (int nf = 0; nf < 4; ++nf)
                    mma16816h(acc[mf][nf][0], acc[mf][nf][1],
                              acc[mf][nf][2], acc[mf][nf][3],
                              a0, a1, a2r, a3r, b[nf*2], b[nf*2+1]);
            }
        }
        __syncthreads();
    }

    #pragma unroll
    for (int mf = 0; mf < 4; ++mf) {
        const int r0 = m0 + wm * 64 + mf * 16 + (lane >> 2);
        #pragma unroll
        for (int nf = 0; nf < 4; ++nf) {
            const int c = n0 + wn * 32 + nf * 8 + (lane & 3) * 2;
            float2 bia = *(const float2*)(b0 + c);
            float2 v0 = make_float2(acc[mf][nf][0] + bia.x, acc[mf][nf][1] + bia.y);
            float2 v1 = make_float2(acc[mf][nf][2] + bia.x, acc[mf][nf][3] + bia.y);
            *(float2*)(C + (size_t)r0 * H_ + c)     = v0;
            *(float2*)(C + (size_t)(r0+8) * H_ + c) = v1;
        }
    }
}

// ===========================================================================
// Persistent tensor-core recurrence (round-15 winner, byte-identical)
// ===========================================================================
#define RSM_H   98304
#define RSM_RED (RSM_H + 65536)
#define RSM_TOTAL (RSM_RED + 128*12*4)

#define LOADCH(ch, buf) do {                                                   \
    const int seg_ = tid & 7;                                                  \
    const int r0_  = tid >> 3;                                                 \
    _Pragma("unroll")                                                          \
    for (int i_ = 0; i_ < 8; i_++) {                                           \
        const int arr_ = i_ >> 1;                                              \
        const int row_ = r0_ + (i_ & 1) * 32;                                  \
        const char* src_ =                                                     \
          (arr_ == 0) ? (const char*)h0h + ((size_t)row_*H_  + (size_t)(ch)*64 + seg_*8)*2 : \
          (arr_ == 1) ? (const char*)h0l + ((size_t)row_*H_  + (size_t)(ch)*64 + seg_*8)*2 : \
          (arr_ == 2) ? (const char*)h1h + ((size_t)row_*h1s + (size_t)(ch)*64 + seg_*8)*2 : \
                        (const char*)h1l + ((size_t)row_*h1s + (size_t)(ch)*64 + seg_*8)*2;  \
        cp16(sb + RSM_H + (buf)*32768 + arr_*8192 + row_*128                   \
                 + (uint32_t)((seg_*16) ^ ((row_ & 7) << 4)), src_);           \
    }                                                                          \
    asm volatile("cp.async.commit_group;");                                    \
} while (0)

__global__ __launch_bounds__(256, 1)
void rnn_persistent_mma(const float* __restrict__ Wh0,
                        const float* __restrict__ Win1,
                        const float* __restrict__ Wh1,
                        const float* __restrict__ b1v,
                        const float* __restrict__ hidden)
{
    extern __shared__ char rsm[];
    const uint32_t sb = smem_u32(rsm);
    const int tid = threadIdx.x, lane = tid & 31, wid = tid >> 5;
    const int wg = wid >> 2, mw = wid & 3;
    const int n0 = blockIdx.x * 8;

    {
        const float* Wm[3] = {Wh0, Win1, Wh1};
        #pragma unroll 1
        for (int m = 0; m < 3; ++m) {
            const float* src = Wm[m] + (size_t)n0 * H_;
            for (int idx = tid; idx < 8 * H_; idx += 256) {
                int r = idx >> 10, k = idx & 1023;
                float v = src[(size_t)r * H_ + k];
                __nv_bfloat16 hh, ll; split_bf16(v, hh, ll);
                uint32_t off = (uint32_t)(2 * k) ^ ((r & 7) << 4);
                *(__nv_bfloat16*)(rsm + m*32768 + r*2048 + off)     = hh;
                *(__nv_bfloat16*)(rsm + m*32768 + (r+8)*2048 + off) = ll;
            }
        }
    }
    for (size_t i = (size_t)blockIdx.x * 256 + tid; i < 2 * (size_t)BH;
         i += (size_t)GRID * 256) {
        __nv_bfloat16 hh, ll; split_bf16(hidden[i], hh, ll);
        if (i < (size_t)BH) { g_hid0h[i] = hh; g_hid0l[i] = ll; }
        else                { g_hp1h[i - BH] = hh; g_hp1l[i - BH] = ll; }
    }
    gsync(0);

    const float b1c0 = b1v[n0 + (lane & 3) * 2];
    const float b1c1 = b1v[n0 + (lane & 3) * 2 + 1];

    for (int tt = -1; tt < T_; ++tt) {
        const __nv_bfloat16 *h0h, *h0l, *h1h, *h1l;
        size_t h1s;
        if (tt < 0) { h0h = g_hid0h; h0l = g_hid0l; }
        else        { h0h = g_h0h[tt & 1]; h0l = g_h0l[tt & 1]; }
        if (tt <= 0) { h1h = g_hp1h; h1l = g_hp1l; h1s = H_; }
        else { h1h = g_A3 + (size_t)(tt - 1) * B_ * K3; h1l = h1h + 2048; h1s = K3; }

        float P0[4] = {0.f,0.f,0.f,0.f}, P1[4] = {0.f,0.f,0.f,0.f};

        LOADCH(0, 0);
        for (int ch = 0; ch < 16; ++ch) {
            if (ch < 15) { LOADCH(ch + 1, (ch + 1) & 1);
                           asm volatile("cp.async.wait_group 1;"); }
            else         { asm volatile("cp.async.wait_group 0;"); }
            __syncthreads();
            const uint32_t hb = sb + RSM_H + (ch & 1) * 32768;
            #pragma unroll
            for (int k16 = 0; k16 < 2; ++k16) {
                const int kb2 = wg * 64 + k16 * 32;
                const int kbw = ch * 128 + kb2;
                const int arow = mw * 16 + (lane & 15);
                const uint32_t aoff = (uint32_t)(kb2 + ((lane >> 4) & 1) * 16)
                                      ^ ((arow & 7) << 4);
                const int brow = ((lane >> 4) & 1) * 8 + (lane & 7);
                const uint32_t boff = (uint32_t)(kbw + ((lane >> 3) & 1) * 16)
                                      ^ ((brow & 7) << 4);

                uint32_t aH0[4], aL0[4];
                ldm_x4(aH0[0], aH0[1], aH0[2], aH0[3], hb + arow*128 + aoff);
                ldm_x4(aL0[0], aL0[1], aL0[2], aL0[3], hb + 8192 + arow*128 + aoff);
                uint32_t b0f[4];
                ldm_x4(b0f[0], b0f[1], b0f[2], b0f[3], sb + brow*2048 + boff);

                mma16816(P0, aH0, b0f[0], b0f[1]);
                mma16816(P0, aH0, b0f[2], b0f[3]);
                mma16816(P0, aL0, b0f[0], b0f[1]);

                if (tt >= 0) {
                    uint32_t aH1[4], aL1[4];
                    ldm_x4(aH1[0], aH1[1], aH1[2], aH1[3], hb + 16384 + arow*128 + aoff);
                    ldm_x4(aL1[0], aL1[1], aL1[2], aL1[3], hb + 24576 + arow*128 + aoff);
                    uint32_t bif[4], bhf[4];
                    ldm_x4(bif[0], bif[1], bif[2], bif[3], sb + 32768 + brow*2048 + boff);
                    ldm_x4(bhf[0], bhf[1], bhf[2], bhf[3], sb + 65536 + brow*2048 + boff);

                    mma16816(P1, aH0, bif[0], bif[1]);
                    mma16816(P1, aH0, bif[2], bif[3]);
                    mma16816(P1, aL0, bif[0], bif[1]);
                    mma16816(P1, aH1, bhf[0], bhf[1]);
                    mma16816(P1, aH1, bhf[2], bhf[3]);
                    mma16816(P1, aL1, bhf[0], bhf[1]);
                }
            }
            __syncthreads();
        }

        // Cross-wg partial exchange: wg1 -> redA (P0+P1), wg0 -> redB (P0)
        float* redA = (float*)(rsm + RSM_RED);           // 128 x 8
        float* redB = redA + 128 * 8;                    // 128 x 4
        const int tl = mw * 32 + lane;
        if (wg == 1) {
            float* r = redA + tl * 8;
            r[0]=P0[0]; r[1]=P0[1]; r[2]=P0[2]; r[3]=P0[3];
            r[4]=P1[0]; r[5]=P1[1]; r[6]=P1[2]; r[7]=P1[3];
        } else {
            float* r = redB + tl * 4;
            r[0]=P0[0]; r[1]=P0[1]; r[2]=P0[2]; r[3]=P0[3];
        }
        __syncthreads();

        const int r0 = mw * 16 + (lane >> 2);
        const int c0 = n0 + (lane & 3) * 2;
        const int rws[4] = {r0, r0, r0 + 8, r0 + 8};
        const int cls[4] = {c0, c0 + 1, c0, c0 + 1};

        if (wg == 0) {
            // L1 epilogue: h1(tt) -> A3 (bf16 hi/lo) + A2f (fp16 Ah)
            if (tt >= 0) {
                const float* r = redA + tl * 8;
                const float bb[4] = {b1c0, b1c1, b1c0, b1c1};
                #pragma unroll
                for (int j = 0; j < 4; j++) {
                    float v = tanhf((P1[j] + r[j + 4]) + bb[j]);
                    __nv_bfloat16 hh, ll; split_bf16(v, hh, ll);
                    size_t row = (size_t)(tt * 64 + rws[j]);
                    size_t ab = row * K3 + cls[j];
                    g_A3[ab] = hh; g_A3[ab + 2048] = ll;
                    g_A2f[row * KD + cls[j]] = __float2half_rn(v);
                    if (tt == T_ - 1) g_H1f[rws[j] * H_ + cls[j]] = v;
                }
            }
        } else {
            // L0 epilogue: h0(tt+1) split writes
            if (tt < T_ - 1) {
                const float* r = redA + tl * 8;
                const float* s = redB + tl * 4;
                __nv_bfloat16* dh = g_h0h[(tt + 1) & 1];
                __nv_bfloat16* dl = g_h0l[(tt + 1) & 1];
                #pragma unroll
                for (int j = 0; j < 4; j++) {
                    float u = g_U0[(size_t)(tt + 1) * BH + rws[j] * H_ + cls[j]];
                    float v = tanhf((s[j] + r[j]) + u);
                    __nv_bfloat16 hh, ll; split_bf16(v, hh, ll);
                    dh[rws[j] * H_ + cls[j]] = hh;
                    dl[rws[j] * H_ + cls[j]] = ll;
                }
            }
        }
        gsync(tt + 2);
    }
}

// ===========================================================================
// Decoder GEMM: single-term fp16 (K=1024), round-15 winner, byte-identical.
// ===========================================================================
__global__ __launch_bounds__(256, 2)
void decoder_mma(const __half* __restrict__ A2,
                 const __half* __restrict__ B1,
                 const float* __restrict__ bdec, float* __restrict__ C)
{
    extern __shared__ char dsm[];
    const uint32_t sb = smem_u32(dsm);

    const int tid  = threadIdx.x;
    const int lane = tid & 31, wid = tid >> 5;
    const int wm = wid >> 2, wn = wid & 3;
    const int m0 = blockIdx.y * 128, n0 = blockIdx.x * 128;

    float acc[4][4][4];
    #pragma unroll
    for (int i = 0; i < 4; i++)
        #pragma unroll
        for (int j = 0; j < 4; j++)
            #pragma unroll
            for (int q = 0; q < 4; q++) acc[i][j][q] = 0.f;

    int lrow[4], lcb[4];
    #pragma unroll
    for (int i = 0; i < 4; i++) {
        int idx = tid + i * 256;
        lrow[i] = idx >> 3;
        lcb[i]  = (idx & 7) * 16;
    }

    #define LOAD_TILE(ch, buf) do {                                            \
        const uint32_t Ab_ = sb + (buf) * 32768;                               \
        const uint32_t Bb_ = Ab_ + 16384;                                      \
        _Pragma("unroll")                                                      \
        for (int i_ = 0; i_ < 4; i_++) {                                       \
            int r_ = lrow[i_], cb_ = lcb[i_];                                  \
            uint32_t sw_ = (uint32_t)(cb_ ^ ((r_ & 7) << 4));                  \
            cp16(Ab_ + r_ * 128 + sw_,                                         \
                 (const char*)A2 + (((size_t)(m0 + r_) * KD + (ch) * 64) * 2 + cb_)); \
            cp16(Bb_ + r_ * 128 + sw_,                                         \
                 (const char*)B1 + (((size_t)(n0 + r_) * H_ + (ch) * 64) * 2 + cb_)); \
        }                                                                      \
        asm volatile("cp.async.commit_group;");                                \
    } while (0)

    LOAD_TILE(0, 0);

    const int KCH = KD / 64;   // 16
    for (int ch = 0; ch < KCH; ++ch) {
        if (ch + 1 < KCH) {
            LOAD_TILE(ch + 1, (ch + 1) & 1);
            asm volatile("cp.async.wait_group 1;");
        } else {
            asm volatile("cp.async.wait_group 0;");
        }
        __syncthreads();

        const uint32_t Ab = sb + (ch & 1) * 32768;
        const uint32_t Bb = Ab + 16384;

        #pragma unroll
        for (int ks = 0; ks < 4; ++ks) {
            const int kb2 = ks * 32;
            uint32_t b[8];
            #pragma unroll
            for (int h = 0; h < 2; ++h) {
                int nrow = wn * 32 + h * 16 + ((lane >> 4) & 1) * 8 + (lane & 7);
                int kcol = kb2 + ((lane >> 3) & 1) * 16;
                uint32_t ad = Bb + nrow * 128 + (kcol ^ ((nrow & 7) << 4));
                ldm_x4(b[4*h+0], b[4*h+1], b[4*h+2], b[4*h+3], ad);
            }
            #pragma unroll
            for (int mf = 0; mf < 4; ++mf) {
                int arow = wm * 64 + mf * 16 + (lane & 15);
                int acol = kb2 + ((lane >> 4) & 1) * 16;
                uint32_t ad = Ab + arow * 128 + (acol ^ ((arow & 7) << 4));
                uint32_t a0, a1, a2r, a3r;
                ldm_x4(a0, a1, a2r, a3r, ad);
                #pragma unroll
                for (int nf = 0; nf < 4; ++nf)
                    mma16816h(acc[mf][nf][0], acc[mf][nf][1],
                              acc[mf][nf][2], acc[mf][nf][3],
                              a0, a1, a2r, a3r, b[nf*2], b[nf*2+1]);
            }
        }
        __syncthreads();
    }

    #pragma unroll
    for (int mf = 0; mf < 4; ++mf) {
        const int r0 = m0 + wm * 64 + mf * 16 + (lane >> 2);
        #pragma unroll
        for (int nf = 0; nf < 4; ++nf) {
            const int c = n0 + wn * 32 + nf * 8 + (lane & 3) * 2;
            if (c < V_) {
                float2 bia = *(const float2*)(bdec + c);
                float2 v0 = make_float2(acc[mf][nf][0] + bia.x, acc[mf][nf][1] + bia.y);
                float2 v1 = make_float2(acc[mf][nf][2] + bia.x, acc[mf][nf][3] + bia.y);
                *(float2*)(C + (size_t)r0 * V_ + c)     = v0;
                *(float2*)(C + (size_t)(r0+8) * V_ + c) = v1;
            }
        }
    }
}

// ===========================================================================
// Final hidden state
// ===========================================================================
__global__ void copy_final(const __nv_bfloat16* __restrict__ h0hh,
                           const __nv_bfloat16* __restrict__ h0ll,
                           const float* __restrict__ h1f,
                           float* __restrict__ out)
{
    int i = blockIdx.x * blockDim.x + threadIdx.x;
    if (i < BH) {
        out[i]      = __bfloat162float(h0hh[i]) + __bfloat162float(h0ll[i]);
        out[BH + i] = h1f[i];
    }
}

extern "C" void kernel_launch(void* const* d_in, const int* in_sizes, int n_in,
                              void* d_out, int out_size)
{
    const float* emb    = (const float*)d_in[0];
    const float* W_in0  = (const float*)d_in[1];
    const float* Wh0    = (const float*)d_in[2];
    const float* b0     = (const float*)d_in[3];
    const float* W_in1  = (const float*)d_in[4];
    const float* Wh1    = (const float*)d_in[5];
    const float* b1     = (const float*)d_in[6];
    const float* Wdec   = (const float*)d_in[7];
    const float* bdec   = (const float*)d_in[8];
    const float* hidden = (const float*)d_in[9];
    const int*   tokens = (const int*)d_in[10];

    float* out    = (float*)d_out;
    float* logits = out;
    float* hfin   = out + (size_t)M_ * V_;

    float *U0 = nullptr, *H1f = nullptr;
    __nv_bfloat16 *h0h = nullptr, *h0l = nullptr;
    __half *EH = nullptr, *EL = nullptr, *W01 = nullptr;
    __half *A2f = nullptr, *B1f = nullptr;
    cudaGetSymbolAddress((void**)&U0,  g_U0);
    cudaGetSymbolAddress((void**)&H1f, g_H1f);
    cudaGetSymbolAddress((void**)&A2f, g_A2f);
    cudaGetSymbolAddress((void**)&B1f, g_B1f);
    cudaGetSymbolAddress((void**)&h0h, g_h0h);
    cudaGetSymbolAddress((void**)&h0l, g_h0l);
    cudaGetSymbolAddress((void**)&EH,  g_embH);
    cudaGetSymbolAddress((void**)&EL,  g_embL);
    cudaGetSymbolAddress((void**)&W01, g_W01f);

    cudaFuncSetAttribute(rnn_persistent_mma,
                         cudaFuncAttributeMaxDynamicSharedMemorySize, RSM_TOTAL);
    cudaFuncSetAttribute(decoder_mma,
                         cudaFuncAttributeMaxDynamicSharedMemorySize, DEC_SMEM);
    cudaFuncSetAttribute(embed_mma,
                         cudaFuncAttributeMaxDynamicSharedMemorySize, DEC_SMEM);

    // 0) splits (vectorized)
    reset_bar_kernel<<<1, 256>>>();
    convert_emb<<<(int)(((size_t)V_ * E_ / 4 + 255) / 256), 256>>>(emb, EH, EL);
    convert_win0<<<(int)(((size_t)H_ * 256) / 256), 256>>>(W_in0, W01);
    convert_wdec<<<(int)(((size_t)VP * 256) / 256), 256>>>(Wdec, B1f);

    // 1) U0 = emb[tokens] @ W_in0^T + b0  (fp16 2-term, K=2048)
    embed_mma<<<dim3(H_ / 128, M_ / 128), 256, DEC_SMEM>>>(EH, EL, W01, tokens,
                                                           b0, U0);

    // 2) Persistent tensor-core recurrence (bf16 3-term, parallel epilogue)
    rnn_persistent_mma<<<GRID, NT, RSM_TOTAL>>>(Wh0, W_in1, Wh1, b1, hidden);

    // 3) logits = A2f @ B1f^T + bdec  (single-term fp16, K=1024)
    decoder_mma<<<dim3(VP / 128, M_ / 128), 256, DEC_SMEM>>>(A2f, B1f, bdec, logits);

    // 4) final hidden states
    copy_final<<<(BH + 255) / 256, 256>>>(h0h + BH, h0l + BH, H1f, hfin);

    (void)in_sizes; (void)n_in; (void)out_size;
}

// round 17
// speedup vs baseline: 2.6806x; 1.2876x over previous
#include <cuda_runtime.h>
#include <cuda_bf16.h>
#include <cuda_fp16.h>
#include <math.h>
#include <stdint.h>

#define T_ 128
#define B_ 64
#define E_ 1024
#define H_ 1024
#define V_ 10000
#define VP 10112              // V padded to 128 (79*128)
#define M_ (T_*B_)            // 8192
#define BH (B_*H_)
#define KE 2048               // fp16 2-term embed A: [Eh|El]
#define KD 1024               // fp16 single-term decoder A (== H_)

#define GRID 128
#define NT 256

// Scratch (no allocs allowed)
__device__ float g_U0[(size_t)M_*H_];
__device__ float g_H1f[BH];
__device__ unsigned int g_bar[256];
__device__ __half g_A2f[(size_t)M_*KD];    // h1 history (decoder A), fp16
__device__ __half g_B1f[(size_t)VP*H_];    // decoder B: Wdec fp16
__device__ __half g_h0f[2][BH];            // h0 double buffer, fp16
__device__ __half g_hid0f[BH];             // initial hidden layer0, fp16
__device__ __half g_hp1f[BH];              // initial hidden layer1, fp16
__device__ __half g_embH[(size_t)V_*E_];   // emb hi fp16
__device__ __half g_embL[(size_t)V_*E_];   // emb lo fp16
__device__ __half g_W01f[(size_t)H_*E_];   // W_in0 fp16

// ===========================================================================
// Grid barrier + helpers
// ===========================================================================
__global__ void reset_bar_kernel() {
    if (threadIdx.x < 256) g_bar[threadIdx.x] = 0;
}

__device__ __forceinline__ void gsync(int slot) {
    __syncthreads();
    if (threadIdx.x == 0) {
        __threadfence();
        atomicAdd(&g_bar[slot], 1u);
        while (*((volatile unsigned int*)&g_bar[slot]) < GRID) { }
        __threadfence();
    }
    __syncthreads();
}

__device__ __forceinline__ uint32_t smem_u32(const void* p) {
    uint32_t a;
    asm("{ .reg .u64 t; cvta.to.shared.u64 t, %1; cvt.u32.u64 %0, t; }"
        : "=r"(a) : "l"(p));
    return a;
}
__device__ __forceinline__ void cp16(uint32_t dst, const void* src) {
    asm volatile("cp.async.cg.shared.global [%0], [%1], 16;"
                 :: "r"(dst), "l"(src));
}
__device__ __forceinline__ void ldm_x4(uint32_t& r0, uint32_t& r1,
                                       uint32_t& r2, uint32_t& r3, uint32_t addr) {
    asm volatile("ldmatrix.sync.aligned.m8n8.x4.shared.b16 {%0,%1,%2,%3}, [%4];"
                 : "=r"(r0), "=r"(r1), "=r"(r2), "=r"(r3) : "r"(addr));
}
__device__ __forceinline__ void mma16816h(float& d0, float& d1, float& d2, float& d3,
                                          uint32_t a0, uint32_t a1, uint32_t a2, uint32_t a3,
                                          uint32_t b0, uint32_t b1) {
    asm volatile("mma.sync.aligned.m16n8k16.row.col.f32.f16.f16.f32 "
                 "{%0,%1,%2,%3}, {%4,%5,%6,%7}, {%8,%9}, {%0,%1,%2,%3};"
                 : "+f"(d0), "+f"(d1), "+f"(d2), "+f"(d3)
                 : "r"(a0), "r"(a1), "r"(a2), "r"(a3), "r"(b0), "r"(b1));
}
__device__ __forceinline__ void mma16816ha(float* d, const uint32_t* a,
                                           uint32_t b0, uint32_t b1) {
    asm volatile("mma.sync.aligned.m16n8k16.row.col.f32.f16.f16.f32 "
                 "{%0,%1,%2,%3}, {%4,%5,%6,%7}, {%8,%9}, {%0,%1,%2,%3};"
                 : "+f"(d[0]), "+f"(d[1]), "+f"(d[2]), "+f"(d[3])
                 : "r"(a[0]), "r"(a[1]), "r"(a[2]), "r"(a[3]), "r"(b0), "r"(b1));
}
__device__ __forceinline__ __half2 packh2(__half a, __half b) {
    __half2 p; p.x = a; p.y = b; return p;
}

// ===========================================================================
// Conversion kernels
// ===========================================================================
__global__ __launch_bounds__(256)
void convert_emb(const float* __restrict__ Wemb,
                 __half* __restrict__ eh, __half* __restrict__ el)
{
    size_t q = (size_t)blockIdx.x * 256 + threadIdx.x;
    if (q < (size_t)V_ * E_ / 4) {
        float4 v = *(const float4*)(Wemb + q * 4);
        __half h0 = __float2half_rn(v.x), l0 = __float2half_rn(v.x - __half2float(h0));
        __half h1 = __float2half_rn(v.y), l1 = __float2half_rn(v.y - __half2float(h1));
        __half h2 = __float2half_rn(v.z), l2 = __float2half_rn(v.z - __half2float(h2));
        __half h3 = __float2half_rn(v.w), l3 = __float2half_rn(v.w - __half2float(h3));
        *(__half2*)(eh + q*4)     = packh2(h0,h1);
        *(__half2*)(eh + q*4 + 2) = packh2(h2,h3);
        *(__half2*)(el + q*4)     = packh2(l0,l1);
        *(__half2*)(el + q*4 + 2) = packh2(l2,l3);
    }
}

__global__ __launch_bounds__(256)
void convert_win0(const float* __restrict__ W, __half* __restrict__ Wf)
{
    size_t q = (size_t)blockIdx.x * 256 + threadIdx.x;
    int n = (int)(q >> 8), kq = (int)(q & 255) * 4;
    float4 v = *(const float4*)(W + (size_t)n * E_ + kq);
    *(__half2*)(Wf + (size_t)n * E_ + kq)     = __floats2half2_rn(v.x, v.y);
    *(__half2*)(Wf + (size_t)n * E_ + kq + 2) = __floats2half2_rn(v.z, v.w);
}

__global__ __launch_bounds__(256)
void convert_wdec(const float* __restrict__ W, __half* __restrict__ Bf)
{
    size_t q = (size_t)blockIdx.x * 256 + threadIdx.x;
    int n = (int)(q >> 8), kq = (int)(q & 255) * 4;
    float4 v = (n < V_) ? *(const float4*)(W + (size_t)n * H_ + kq)
                        : make_float4(0.f,0.f,0.f,0.f);
    *(__half2*)(Bf + (size_t)n * H_ + kq)     = __floats2half2_rn(v.x, v.y);
    *(__half2*)(Bf + (size_t)n * H_ + kq + 2) = __floats2half2_rn(v.z, v.w);
}

// ===========================================================================
// Embedding projection: fp16 2-term (round-16 winner, byte-identical)
// ===========================================================================
#define DEC_SMEM 65536

__global__ __launch_bounds__(256, 2)
void embed_mma(const __half* __restrict__ EH,
               const __half* __restrict__ EL,
               const __half* __restrict__ W1,
               const int* __restrict__ tokens,
               const float* __restrict__ b0, float* __restrict__ C)
{
    extern __shared__ char dsm[];
    const uint32_t sb = smem_u32(dsm);

    const int tid  = threadIdx.x;
    const int lane = tid & 31, wid = tid >> 5;
    const int wm = wid >> 2, wn = wid & 3;
    const int m0 = blockIdx.y * 128, n0 = blockIdx.x * 128;

    float acc[4][4][4];
    #pragma unroll
    for (int i = 0; i < 4; i++)
        #pragma unroll
        for (int j = 0; j < 4; j++)
            #pragma unroll
            for (int q = 0; q < 4; q++) acc[i][j][q] = 0.f;

    int lrow[4], lcb[4], tokr[4];
    #pragma unroll
    for (int i = 0; i < 4; i++) {
        int idx = tid + i * 256;
        lrow[i] = idx >> 3;
        lcb[i]  = (idx & 7) * 16;
        tokr[i] = tokens[m0 + lrow[i]];
    }

    #define LOAD_TILE_E(ch, buf) do {                                          \
        const uint32_t Ab_ = sb + (buf) * 32768;                               \
        const uint32_t Bb_ = Ab_ + 16384;                                      \
        const __half* Aarr_ = ((ch) < 16) ? EH : EL;                           \
        const int kc_ = ((ch) & 15) * 64;                                      \
        _Pragma("unroll")                                                      \
        for (int i_ = 0; i_ < 4; i_++) {                                       \
            int r_ = lrow[i_], cb_ = lcb[i_];                                  \
            uint32_t sw_ = (uint32_t)(cb_ ^ ((r_ & 7) << 4));                  \
            cp16(Ab_ + r_ * 128 + sw_,                                         \
                 (const char*)Aarr_ + (((size_t)tokr[i_] * E_ + kc_) * 2 + cb_)); \
            cp16(Bb_ + r_ * 128 + sw_,                                         \
                 (const char*)W1 + (((size_t)(n0 + r_) * E_ + kc_) * 2 + cb_)); \
        }                                                                      \
        asm volatile("cp.async.commit_group;");                                \
    } while (0)

    LOAD_TILE_E(0, 0);

    const int KCH = KE / 64;   // 32
    for (int ch = 0; ch < KCH; ++ch) {
        if (ch + 1 < KCH) {
            LOAD_TILE_E(ch + 1, (ch + 1) & 1);
            asm volatile("cp.async.wait_group 1;");
        } else {
            asm volatile("cp.async.wait_group 0;");
        }
        __syncthreads();

        const uint32_t Ab = sb + (ch & 1) * 32768;
        const uint32_t Bb = Ab + 16384;

        #pragma unroll
        for (int ks = 0; ks < 4; ++ks) {
            const int kb2 = ks * 32;
            uint32_t b[8];
            #pragma unroll
            for (int h = 0; h < 2; ++h) {
                int nrow = wn * 32 + h * 16 + ((lane >> 4) & 1) * 8 + (lane & 7);
                int kcol = kb2 + ((lane >> 3) & 1) * 16;
                uint32_t ad = Bb + nrow * 128 + (kcol ^ ((nrow & 7) << 4));
                ldm_x4(b[4*h+0], b[4*h+1], b[4*h+2], b[4*h+3], ad);
            }
            #pragma unroll
            for (int mf = 0; mf < 4; ++mf) {
                int arow = wm * 64 + mf * 16 + (lane & 15);
                int acol = kb2 + ((lane >> 4) & 1) * 16;
                uint32_t ad = Ab + arow * 128 + (acol ^ ((arow & 7) << 4));
                uint32_t a0, a1, a2r, a3r;
                ldm_x4(a0, a1, a2r, a3r, ad);
                #pragma unroll
                for (int nf = 0; nf < 4; ++nf)
                    mma16816h(acc[mf][nf][0], acc[mf][nf][1],
                              acc[mf][nf][2], acc[mf][nf][3],
                              a0, a1, a2r, a3r, b[nf*2], b[nf*2+1]);
            }
        }
        __syncthreads();
    }

    #pragma unroll
    for (int mf = 0; mf < 4; ++mf) {
        const int r0 = m0 + wm * 64 + mf * 16 + (lane >> 2);
        #pragma unroll
        for (int nf = 0; nf < 4; ++nf) {
            const int c = n0 + wn * 32 + nf * 8 + (lane & 3) * 2;
            float2 bia = *(const float2*)(b0 + c);
            float2 v0 = make_float2(acc[mf][nf][0] + bia.x, acc[mf][nf][1] + bia.y);
            float2 v1 = make_float2(acc[mf][nf][2] + bia.x, acc[mf][nf][3] + bia.y);
            *(float2*)(C + (size_t)r0 * H_ + c)     = v0;
            *(float2*)(C + (size_t)(r0+8) * H_ + c) = v1;
        }
    }
}

// ===========================================================================
// Persistent recurrence, fp16 single-term.
//   Weights smem: block A [16 rows x 2048B]: rows 0-7 = Wh0, 8-15 = Win1;
//                 block B [16 rows x 2048B]: rows 0-7 = Wh1 (8-15 unused).
//   h streams: h0f fp16 + h1f fp16 (h1 read from / written to g_A2f).
//   Per k16: 2 A-ldm + 2 B-ldm + 3 MMAs.
// ===========================================================================
#define RSM_HB  65536                       // weights: 2 x 32768
#define RSM_RED (RSM_HB + 2*16384)          // h bufs: 2 x 16KB
#define RSM_TOTAL (RSM_RED + 128*12*4)

#define LOADCH(ch, buf) do {                                                   \
    const int seg_ = tid & 7;                                                  \
    const int r0_  = tid >> 3;                                                 \
    _Pragma("unroll")                                                          \
    for (int i_ = 0; i_ < 4; i_++) {                                           \
        const int arr_ = i_ >> 1;                                              \
        const int row_ = r0_ + (i_ & 1) * 32;                                  \
        const char* src_ = (arr_ == 0)                                         \
          ? (const char*)h0f + ((size_t)row_*H_ + (size_t)(ch)*64 + seg_*8)*2  \
          : (const char*)h1f + ((size_t)row_*H_ + (size_t)(ch)*64 + seg_*8)*2; \
        cp16(sb + RSM_HB + (buf)*16384 + arr_*8192 + row_*128                  \
                 + (uint32_t)((seg_*16) ^ ((row_ & 7) << 4)), src_);           \
    }                                                                          \
    asm volatile("cp.async.commit_group;");                                    \
} while (0)

__global__ __launch_bounds__(256, 1)
void rnn_persistent_mma(const float* __restrict__ Wh0,
                        const float* __restrict__ Win1,
                        const float* __restrict__ Wh1,
                        const float* __restrict__ b1v,
                        const float* __restrict__ hidden)
{
    extern __shared__ char rsm[];
    const uint32_t sb = smem_u32(rsm);
    const int tid = threadIdx.x, lane = tid & 31, wid = tid >> 5;
    const int wg = wid >> 2, mw = wid & 3;
    const int n0 = blockIdx.x * 8;

    // Weights -> smem, fp16 single. m0: Wh0 rows 0-7 blkA; m1: Win1 rows 8-15
    // blkA; m2: Wh1 rows 0-7 blkB.
    {
        const float* Wm[3] = {Wh0, Win1, Wh1};
        #pragma unroll 1
        for (int m = 0; m < 3; ++m) {
            const float* src = Wm[m] + (size_t)n0 * H_;
            char* base = rsm + ((m == 2) ? 32768 : 0);
            const int radd = (m == 1) ? 8 : 0;
            for (int idx = tid; idx < 8 * H_; idx += 256) {
                int r = idx >> 10, k = idx & 1023;
                uint32_t off = (uint32_t)(2 * k) ^ ((r & 7) << 4);
                *(__half*)(base + (r + radd) * 2048 + off) =
                    __float2half_rn(src[(size_t)r * H_ + k]);
            }
        }
    }
    // Initial hidden -> fp16
    for (size_t i = (size_t)blockIdx.x * 256 + tid; i < 2 * (size_t)BH;
         i += (size_t)GRID * 256) {
        __half f = __float2half_rn(hidden[i]);
        if (i < (size_t)BH) g_hid0f[i] = f;
        else                g_hp1f[i - BH] = f;
    }
    gsync(0);

    const float b1c0 = b1v[n0 + (lane & 3) * 2];
    const float b1c1 = b1v[n0 + (lane & 3) * 2 + 1];

    for (int tt = -1; tt < T_; ++tt) {
        const __half* h0f = (tt < 0) ? g_hid0f : g_h0f[tt & 1];
        const __half* h1f = (tt <= 0) ? g_hp1f
                                      : (g_A2f + (size_t)(tt - 1) * B_ * KD);

        float P0[4] = {0.f,0.f,0.f,0.f}, P1[4] = {0.f,0.f,0.f,0.f};

        LOADCH(0, 0);
        for (int ch = 0; ch < 16; ++ch) {
            if (ch < 15) { LOADCH(ch + 1, (ch + 1) & 1);
                           asm volatile("cp.async.wait_group 1;"); }
            else         { asm volatile("cp.async.wait_group 0;"); }
            __syncthreads();
            const uint32_t hb = sb + RSM_HB + (ch & 1) * 16384;
            #pragma unroll
            for (int k16 = 0; k16 < 2; ++k16) {
                const int kb2 = wg * 64 + k16 * 32;
                const int kbw = ch * 128 + kb2;
                const int arow = mw * 16 + (lane & 15);
                const uint32_t aoff = (uint32_t)(kb2 + ((lane >> 4) & 1) * 16)
                                      ^ ((arow & 7) << 4);
                const int brow = ((lane >> 4) & 1) * 8 + (lane & 7);
                const uint32_t boff = (uint32_t)(kbw + ((lane >> 3) & 1) * 16)
                                      ^ ((brow & 7) << 4);

                uint32_t a0[4];
                ldm_x4(a0[0], a0[1], a0[2], a0[3], hb + arow*128 + aoff);
                uint32_t wab[4];   // regs 0,1: Wh0 frag; regs 2,3: Win1 frag
                ldm_x4(wab[0], wab[1], wab[2], wab[3], sb + brow*2048 + boff);

                mma16816ha(P0, a0, wab[0], wab[1]);

                if (tt >= 0) {
                    uint32_t a1[4];
                    ldm_x4(a1[0], a1[1], a1[2], a1[3], hb + 8192 + arow*128 + aoff);
                    uint32_t wc[4];  // regs 0,1: Wh1 frag (2,3 unused)
                    ldm_x4(wc[0], wc[1], wc[2], wc[3], sb + 32768 + brow*2048 + boff);

                    mma16816ha(P1, a0, wab[2], wab[3]);
                    mma16816ha(P1, a1, wc[0], wc[1]);
                }
            }
            __syncthreads();
        }

        // Cross-wg partial exchange: wg1 -> redA (P0+P1), wg0 -> redB (P0)
        float* redA = (float*)(rsm + RSM_RED);           // 128 x 8
        float* redB = redA + 128 * 8;                    // 128 x 4
        const int tl = mw * 32 + lane;
        if (wg == 1) {
            float* r = redA + tl * 8;
            r[0]=P0[0]; r[1]=P0[1]; r[2]=P0[2]; r[3]=P0[3];
            r[4]=P1[0]; r[5]=P1[1]; r[6]=P1[2]; r[7]=P1[3];
        } else {
            float* r = redB + tl * 4;
            r[0]=P0[0]; r[1]=P0[1]; r[2]=P0[2]; r[3]=P0[3];
        }
        __syncthreads();

        const int r0 = mw * 16 + (lane >> 2);
        const int c0 = n0 + (lane & 3) * 2;
        const int rws[4] = {r0, r0, r0 + 8, r0 + 8};
        const int cls[4] = {c0, c0 + 1, c0, c0 + 1};

        if (wg == 0) {
            // L1 epilogue: h1(tt) -> g_A2f fp16 (+ H1f fp32 at last step)
            if (tt >= 0) {
                const float* r = redA + tl * 8;
                const float bb[4] = {b1c0, b1c1, b1c0, b1c1};
                #pragma unroll
                for (int j = 0; j < 4; j++) {
                    float v = tanhf((P1[j] + r[j + 4]) + bb[j]);
                    g_A2f[(size_t)(tt * 64 + rws[j]) * KD + cls[j]] =
                        __float2half_rn(v);
                    if (tt == T_ - 1) g_H1f[rws[j] * H_ + cls[j]] = v;
                }
            }
        } else {
            // L0 epilogue: h0(tt+1) fp16 write
            if (tt < T_ - 1) {
                const float* r = redA + tl * 8;
                const float* s = redB + tl * 4;
                __half* dh = g_h0f[(tt + 1) & 1];
                #pragma unroll
                for (int j = 0; j < 4; j++) {
                    float u = g_U0[(size_t)(tt + 1) * BH + rws[j] * H_ + cls[j]];
                    float v = tanhf((s[j] + r[j]) + u);
                    dh[rws[j] * H_ + cls[j]] = __float2half_rn(v);
                }
            }
        }
        gsync(tt + 2);
    }
}

// ===========================================================================
// Decoder GEMM: single-term fp16 (round-15/16 winner, byte-identical)
// ===========================================================================
__global__ __launch_bounds__(256, 2)
void decoder_mma(const __half* __restrict__ A2,
                 const __half* __restrict__ B1,
                 const float* __restrict__ bdec, float* __restrict__ C)
{
    extern __shared__ char dsm[];
    const uint32_t sb = smem_u32(dsm);

    const int tid  = threadIdx.x;
    const int lane = tid & 31, wid = tid >> 5;
    const int wm = wid >> 2, wn = wid & 3;
    const int m0 = blockIdx.y * 128, n0 = blockIdx.x * 128;

    float acc[4][4][4];
    #pragma unroll
    for (int i = 0; i < 4; i++)
        #pragma unroll
        for (int j = 0; j < 4; j++)
            #pragma unroll
            for (int q = 0; q < 4; q++) acc[i][j][q] = 0.f;

    int lrow[4], lcb[4];
    #pragma unroll
    for (int i = 0; i < 4; i++) {
        int idx = tid + i * 256;
        lrow[i] = idx >> 3;
        lcb[i]  = (idx & 7) * 16;
    }

    #define LOAD_TILE(ch, buf) do {                                            \
        const uint32_t Ab_ = sb + (buf) * 32768;                               \
        const uint32_t Bb_ = Ab_ + 16384;                                      \
        _Pragma("unroll")                                                      \
        for (int i_ = 0; i_ < 4; i_++) {                                       \
            int r_ = lrow[i_], cb_ = lcb[i_];                                  \
            uint32_t sw_ = (uint32_t)(cb_ ^ ((r_ & 7) << 4));                  \
            cp16(Ab_ + r_ * 128 + sw_,                                         \
                 (const char*)A2 + (((size_t)(m0 + r_) * KD + (ch) * 64) * 2 + cb_)); \
            cp16(Bb_ + r_ * 128 + sw_,                                         \
                 (const char*)B1 + (((size_t)(n0 + r_) * H_ + (ch) * 64) * 2 + cb_)); \
        }                                                                      \
        asm volatile("cp.async.commit_group;");                                \
    } while (0)

    LOAD_TILE(0, 0);

    const int KCH = KD / 64;   // 16
    for (int ch = 0; ch < KCH; ++ch) {
        if (ch + 1 < KCH) {
            LOAD_TILE(ch + 1, (ch + 1) & 1);
            asm volatile("cp.async.wait_group 1;");
        } else {
            asm volatile("cp.async.wait_group 0;");
        }
        __syncthreads();

        const uint32_t Ab = sb + (ch & 1) * 32768;
        const uint32_t Bb = Ab + 16384;

        #pragma unroll
        for (int ks = 0; ks < 4; ++ks) {
            const int kb2 = ks * 32;
            uint32_t b[8];
            #pragma unroll
            for (int h = 0; h < 2; ++h) {
                int nrow = wn * 32 + h * 16 + ((lane >> 4) & 1) * 8 + (lane & 7);
                int kcol = kb2 + ((lane >> 3) & 1) * 16;
                uint32_t ad = Bb + nrow * 128 + (kcol ^ ((nrow & 7) << 4));
                ldm_x4(b[4*h+0], b[4*h+1], b[4*h+2], b[4*h+3], ad);
            }
            #pragma unroll
            for (int mf = 0; mf < 4; ++mf) {
                int arow = wm * 64 + mf * 16 + (lane & 15);
                int acol = kb2 + ((lane >> 4) & 1) * 16;
                uint32_t ad = Ab + arow * 128 + (acol ^ ((arow & 7) << 4));
                uint32_t a0, a1, a2r, a3r;
                ldm_x4(a0, a1, a2r, a3r, ad);
                #pragma unroll
                for (int nf = 0; nf < 4; ++nf)
                    mma16816h(acc[mf][nf][0], acc[mf][nf][1],
                              acc[mf][nf][2], acc[mf][nf][3],
                              a0, a1, a2r, a3r, b[nf*2], b[nf*2+1]);
            }
        }
        __syncthreads();
    }

    #pragma unroll
    for (int mf = 0; mf < 4; ++mf) {
        const int r0 = m0 + wm * 64 + mf * 16 + (lane >> 2);
        #pragma unroll
        for (int nf = 0; nf < 4; ++nf) {
            const int c = n0 + wn * 32 + nf * 8 + (lane & 3) * 2;
            if (c < V_) {
                float2 bia = *(const float2*)(bdec + c);
                float2 v0 = make_float2(acc[mf][nf][0] + bia.x, acc[mf][nf][1] + bia.y);
                float2 v1 = make_float2(acc[mf][nf][2] + bia.x, acc[mf][nf][3] + bia.y);
                *(float2*)(C + (size_t)r0 * V_ + c)     = v0;
                *(float2*)(C + (size_t)(r0+8) * V_ + c) = v1;
            }
        }
    }
}

// ===========================================================================
// Final hidden state
// ===========================================================================
__global__ void copy_final(const __half* __restrict__ h0ff,
                           const float* __restrict__ h1f,
                           float* __restrict__ out)
{
    int i = blockIdx.x * blockDim.x + threadIdx.x;
    if (i < BH) {
        out[i]      = __half2float(h0ff[i]);
        out[BH + i] = h1f[i];
    }
}

extern "C" void kernel_launch(void* const* d_in, const int* in_sizes, int n_in,
                              void* d_out, int out_size)
{
    const float* emb    = (const float*)d_in[0];
    const float* W_in0  = (const float*)d_in[1];
    const float* Wh0    = (const float*)d_in[2];
    const float* b0     = (const float*)d_in[3];
    const float* W_in1  = (const float*)d_in[4];
    const float* Wh1    = (const float*)d_in[5];
    const float* b1     = (const float*)d_in[6];
    const float* Wdec   = (const float*)d_in[7];
    const float* bdec   = (const float*)d_in[8];
    const float* hidden = (const float*)d_in[9];
    const int*   tokens = (const int*)d_in[10];

    float* out    = (float*)d_out;
    float* logits = out;
    float* hfin   = out + (size_t)M_ * V_;

    float *U0 = nullptr, *H1f = nullptr;
    __half *EH = nullptr, *EL = nullptr, *W01 = nullptr;
    __half *A2f = nullptr, *B1f = nullptr, *h0f = nullptr;
    cudaGetSymbolAddress((void**)&U0,  g_U0);
    cudaGetSymbolAddress((void**)&H1f, g_H1f);
    cudaGetSymbolAddress((void**)&A2f, g_A2f);
    cudaGetSymbolAddress((void**)&B1f, g_B1f);
    cudaGetSymbolAddress((void**)&h0f, g_h0f);
    cudaGetSymbolAddress((void**)&EH,  g_embH);
    cudaGetSymbolAddress((void**)&EL,  g_embL);
    cudaGetSymbolAddress((void**)&W01, g_W01f);

    cudaFuncSetAttribute(rnn_persistent_mma,
                         cudaFuncAttributeMaxDynamicSharedMemorySize, RSM_TOTAL);
    cudaFuncSetAttribute(decoder_mma,
                         cudaFuncAttributeMaxDynamicSharedMemorySize, DEC_SMEM);
    cudaFuncSetAttribute(embed_mma,
                         cudaFuncAttributeMaxDynamicSharedMemorySize, DEC_SMEM);

    // 0) splits (vectorized)
    reset_bar_kernel<<<1, 256>>>();
    convert_emb<<<(int)(((size_t)V_ * E_ / 4 + 255) / 256), 256>>>(emb, EH, EL);
    convert_win0<<<(int)(((size_t)H_ * 256) / 256), 256>>>(W_in0, W01);
    convert_wdec<<<(int)(((size_t)VP * 256) / 256), 256>>>(Wdec, B1f);

    // 1) U0 = emb[tokens] @ W_in0^T + b0  (fp16 2-term, K=2048)
    embed_mma<<<dim3(H_ / 128, M_ / 128), 256, DEC_SMEM>>>(EH, EL, W01, tokens,
                                                           b0, U0);

    // 2) Persistent recurrence (fp16 single-term, halved L2 stream)
    rnn_persistent_mma<<<GRID, NT, RSM_TOTAL>>>(Wh0, W_in1, Wh1, b1, hidden);

    // 3) logits = A2f @ B1f^T + bdec  (single-term fp16, K=1024)
    decoder_mma<<<dim3(VP / 128, M_ / 128), 256, DEC_SMEM>>>(A2f, B1f, bdec, logits);

    // 4) final hidden states: h0(127) in g_h0f[1], h1(127) in H1f
    copy_final<<<(BH + 255) / 256, 256>>>(h0f + BH, H1f, hfin);

    (void)in_sizes; (void)n_in; (void)out_size;
}